// round 1
// baseline (speedup 1.0000x reference)
#include <cuda_runtime.h>
#include <cuda_bf16.h>
#include <math.h>

// ---------------- problem constants ----------------
#define B_    2
#define S_    2048
#define DIM_  2048
#define H_    16
#define C_    512
#define NOPE_ 128
#define ROPE_ 64
#define V_    128
#define QK_   192      // NOPE+ROPE
#define BS_   (B_*S_)  // 4096

__device__ __constant__ float d_dummy; // keep compiler happy if needed

// ---------------- scratch (static device globals; allocation-free) ----------------
__device__ float g_q[(long long)BS_*H_*QK_];      // (b,s,h,192)   50 MB
__device__ float g_kvpe[(long long)BS_*(C_+ROPE_)];// (b,s,576)     9 MB
__device__ float g_kv[(long long)BS_*C_];          // normalized kv 8 MB
__device__ float g_kpe[(long long)BS_*ROPE_];      // roped k_pe    1 MB
__device__ float g_qabs[(long long)BS_*H_*C_];     // (b,s,h,512) 134 MB
__device__ float g_oh[(long long)BS_*H_*C_];       // (b,s,h,512) 134 MB
__device__ float g_o2[(long long)BS_*H_*V_];       // (b,s,2048)   33 MB

// =====================================================================
// Generic batched SGEMM:  C = A @ op(B),  A: MxK row-major (lda)
// TRANSB=1: B is NxK row-major (NT, dot of rows)
// TRANSB=0: B is KxN row-major (NN)
// Tiles 128x128xK8, 256 threads, 8x8 microtile.
// =====================================================================
template<int TRANSB>
__global__ __launch_bounds__(256) void sgemm_k(
    const float* __restrict__ A, const float* __restrict__ Bm, float* __restrict__ Cm,
    int M, int N, int K, int lda, int ldb, int ldc,
    long long sAz, long long sBz, long long sCz)
{
    A  += (long long)blockIdx.z * sAz;
    Bm += (long long)blockIdx.z * sBz;
    Cm += (long long)blockIdx.z * sCz;

    __shared__ float As[8][132];
    __shared__ float Bs[8][132];

    const int tid = threadIdx.x;
    const int m0 = blockIdx.y * 128;
    const int n0 = blockIdx.x * 128;
    const int tx = tid & 15;
    const int ty = tid >> 4;
    const int lr = tid >> 1;          // load row 0..127
    const int lk = (tid & 1) * 4;     // 0 or 4
    const int bk = tid >> 5;          // NN: 0..7
    const int bn = (tid & 31) * 4;    // NN: 0..124

    float acc[8][8];
#pragma unroll
    for (int i = 0; i < 8; i++)
#pragma unroll
        for (int j = 0; j < 8; j++) acc[i][j] = 0.f;

    for (int k0 = 0; k0 < K; k0 += 8) {
        float4 av = make_float4(0.f,0.f,0.f,0.f);
        if (m0 + lr < M)
            av = *(const float4*)(A + (long long)(m0 + lr) * lda + k0 + lk);
        As[lk+0][lr] = av.x; As[lk+1][lr] = av.y;
        As[lk+2][lr] = av.z; As[lk+3][lr] = av.w;

        if (TRANSB) {
            float4 bv = make_float4(0.f,0.f,0.f,0.f);
            if (n0 + lr < N)
                bv = *(const float4*)(Bm + (long long)(n0 + lr) * ldb + k0 + lk);
            Bs[lk+0][lr] = bv.x; Bs[lk+1][lr] = bv.y;
            Bs[lk+2][lr] = bv.z; Bs[lk+3][lr] = bv.w;
        } else {
            float4 bv = make_float4(0.f,0.f,0.f,0.f);
            if (n0 + bn < N)
                bv = *(const float4*)(Bm + (long long)(k0 + bk) * ldb + n0 + bn);
            *(float4*)&Bs[bk][bn] = bv;
        }
        __syncthreads();

#pragma unroll
        for (int kk = 0; kk < 8; kk++) {
            float a[8], b[8];
#pragma unroll
            for (int i = 0; i < 8; i++) a[i] = As[kk][ty*8 + i];
#pragma unroll
            for (int j = 0; j < 8; j++) b[j] = Bs[kk][tx*8 + j];
#pragma unroll
            for (int i = 0; i < 8; i++)
#pragma unroll
                for (int j = 0; j < 8; j++)
                    acc[i][j] = fmaf(a[i], b[j], acc[i][j]);
        }
        __syncthreads();
    }

#pragma unroll
    for (int i = 0; i < 8; i++) {
        int m = m0 + ty*8 + i;
        if (m >= M) continue;
#pragma unroll
        for (int j = 0; j < 8; j += 4) {
            int n = n0 + tx*8 + j;
            if (n + 3 < N) {
                *(float4*)(Cm + (long long)m * ldc + n) =
                    make_float4(acc[i][j], acc[i][j+1], acc[i][j+2], acc[i][j+3]);
            } else {
#pragma unroll
                for (int jj = 0; jj < 4; jj++)
                    if (n + jj < N) Cm[(long long)m * ldc + n + jj] = acc[i][j+jj];
            }
        }
    }
}

// =====================================================================
// RoPE on q_pe (in-place in g_q).  grid = BS_, block = 512 (h=tid/32, i=tid%32)
// =====================================================================
__global__ void rope_q_k(float* __restrict__ q,
                         const float* __restrict__ fcos, const float* __restrict__ fsin)
{
    int bs = blockIdx.x;
    int s  = bs & (S_ - 1);
    int t  = threadIdx.x;
    int h  = t >> 5, i = t & 31;
    float c  = fcos[s*(ROPE_/2) + i];
    float sn = fsin[s*(ROPE_/2) + i];
    float* p = q + (long long)bs * (H_*QK_) + h*QK_ + NOPE_ + 2*i;
    float a = p[0], b = p[1];
    p[0] = a*c - b*sn;
    p[1] = a*sn + b*c;
}

// =====================================================================
// RMSNorm(kv) * w  and  RoPE(k_pe).  grid = BS_, block = 128
// =====================================================================
__global__ void kv_prep_k(const float* __restrict__ kvpe, const float* __restrict__ w,
                          const float* __restrict__ fcos, const float* __restrict__ fsin,
                          float* __restrict__ kvout, float* __restrict__ kpeout)
{
    int bs = blockIdx.x;
    int s  = bs & (S_ - 1);
    const float* row = kvpe + (long long)bs * (C_ + ROPE_);
    __shared__ float red[4];
    int t = threadIdx.x;
    float v[4]; float ss = 0.f;
#pragma unroll
    for (int i = 0; i < 4; i++) { v[i] = row[t + i*128]; ss = fmaf(v[i], v[i], ss); }
#pragma unroll
    for (int o = 16; o > 0; o >>= 1) ss += __shfl_xor_sync(0xffffffffu, ss, o);
    if ((t & 31) == 0) red[t >> 5] = ss;
    __syncthreads();
    float tot = red[0] + red[1] + red[2] + red[3];
    float r = rsqrtf(tot * (1.0f/512.0f) + 1e-6f);
#pragma unroll
    for (int i = 0; i < 4; i++) {
        int c = t + i*128;
        kvout[(long long)bs*C_ + c] = v[i] * r * w[c];
    }
    if (t < 32) {
        float c  = fcos[s*(ROPE_/2) + t];
        float sn = fsin[s*(ROPE_/2) + t];
        float a = row[C_ + 2*t], b = row[C_ + 2*t + 1];
        kpeout[(long long)bs*ROPE_ + 2*t]     = a*c - b*sn;
        kpeout[(long long)bs*ROPE_ + 2*t + 1] = a*sn + b*c;
    }
}

// =====================================================================
// Fused causal flash attention (absorbed MLA form).
// grid = (S/32, H, B), block = 256, dynamic smem ~154KB.
// scores: (q_abs . kv) + (q_pe . k_pe), scale, online softmax, o += p @ kv (512)
// =====================================================================
#define FBM 32
#define FBN 32
#define CDP 516
#define RDP 68
#define PP  33
#define FLASH_SMEM ((2*FBM*CDP + 2*FBM*RDP + FBM*PP + 3*FBM) * 4)

__global__ __launch_bounds__(256, 1) void flash_k(
    const float* __restrict__ qabs, const float* __restrict__ qfull,
    const float* __restrict__ kv, const float* __restrict__ kpe,
    float* __restrict__ oh)
{
    extern __shared__ float sm[];
    float* sQ  = sm;                      // 32 x 516
    float* sK  = sQ  + FBM*CDP;           // 32 x 516
    float* sQp = sK  + FBM*CDP;           // 32 x 68
    float* sKp = sQp + FBM*RDP;           // 32 x 68
    float* sP  = sKp + FBM*RDP;           // 32 x 33
    float* sMx = sP  + FBM*PP;
    float* sL  = sMx + FBM;
    float* sA  = sL  + FBM;

    const int s0  = blockIdx.x * FBM;
    const int h   = blockIdx.y;
    const int b   = blockIdx.z;
    const int tid = threadIdx.x;

    // load Q block (q_abs 32x512, q_pe 32x64)
    for (int i = tid; i < FBM * (C_/4); i += 256) {
        int r = i >> 7, c4 = i & 127;
        float4 v = *(const float4*)(qabs +
            (((long long)(b*S_ + s0 + r) * H_ + h) * C_) + c4*4);
        *(float4*)(sQ + r*CDP + c4*4) = v;
    }
    for (int i = tid; i < FBM * (ROPE_/4); i += 256) {
        int r = i >> 4, c4 = i & 15;
        float4 v = *(const float4*)(qfull +
            ((long long)(b*S_ + s0 + r)) * (H_*QK_) + h*QK_ + NOPE_ + c4*4);
        *(float4*)(sQp + r*RDP + c4*4) = v;
    }
    if (tid < FBM) { sMx[tid] = -INFINITY; sL[tid] = 0.f; }

    float acc[8][8];
#pragma unroll
    for (int i = 0; i < 8; i++)
#pragma unroll
        for (int j = 0; j < 8; j++) acc[i][j] = 0.f;

    const int r0 = (tid >> 6) * 8;        // 8 owned rows
    const int c0 = (tid & 63) * 8;        // 8 owned cols of 512
    const int tr = (tid >> 4) * 2;        // score rows (2)
    const int tc = (tid & 15) * 2;        // score cols (2)
    const float SCALE = 0.07216878364870322f; // 1/sqrt(192)

    __syncthreads();

    for (int t0 = 0; t0 <= s0; t0 += FBN) {
        // load KV tile
        for (int i = tid; i < FBN * (C_/4); i += 256) {
            int r = i >> 7, c4 = i & 127;
            *(float4*)(sK + r*CDP + c4*4) =
                *(const float4*)(kv + ((long long)(b*S_ + t0 + r)) * C_ + c4*4);
        }
        for (int i = tid; i < FBN * (ROPE_/4); i += 256) {
            int r = i >> 4, c4 = i & 15;
            *(float4*)(sKp + r*RDP + c4*4) =
                *(const float4*)(kpe + ((long long)(b*S_ + t0 + r)) * ROPE_ + c4*4);
        }
        __syncthreads();

        // ---- scores: each thread 2x2 ----
        float s00=0.f, s01=0.f, s10=0.f, s11=0.f;
        {
            const float* q0 = sQ + tr*CDP;
            const float* q1 = q0 + CDP;
            const float* k0 = sK + tc*CDP;
            const float* k1 = k0 + CDP;
#pragma unroll 8
            for (int k = 0; k < C_; k += 4) {
                float4 a0 = *(const float4*)(q0 + k);
                float4 a1 = *(const float4*)(q1 + k);
                float4 b0 = *(const float4*)(k0 + k);
                float4 b1 = *(const float4*)(k1 + k);
                s00 = fmaf(a0.x,b0.x,fmaf(a0.y,b0.y,fmaf(a0.z,b0.z,fmaf(a0.w,b0.w,s00))));
                s01 = fmaf(a0.x,b1.x,fmaf(a0.y,b1.y,fmaf(a0.z,b1.z,fmaf(a0.w,b1.w,s01))));
                s10 = fmaf(a1.x,b0.x,fmaf(a1.y,b0.y,fmaf(a1.z,b0.z,fmaf(a1.w,b0.w,s10))));
                s11 = fmaf(a1.x,b1.x,fmaf(a1.y,b1.y,fmaf(a1.z,b1.z,fmaf(a1.w,b1.w,s11))));
            }
            const float* qp0 = sQp + tr*RDP;
            const float* qp1 = qp0 + RDP;
            const float* kp0 = sKp + tc*RDP;
            const float* kp1 = kp0 + RDP;
#pragma unroll
            for (int k = 0; k < ROPE_; k += 4) {
                float4 a0 = *(const float4*)(qp0 + k);
                float4 a1 = *(const float4*)(qp1 + k);
                float4 b0 = *(const float4*)(kp0 + k);
                float4 b1 = *(const float4*)(kp1 + k);
                s00 = fmaf(a0.x,b0.x,fmaf(a0.y,b0.y,fmaf(a0.z,b0.z,fmaf(a0.w,b0.w,s00))));
                s01 = fmaf(a0.x,b1.x,fmaf(a0.y,b1.y,fmaf(a0.z,b1.z,fmaf(a0.w,b1.w,s01))));
                s10 = fmaf(a1.x,b0.x,fmaf(a1.y,b0.y,fmaf(a1.z,b0.z,fmaf(a1.w,b0.w,s10))));
                s11 = fmaf(a1.x,b1.x,fmaf(a1.y,b1.y,fmaf(a1.z,b1.z,fmaf(a1.w,b1.w,s11))));
            }
            int gr0 = s0 + tr, gr1 = gr0 + 1;
            int gc0 = t0 + tc, gc1 = gc0 + 1;
            sP[(tr+0)*PP + tc+0] = (gc0 <= gr0) ? s00*SCALE : -1e30f;
            sP[(tr+0)*PP + tc+1] = (gc1 <= gr0) ? s01*SCALE : -1e30f;
            sP[(tr+1)*PP + tc+0] = (gc0 <= gr1) ? s10*SCALE : -1e30f;
            sP[(tr+1)*PP + tc+1] = (gc1 <= gr1) ? s11*SCALE : -1e30f;
        }
        __syncthreads();

        // ---- online softmax row update (one warp) ----
        if (tid < FBM) {
            int r = tid;
            float m_old = sMx[r];
            float mrow = m_old;
#pragma unroll
            for (int j = 0; j < FBN; j++) mrow = fmaxf(mrow, sP[r*PP + j]);
            float alpha = __expf(m_old - mrow);
            float l = sL[r] * alpha;
#pragma unroll
            for (int j = 0; j < FBN; j++) {
                float p = __expf(sP[r*PP + j] - mrow);
                sP[r*PP + j] = p;
                l += p;
            }
            sMx[r] = mrow; sL[r] = l; sA[r] = alpha;
        }
        __syncthreads();

        // ---- o update: acc = acc*alpha + P @ KV ----
        {
            float al[8];
#pragma unroll
            for (int i = 0; i < 8; i++) al[i] = sA[r0 + i];
#pragma unroll
            for (int i = 0; i < 8; i++)
#pragma unroll
                for (int j = 0; j < 8; j++) acc[i][j] *= al[i];
#pragma unroll 4
            for (int j = 0; j < FBN; j++) {
                float4 v0 = *(const float4*)(sK + j*CDP + c0);
                float4 v1 = *(const float4*)(sK + j*CDP + c0 + 4);
                float vv[8] = {v0.x,v0.y,v0.z,v0.w,v1.x,v1.y,v1.z,v1.w};
#pragma unroll
                for (int i = 0; i < 8; i++) {
                    float pi = sP[(r0+i)*PP + j];
#pragma unroll
                    for (int cj = 0; cj < 8; cj++)
                        acc[i][cj] = fmaf(pi, vv[cj], acc[i][cj]);
                }
            }
        }
        __syncthreads();
    }

    // ---- epilogue: normalize and store ----
#pragma unroll
    for (int i = 0; i < 8; i++) {
        float inv = 1.0f / sL[r0 + i];
        int s = s0 + r0 + i;
        float4 o0 = make_float4(acc[i][0]*inv, acc[i][1]*inv, acc[i][2]*inv, acc[i][3]*inv);
        float4 o1 = make_float4(acc[i][4]*inv, acc[i][5]*inv, acc[i][6]*inv, acc[i][7]*inv);
        float* dst = oh + (((long long)(b*S_ + s) * H_ + h) * C_) + c0;
        *(float4*)(dst)     = o0;
        *(float4*)(dst + 4) = o1;
    }
}

// =====================================================================
// Host launch
// =====================================================================
static float* sym_addr(const void* sym) {
    void* p = nullptr;
    cudaGetSymbolAddress(&p, sym);
    return (float*)p;
}

extern "C" void kernel_launch(void* const* d_in, const int* in_sizes, int n_in,
                              void* d_out, int out_size)
{
    const float* x     = (const float*)d_in[0];
    const float* wq    = (const float*)d_in[1];
    const float* wkv_a = (const float*)d_in[2];
    const float* wkv_b = (const float*)d_in[3];
    const float* wo    = (const float*)d_in[4];
    const float* kvw   = (const float*)d_in[5];
    const float* fcos  = (const float*)d_in[6];
    const float* fsin  = (const float*)d_in[7];
    // d_in[8]=mask (exact causal, folded into kernel), d_in[9]=start_pos (0)
    float* out = (float*)d_out;

    float* qb    = sym_addr(g_q);
    float* kvpeb = sym_addr(g_kvpe);
    float* kvb   = sym_addr(g_kv);
    float* kpeb  = sym_addr(g_kpe);
    float* qabsb = sym_addr(g_qabs);
    float* ohb   = sym_addr(g_oh);
    float* o2b   = sym_addr(g_o2);

    cudaFuncSetAttribute(flash_k, cudaFuncAttributeMaxDynamicSharedMemorySize, FLASH_SMEM);

    dim3 blk(256);

    // 1. q = x @ wq^T   (4096 x 3072, K=2048)
    sgemm_k<1><<<dim3((3072+127)/128, (BS_+127)/128, 1), blk>>>(
        x, wq, qb, BS_, H_*QK_, DIM_, DIM_, DIM_, H_*QK_, 0, 0, 0);

    // 2. kvpe = x @ wkv_a^T   (4096 x 576, K=2048)
    sgemm_k<1><<<dim3((576+127)/128, (BS_+127)/128, 1), blk>>>(
        x, wkv_a, kvpeb, BS_, C_+ROPE_, DIM_, DIM_, DIM_, C_+ROPE_, 0, 0, 0);

    // 3. rope(q_pe) in place
    rope_q_k<<<BS_, H_*32>>>(qb, fcos, fsin);

    // 4. rmsnorm(kv), rope(k_pe)
    kv_prep_k<<<BS_, 128>>>(kvpeb, kvw, fcos, fsin, kvb, kpeb);

    // 5. q_abs[h] = q_nope[h] @ wkv_b[h,:128,:]   (NN, batched over h)
    sgemm_k<0><<<dim3(C_/128, BS_/128, H_), blk>>>(
        qb, wkv_b, qabsb,
        BS_, C_, NOPE_,
        H_*QK_, C_, H_*C_,
        (long long)QK_, (long long)(NOPE_+V_)*C_, (long long)C_);

    // 6. flash attention -> g_oh (b,s,h,512)
    flash_k<<<dim3(S_/FBM, H_, B_), blk, FLASH_SMEM>>>(qabsb, qb, kvb, kpeb, ohb);

    // 7. o2[h] = oh[h] @ wkv_b[h,128:,:]^T   (NT, batched over h)
    sgemm_k<1><<<dim3(V_/128, BS_/128, H_), blk>>>(
        ohb, wkv_b + (long long)NOPE_*C_, o2b,
        BS_, V_, C_,
        H_*C_, C_, H_*V_,
        (long long)C_, (long long)(NOPE_+V_)*C_, (long long)V_);

    // 8. out = o2 @ wo^T   (4096 x 2048, K=2048)
    sgemm_k<1><<<dim3(DIM_/128, BS_/128, 1), blk>>>(
        o2b, wo, out, BS_, DIM_, H_*V_, H_*V_, H_*V_, DIM_, 0, 0, 0);

    (void)in_sizes; (void)n_in; (void)out_size;
}

// round 2
// speedup vs baseline: 2.2808x; 2.2808x over previous
#include <cuda_runtime.h>
#include <cuda_bf16.h>
#include <math.h>

// ---------------- problem constants ----------------
#define B_    2
#define S_    2048
#define DIM_  2048
#define H_    16
#define C_    512
#define NOPE_ 128
#define ROPE_ 64
#define V_    128
#define QK_   192      // NOPE+ROPE
#define BS_   (B_*S_)  // 4096

// ---------------- scratch (static device globals; allocation-free) ----------------
__device__ float g_q[(long long)BS_*H_*QK_];        // (bs,h,192) roped in place
__device__ float g_kvpe[(long long)BS_*(C_+ROPE_)]; // (bs,576)
__device__ float g_kv[(long long)BS_*C_];           // normalized kv (bs,512)
__device__ float g_kpe[(long long)BS_*ROPE_];       // roped k_pe (bs,64)
__device__ float g_kn[(long long)H_*BS_*NOPE_];     // per-head k_nope (h,bs,128)
__device__ float g_v [(long long)H_*BS_*V_];        // per-head v      (h,bs,128)
__device__ float g_o2[(long long)BS_*H_*V_];        // attn out (bs, 2048)

// =====================================================================
// NT SGEMM: C = A @ B^T. A: MxK (lda), B: NxK (ldb), C: MxN (ldc).
// 128x128xK8 tiles, 256 threads, split 8x8 microtile (conflict-free frags).
// =====================================================================
__global__ __launch_bounds__(256) void sgemm_nt(
    const float* __restrict__ A, const float* __restrict__ Bm, float* __restrict__ Cm,
    int M, int N, int K, int lda, int ldb, int ldc,
    long long sAz, long long sBz, long long sCz)
{
    A  += (long long)blockIdx.z * sAz;
    Bm += (long long)blockIdx.z * sBz;
    Cm += (long long)blockIdx.z * sCz;

    __shared__ float As[8][132];
    __shared__ float Bs[8][132];

    const int tid = threadIdx.x;
    const int m0 = blockIdx.y * 128;
    const int n0 = blockIdx.x * 128;
    const int tx = tid & 15;          // 16 col groups
    const int ty = tid >> 4;          // 16 row groups
    const int lr = tid >> 1;          // load row 0..127
    const int lk = (tid & 1) * 4;     // 0 or 4

    float acc[8][8];
#pragma unroll
    for (int i = 0; i < 8; i++)
#pragma unroll
        for (int j = 0; j < 8; j++) acc[i][j] = 0.f;

    for (int k0 = 0; k0 < K; k0 += 8) {
        float4 av = make_float4(0.f,0.f,0.f,0.f);
        if (m0 + lr < M)
            av = *(const float4*)(A + (long long)(m0 + lr) * lda + k0 + lk);
        As[lk+0][lr] = av.x; As[lk+1][lr] = av.y;
        As[lk+2][lr] = av.z; As[lk+3][lr] = av.w;

        float4 bv = make_float4(0.f,0.f,0.f,0.f);
        if (n0 + lr < N)
            bv = *(const float4*)(Bm + (long long)(n0 + lr) * ldb + k0 + lk);
        Bs[lk+0][lr] = bv.x; Bs[lk+1][lr] = bv.y;
        Bs[lk+2][lr] = bv.z; Bs[lk+3][lr] = bv.w;
        __syncthreads();

#pragma unroll
        for (int kk = 0; kk < 8; kk++) {
            float4 a0 = *(const float4*)&As[kk][ty*4];
            float4 a1 = *(const float4*)&As[kk][64 + ty*4];
            float4 b0 = *(const float4*)&Bs[kk][tx*4];
            float4 b1 = *(const float4*)&Bs[kk][64 + tx*4];
            float a[8] = {a0.x,a0.y,a0.z,a0.w,a1.x,a1.y,a1.z,a1.w};
            float b[8] = {b0.x,b0.y,b0.z,b0.w,b1.x,b1.y,b1.z,b1.w};
#pragma unroll
            for (int i = 0; i < 8; i++)
#pragma unroll
                for (int j = 0; j < 8; j++)
                    acc[i][j] = fmaf(a[i], b[j], acc[i][j]);
        }
        __syncthreads();
    }

#pragma unroll
    for (int i = 0; i < 8; i++) {
        int m = (i < 4) ? (m0 + ty*4 + i) : (m0 + 64 + ty*4 + i - 4);
        if (m >= M) continue;
#pragma unroll
        for (int half = 0; half < 2; half++) {
            int n = n0 + half*64 + tx*4;
            int jb = half*4;
            if (n + 3 < N) {
                *(float4*)(Cm + (long long)m * ldc + n) =
                    make_float4(acc[i][jb], acc[i][jb+1], acc[i][jb+2], acc[i][jb+3]);
            } else {
#pragma unroll
                for (int jj = 0; jj < 4; jj++)
                    if (n + jj < N) Cm[(long long)m * ldc + n + jj] = acc[i][jb+jj];
            }
        }
    }
}

// =====================================================================
// RoPE on q_pe (in-place in g_q). grid = BS_, block = 512
// =====================================================================
__global__ void rope_q_k(float* __restrict__ q,
                         const float* __restrict__ fcos, const float* __restrict__ fsin)
{
    int bs = blockIdx.x;
    int s  = bs & (S_ - 1);
    int t  = threadIdx.x;
    int h  = t >> 5, i = t & 31;
    float c  = fcos[s*(ROPE_/2) + i];
    float sn = fsin[s*(ROPE_/2) + i];
    float* p = q + (long long)bs * (H_*QK_) + h*QK_ + NOPE_ + 2*i;
    float a = p[0], b = p[1];
    p[0] = a*c - b*sn;
    p[1] = a*sn + b*c;
}

// =====================================================================
// RMSNorm(kv)*w and RoPE(k_pe). grid = BS_, block = 128
// =====================================================================
__global__ void kv_prep_k(const float* __restrict__ kvpe, const float* __restrict__ w,
                          const float* __restrict__ fcos, const float* __restrict__ fsin,
                          float* __restrict__ kvout, float* __restrict__ kpeout)
{
    int bs = blockIdx.x;
    int s  = bs & (S_ - 1);
    const float* row = kvpe + (long long)bs * (C_ + ROPE_);
    __shared__ float red[4];
    int t = threadIdx.x;
    float v[4]; float ss = 0.f;
#pragma unroll
    for (int i = 0; i < 4; i++) { v[i] = row[t + i*128]; ss = fmaf(v[i], v[i], ss); }
#pragma unroll
    for (int o = 16; o > 0; o >>= 1) ss += __shfl_xor_sync(0xffffffffu, ss, o);
    if ((t & 31) == 0) red[t >> 5] = ss;
    __syncthreads();
    float tot = red[0] + red[1] + red[2] + red[3];
    float r = rsqrtf(tot * (1.0f/512.0f) + 1e-6f);
#pragma unroll
    for (int i = 0; i < 4; i++) {
        int c = t + i*128;
        kvout[(long long)bs*C_ + c] = v[i] * r * w[c];
    }
    if (t < 32) {
        float c  = fcos[s*(ROPE_/2) + t];
        float sn = fsin[s*(ROPE_/2) + t];
        float a = row[C_ + 2*t], b = row[C_ + 2*t + 1];
        kpeout[(long long)bs*ROPE_ + 2*t]     = a*c - b*sn;
        kpeout[(long long)bs*ROPE_ + 2*t + 1] = a*sn + b*c;
    }
}

// =====================================================================
// Fused causal flash attention (per-head, non-absorbed form).
// scores: q(192) . [k_nope|k_pe](192), PV: 128-d.
// grid = (S/64, H, B), block = 256, ~152KB dynamic smem.
// Q/K kept TRANSPOSED in smem ([k][m], pitch 68) -> conflict-free frags.
// =====================================================================
#define FBM 64
#define FBN 64
#define QP  68
#define VP  132
#define PP  65
#define FLASH_SMEM ((2*QK_*QP + FBM*VP + FBM*PP + 3*FBM) * 4)

__global__ __launch_bounds__(256, 1) void flash_k(
    const float* __restrict__ q,    // (bs, H, 192) roped
    const float* __restrict__ kn,   // (H, bs, 128)
    const float* __restrict__ kpe,  // (bs, 64)
    const float* __restrict__ v,    // (H, bs, 128)
    float* __restrict__ out)        // (bs, H*128)
{
    extern __shared__ float sm[];
    float* sQT = sm;                 // [192][QP]
    float* sKT = sQT + QK_*QP;       // [192][QP]
    float* sV  = sKT + QK_*QP;       // [64][VP]
    float* sP  = sV  + FBM*VP;       // [64][PP]
    float* sMx = sP  + FBM*PP;
    float* sL  = sMx + FBM;
    float* sA  = sL  + FBM;

    // balance causal work across waves: pair small and large s-blocks
    int bx = blockIdx.x;
    int sblk = (bx & 1) ? ((int)gridDim.x - 1 - (bx >> 1)) : (bx >> 1);
    const int s0 = sblk * FBM;
    const int h  = blockIdx.y;
    const int b  = blockIdx.z;
    const int tid = threadIdx.x;

    const float* knh = kn + (long long)h * BS_ * NOPE_;
    const float* vh  = v  + (long long)h * BS_ * V_;

    // load Q tile transposed
    for (int i = tid; i < FBM * (QK_/4); i += 256) {
        int r = i / (QK_/4), c4 = i % (QK_/4);
        float4 x4 = *(const float4*)(q + (long long)(b*S_ + s0 + r) * (H_*QK_) + h*QK_ + c4*4);
        float* dst = sQT + (c4*4)*QP + r;
        dst[0] = x4.x; dst[QP] = x4.y; dst[2*QP] = x4.z; dst[3*QP] = x4.w;
    }
    if (tid < FBM) { sMx[tid] = -INFINITY; sL[tid] = 0.f; }

    float oacc[8][4];
#pragma unroll
    for (int i = 0; i < 8; i++)
#pragma unroll
        for (int c = 0; c < 4; c++) oacc[i][c] = 0.f;

    const int tr = (tid >> 4) * 4;     // score rows
    const int tc = (tid & 15) * 4;     // score cols
    const int pr = (tid >> 5) * 8;     // PV rows
    const int pc = (tid & 31) * 4;     // PV cols (of 128)
    const float SC = 0.07216878364870322f; // 1/sqrt(192)

    __syncthreads();

    for (int t0 = 0; t0 <= s0; t0 += FBN) {
        const bool diag = (t0 == s0);

        // load K tile transposed (k_nope 128 + k_pe 64) and V tile
        for (int i = tid; i < FBN * (QK_/4); i += 256) {
            int r = i / (QK_/4), c4 = i % (QK_/4);
            long long trow = (long long)(b*S_ + t0 + r);
            float4 x4;
            if (c4 < NOPE_/4) x4 = *(const float4*)(knh + trow*NOPE_ + c4*4);
            else              x4 = *(const float4*)(kpe + trow*ROPE_ + (c4 - NOPE_/4)*4);
            float* dst = sKT + (c4*4)*QP + r;
            dst[0] = x4.x; dst[QP] = x4.y; dst[2*QP] = x4.z; dst[3*QP] = x4.w;
        }
        for (int i = tid; i < FBN * (V_/4); i += 256) {
            int r = i >> 5, c4 = i & 31;
            *(float4*)(sV + r*VP + c4*4) =
                *(const float4*)(vh + (long long)(b*S_ + t0 + r)*V_ + c4*4);
        }
        __syncthreads();

        // ---- scores: 4x4 per thread over 192-d ----
        float sc[4][4];
#pragma unroll
        for (int i = 0; i < 4; i++)
#pragma unroll
            for (int j = 0; j < 4; j++) sc[i][j] = 0.f;
#pragma unroll 4
        for (int k = 0; k < QK_; k++) {
            float4 av = *(const float4*)(sQT + k*QP + tr);
            float4 bv = *(const float4*)(sKT + k*QP + tc);
            float a[4] = {av.x, av.y, av.z, av.w};
            float bb[4] = {bv.x, bv.y, bv.z, bv.w};
#pragma unroll
            for (int i = 0; i < 4; i++)
#pragma unroll
                for (int j = 0; j < 4; j++)
                    sc[i][j] = fmaf(a[i], bb[j], sc[i][j]);
        }
        if (diag) {
#pragma unroll
            for (int i = 0; i < 4; i++)
#pragma unroll
                for (int j = 0; j < 4; j++)
                    sP[(tr+i)*PP + tc+j] =
                        ((t0 + tc + j) <= (s0 + tr + i)) ? sc[i][j]*SC : -1e30f;
        } else {
#pragma unroll
            for (int i = 0; i < 4; i++)
#pragma unroll
                for (int j = 0; j < 4; j++)
                    sP[(tr+i)*PP + tc+j] = sc[i][j]*SC;
        }
        __syncthreads();

        // ---- online softmax row update ----
        if (tid < FBM) {
            float m_old = sMx[tid];
            float m = m_old;
            float* prow = sP + tid*PP;
#pragma unroll
            for (int j = 0; j < FBN; j++) m = fmaxf(m, prow[j]);
            float al = __expf(m_old - m);
            float l = sL[tid] * al;
#pragma unroll
            for (int j = 0; j < FBN; j++) {
                float p = __expf(prow[j] - m);
                prow[j] = p;
                l += p;
            }
            sMx[tid] = m; sL[tid] = l; sA[tid] = al;
        }
        __syncthreads();

        // ---- PV: oacc = oacc*alpha + P @ V ----
        {
            float al[8];
#pragma unroll
            for (int i = 0; i < 8; i++) al[i] = sA[pr + i];
#pragma unroll
            for (int i = 0; i < 8; i++)
#pragma unroll
                for (int c = 0; c < 4; c++) oacc[i][c] *= al[i];
#pragma unroll 2
            for (int j = 0; j < FBN; j++) {
                float4 vv = *(const float4*)(sV + j*VP + pc);
#pragma unroll
                for (int i = 0; i < 8; i++) {
                    float p = sP[(pr+i)*PP + j];
                    oacc[i][0] = fmaf(p, vv.x, oacc[i][0]);
                    oacc[i][1] = fmaf(p, vv.y, oacc[i][1]);
                    oacc[i][2] = fmaf(p, vv.z, oacc[i][2]);
                    oacc[i][3] = fmaf(p, vv.w, oacc[i][3]);
                }
            }
        }
        __syncthreads();
    }

    // ---- epilogue ----
#pragma unroll
    for (int i = 0; i < 8; i++) {
        float inv = 1.0f / sL[pr + i];
        int srow = s0 + pr + i;
        float4 o = make_float4(oacc[i][0]*inv, oacc[i][1]*inv, oacc[i][2]*inv, oacc[i][3]*inv);
        *(float4*)(out + (long long)(b*S_ + srow)*(H_*V_) + h*V_ + pc) = o;
    }
}

// =====================================================================
// Host launch
// =====================================================================
static float* sym_addr(const void* sym) {
    void* p = nullptr;
    cudaGetSymbolAddress(&p, sym);
    return (float*)p;
}

extern "C" void kernel_launch(void* const* d_in, const int* in_sizes, int n_in,
                              void* d_out, int out_size)
{
    const float* x     = (const float*)d_in[0];
    const float* wq    = (const float*)d_in[1];
    const float* wkv_a = (const float*)d_in[2];
    const float* wkv_b = (const float*)d_in[3];
    const float* wo    = (const float*)d_in[4];
    const float* kvw   = (const float*)d_in[5];
    const float* fcos  = (const float*)d_in[6];
    const float* fsin  = (const float*)d_in[7];
    float* out = (float*)d_out;

    float* qb    = sym_addr(g_q);
    float* kvpeb = sym_addr(g_kvpe);
    float* kvb   = sym_addr(g_kv);
    float* kpeb  = sym_addr(g_kpe);
    float* knb   = sym_addr(g_kn);
    float* vb    = sym_addr(g_v);
    float* o2b   = sym_addr(g_o2);

    cudaFuncSetAttribute(flash_k, cudaFuncAttributeMaxDynamicSharedMemorySize, FLASH_SMEM);

    dim3 blk(256);

    // 1. q = x @ wq^T   (4096 x 3072, K=2048)
    sgemm_nt<<<dim3(24, 32, 1), blk>>>(
        x, wq, qb, BS_, H_*QK_, DIM_, DIM_, DIM_, H_*QK_, 0, 0, 0);

    // 2. kvpe = x @ wkv_a^T   (4096 x 576, K=2048)
    sgemm_nt<<<dim3(5, 32, 1), blk>>>(
        x, wkv_a, kvpeb, BS_, C_+ROPE_, DIM_, DIM_, DIM_, C_+ROPE_, 0, 0, 0);

    // 3. rope(q_pe) in place
    rope_q_k<<<BS_, H_*32>>>(qb, fcos, fsin);

    // 4. rmsnorm(kv), rope(k_pe)
    kv_prep_k<<<BS_, 128>>>(kvpeb, kvw, fcos, fsin, kvb, kpeb);

    // 5. k_nope[h] = kv @ wkv_b[h,:128,:]^T   (NT, batched over h)
    sgemm_nt<<<dim3(1, 32, H_), blk>>>(
        kvb, wkv_b, knb,
        BS_, NOPE_, C_,
        C_, C_, NOPE_,
        0, (long long)(NOPE_+V_)*C_, (long long)BS_*NOPE_);

    // 6. v[h] = kv @ wkv_b[h,128:,:]^T   (NT, batched over h)
    sgemm_nt<<<dim3(1, 32, H_), blk>>>(
        kvb, wkv_b + (long long)NOPE_*C_, vb,
        BS_, V_, C_,
        C_, C_, V_,
        0, (long long)(NOPE_+V_)*C_, (long long)BS_*V_);

    // 7. flash attention -> g_o2 (bs, 2048)
    flash_k<<<dim3(S_/FBM, H_, B_), blk, FLASH_SMEM>>>(qb, knb, kpeb, vb, o2b);

    // 8. out = o2 @ wo^T   (4096 x 2048, K=2048)
    sgemm_nt<<<dim3(16, 32, 1), blk>>>(
        o2b, wo, out, BS_, DIM_, H_*V_, H_*V_, H_*V_, DIM_, 0, 0, 0);

    (void)in_sizes; (void)n_in; (void)out_size;
}

// round 3
// speedup vs baseline: 4.9123x; 2.1538x over previous
#include <cuda_runtime.h>
#include <cuda_bf16.h>
#include <math.h>

// ---------------- problem constants ----------------
#define B_    2
#define S_    2048
#define DIM_  2048
#define H_    16
#define C_    512
#define NOPE_ 128
#define ROPE_ 64
#define V_    128
#define QK_   192
#define BS_   (B_*S_)

// ---------------- scratch ----------------
__device__ float g_q[(long long)BS_*H_*QK_];
__device__ float g_kvpe[(long long)BS_*(C_+ROPE_)];
__device__ float g_kv[(long long)BS_*C_];
__device__ float g_kpe[(long long)BS_*ROPE_];
__device__ float g_kn[(long long)H_*BS_*NOPE_];
__device__ float g_v [(long long)H_*BS_*V_];
__device__ float g_o2[(long long)BS_*H_*V_];

// ---------------- tf32 helpers ----------------
__device__ __forceinline__ unsigned f2tf(float f) {
    unsigned u; asm("cvt.rna.tf32.f32 %0, %1;" : "=r"(u) : "f"(f)); return u;
}
__device__ __forceinline__ void mma8(float* c, unsigned a0, unsigned a1, unsigned a2,
                                     unsigned a3, unsigned b0, unsigned b1) {
    asm volatile(
        "mma.sync.aligned.m16n8k8.row.col.f32.tf32.tf32.f32 "
        "{%0,%1,%2,%3},{%4,%5,%6,%7},{%8,%9},{%0,%1,%2,%3};"
        : "+f"(c[0]), "+f"(c[1]), "+f"(c[2]), "+f"(c[3])
        : "r"(a0), "r"(a1), "r"(a2), "r"(a3), "r"(b0), "r"(b1));
}

// =====================================================================
// TF32 tensor-core NT GEMM: C = A @ B^T.
// A: MxK (lda), B: NxK (ldb). CTA 128x128xk32, 128 thr, 4 warps 64x64.
// smem pitch 36 (== 4 mod 32) -> conflict-free fragment lds.
// =====================================================================
#define GP 36
#define GEMM_SMEM (4*128*GP*4)

__global__ __launch_bounds__(128) void gemm_tf32_nt(
    const float* __restrict__ A, const float* __restrict__ Bm, float* __restrict__ Cm,
    int M, int N, int K, int lda, int ldb, int ldc,
    long long sAz, long long sBz, long long sCz)
{
    A  += (long long)blockIdx.z * sAz;
    Bm += (long long)blockIdx.z * sBz;
    Cm += (long long)blockIdx.z * sCz;

    extern __shared__ float sg[];
    float* Abuf[2] = { sg,              sg + 2*128*GP };
    float* Bbuf[2] = { sg + 128*GP,     sg + 3*128*GP };

    const int tid  = threadIdx.x;
    const int lane = tid & 31;
    const int warp = tid >> 5;
    const int m0 = blockIdx.y * 128;
    const int n0 = blockIdx.x * 128;
    const int wm = (warp >> 1) * 64;
    const int wn = (warp & 1) * 64;
    const int qr = lane >> 2;
    const int qc = lane & 3;

    float c[4][8][4];
#pragma unroll
    for (int mi = 0; mi < 4; mi++)
#pragma unroll
        for (int ni = 0; ni < 8; ni++)
#pragma unroll
            for (int j = 0; j < 4; j++) c[mi][ni][j] = 0.f;

    const bool bok = (n0 + tid) < N;

    // tile loader: gmem -> cvt.rna -> smem
    auto loadT = [&](int k0, float* as, float* bs) {
        const float4* ap = (const float4*)(A + (long long)(m0 + tid) * lda + k0);
        float4* ad = (float4*)(as + tid * GP);
#pragma unroll
        for (int j = 0; j < 8; j++) {
            float4 v = ap[j];
            uint4 u = make_uint4(f2tf(v.x), f2tf(v.y), f2tf(v.z), f2tf(v.w));
            ad[j] = *(float4*)&u;
        }
        const float4* bp = (const float4*)(Bm + (long long)(n0 + tid) * ldb + k0);
        float4* bd = (float4*)(bs + tid * GP);
#pragma unroll
        for (int j = 0; j < 8; j++) {
            float4 v = bok ? bp[j] : make_float4(0.f,0.f,0.f,0.f);
            uint4 u = make_uint4(f2tf(v.x), f2tf(v.y), f2tf(v.z), f2tf(v.w));
            bd[j] = *(float4*)&u;
        }
    };

    loadT(0, Abuf[0], Bbuf[0]);
    __syncthreads();
    int buf = 0;

    for (int k0 = 0; k0 < K; k0 += 32) {
        if (k0 + 32 < K) loadT(k0 + 32, Abuf[buf ^ 1], Bbuf[buf ^ 1]);
        const float* as = Abuf[buf];
        const float* bs = Bbuf[buf];
#pragma unroll
        for (int k8 = 0; k8 < 4; k8++) {
            const int kk = k8 * 8;
            unsigned a[4][4], b[8][2];
#pragma unroll
            for (int mi = 0; mi < 4; mi++) {
                int r = wm + mi*16 + qr;
                a[mi][0] = __float_as_uint(as[r*GP + kk + qc]);
                a[mi][1] = __float_as_uint(as[(r+8)*GP + kk + qc]);
                a[mi][2] = __float_as_uint(as[r*GP + kk + qc + 4]);
                a[mi][3] = __float_as_uint(as[(r+8)*GP + kk + qc + 4]);
            }
#pragma unroll
            for (int ni = 0; ni < 8; ni++) {
                int rn = wn + ni*8 + qr;
                b[ni][0] = __float_as_uint(bs[rn*GP + kk + qc]);
                b[ni][1] = __float_as_uint(bs[rn*GP + kk + qc + 4]);
            }
#pragma unroll
            for (int mi = 0; mi < 4; mi++)
#pragma unroll
                for (int ni = 0; ni < 8; ni++)
                    mma8(c[mi][ni], a[mi][0], a[mi][1], a[mi][2], a[mi][3],
                         b[ni][0], b[ni][1]);
        }
        __syncthreads();
        buf ^= 1;
    }

#pragma unroll
    for (int mi = 0; mi < 4; mi++) {
        int r = m0 + wm + mi*16 + qr;
#pragma unroll
        for (int ni = 0; ni < 8; ni++) {
            int cn = n0 + wn + ni*8 + 2*qc;
            if (cn < N) {
                float2 v0 = make_float2(c[mi][ni][0], c[mi][ni][1]);
                float2 v1 = make_float2(c[mi][ni][2], c[mi][ni][3]);
                *(float2*)(Cm + (long long)r * ldc + cn) = v0;
                *(float2*)(Cm + (long long)(r+8) * ldc + cn) = v1;
            }
        }
    }
}

// =====================================================================
// RoPE on q_pe (in-place). grid = BS_, block = 512
// =====================================================================
__global__ void rope_q_k(float* __restrict__ q,
                         const float* __restrict__ fcos, const float* __restrict__ fsin)
{
    int bs = blockIdx.x;
    int s  = bs & (S_ - 1);
    int t  = threadIdx.x;
    int h  = t >> 5, i = t & 31;
    float c  = fcos[s*(ROPE_/2) + i];
    float sn = fsin[s*(ROPE_/2) + i];
    float* p = q + (long long)bs * (H_*QK_) + h*QK_ + NOPE_ + 2*i;
    float a = p[0], b = p[1];
    p[0] = a*c - b*sn;
    p[1] = a*sn + b*c;
}

// =====================================================================
// RMSNorm(kv)*w and RoPE(k_pe). grid = BS_, block = 128
// =====================================================================
__global__ void kv_prep_k(const float* __restrict__ kvpe, const float* __restrict__ w,
                          const float* __restrict__ fcos, const float* __restrict__ fsin,
                          float* __restrict__ kvout, float* __restrict__ kpeout)
{
    int bs = blockIdx.x;
    int s  = bs & (S_ - 1);
    const float* row = kvpe + (long long)bs * (C_ + ROPE_);
    __shared__ float red[4];
    int t = threadIdx.x;
    float v[4]; float ss = 0.f;
#pragma unroll
    for (int i = 0; i < 4; i++) { v[i] = row[t + i*128]; ss = fmaf(v[i], v[i], ss); }
#pragma unroll
    for (int o = 16; o > 0; o >>= 1) ss += __shfl_xor_sync(0xffffffffu, ss, o);
    if ((t & 31) == 0) red[t >> 5] = ss;
    __syncthreads();
    float tot = red[0] + red[1] + red[2] + red[3];
    float r = rsqrtf(tot * (1.0f/512.0f) + 1e-6f);
#pragma unroll
    for (int i = 0; i < 4; i++) {
        int c = t + i*128;
        kvout[(long long)bs*C_ + c] = v[i] * r * w[c];
    }
    if (t < 32) {
        float c  = fcos[s*(ROPE_/2) + t];
        float sn = fsin[s*(ROPE_/2) + t];
        float a = row[C_ + 2*t], b = row[C_ + 2*t + 1];
        kpeout[(long long)bs*ROPE_ + 2*t]     = a*c - b*sn;
        kpeout[(long long)bs*ROPE_ + 2*t + 1] = a*sn + b*c;
    }
}

// =====================================================================
// TF32 tensor-core causal flash attention.
// CTA: 128 q-rows, 8 warps (16 rows each). K/V tiles of 64.
// Softmax fully in registers (quad-group shfl). ~215KB smem, 1 CTA/SM.
// =====================================================================
#define FM  128
#define FN  64
#define QP2 196   // pitch for [row][192] (== 4 mod 32)
#define VTP 68    // pitch for Vt [128][64] and P [128][64]
#define FLASH_SMEM ((FM*QP2 + FN*QP2 + V_*VTP + FM*VTP) * 4)

__global__ __launch_bounds__(256, 1) void flash_k(
    const float* __restrict__ q,    // (bs, H, 192) roped
    const float* __restrict__ kn,   // (H, bs, 128)
    const float* __restrict__ kpe,  // (bs, 64)
    const float* __restrict__ v,    // (H, bs, 128)
    float* __restrict__ out)        // (bs, H*128)
{
    extern __shared__ float sm[];
    float* sQ  = sm;                 // [128][196] tf32
    float* sK  = sQ  + FM*QP2;       // [64][196]  tf32
    float* sVt = sK  + FN*QP2;       // [128][68]  tf32 (d-major, t cols)
    float* sP  = sVt + V_*VTP;       // [128][68]  tf32

    int bx = blockIdx.x;
    int nb = gridDim.x;
    int sblk = (bx & 1) ? (nb - 1 - (bx >> 1)) : (bx >> 1);
    const int s0 = sblk * FM;
    const int h  = blockIdx.y;
    const int b  = blockIdx.z;
    const int tid = threadIdx.x;
    const int lane = tid & 31;
    const int warp = tid >> 5;
    const int rb = warp * 16;
    const int qr = lane >> 2;
    const int qc = lane & 3;
    const int g0 = s0 + rb + qr;     // global row of this thread's row0
    const int g1 = g0 + 8;

    const float* knh = kn + (long long)h * BS_ * NOPE_;
    const float* vh  = v  + (long long)h * BS_ * V_;
    const float SC = 0.07216878364870322f; // 1/sqrt(192)

    // load Q tile (tf32)
    for (int i = tid; i < FM * 48; i += 256) {
        int r = i / 48, c4 = i % 48;
        float4 x4 = *(const float4*)(q + (long long)(b*S_ + s0 + r) * (H_*QK_) + h*QK_ + c4*4);
        uint4 u = make_uint4(f2tf(x4.x), f2tf(x4.y), f2tf(x4.z), f2tf(x4.w));
        *(uint4*)(sQ + r*QP2 + c4*4) = u;
    }

    float mr0 = -INFINITY, mr1 = -INFINITY, l0 = 0.f, l1 = 0.f;
    float o[16][4];
#pragma unroll
    for (int ni = 0; ni < 16; ni++)
#pragma unroll
        for (int j = 0; j < 4; j++) o[ni][j] = 0.f;

    __syncthreads();

    for (int t0 = 0; t0 <= s0 + (FM - FN); t0 += FN) {
        const bool domask = (t0 + FN - 1 > s0);

        // K tile: [64][192] = kn | kpe, tf32
        for (int i = tid; i < FN * 48; i += 256) {
            int r = i / 48, c4 = i % 48;
            long long trow = (long long)(b*S_ + t0 + r);
            float4 x4 = (c4 < 32)
                ? *(const float4*)(knh + trow*NOPE_ + c4*4)
                : *(const float4*)(kpe + trow*ROPE_ + (c4-32)*4);
            uint4 u = make_uint4(f2tf(x4.x), f2tf(x4.y), f2tf(x4.z), f2tf(x4.w));
            *(uint4*)(sK + r*QP2 + c4*4) = u;
        }
        // Vt tile: transpose (t-contiguous stores, conflict-free)
        for (int i = tid; i < FN * 32; i += 256) {
            int t  = i & 63, c4 = i >> 6;
            float4 x4 = *(const float4*)(vh + (long long)(b*S_ + t0 + t)*V_ + c4*4);
            int d = c4 * 4;
            sVt[(d+0)*VTP + t] = __uint_as_float(f2tf(x4.x));
            sVt[(d+1)*VTP + t] = __uint_as_float(f2tf(x4.y));
            sVt[(d+2)*VTP + t] = __uint_as_float(f2tf(x4.z));
            sVt[(d+3)*VTP + t] = __uint_as_float(f2tf(x4.w));
        }
        __syncthreads();

        // ---- scores: warp tile 16x64, mma over 192 ----
        float sc[8][4];
#pragma unroll
        for (int ni = 0; ni < 8; ni++)
#pragma unroll
            for (int j = 0; j < 4; j++) sc[ni][j] = 0.f;

#pragma unroll
        for (int k8 = 0; k8 < 24; k8++) {
            const int kk = k8 * 8;
            unsigned a0 = __float_as_uint(sQ[(rb+qr)*QP2 + kk + qc]);
            unsigned a1 = __float_as_uint(sQ[(rb+qr+8)*QP2 + kk + qc]);
            unsigned a2 = __float_as_uint(sQ[(rb+qr)*QP2 + kk + qc + 4]);
            unsigned a3 = __float_as_uint(sQ[(rb+qr+8)*QP2 + kk + qc + 4]);
#pragma unroll
            for (int ni = 0; ni < 8; ni++) {
                unsigned b0 = __float_as_uint(sK[(8*ni+qr)*QP2 + kk + qc]);
                unsigned b1 = __float_as_uint(sK[(8*ni+qr)*QP2 + kk + qc + 4]);
                mma8(sc[ni], a0, a1, a2, a3, b0, b1);
            }
        }

        // ---- scale + mask + row max (quad-group) ----
        float mx0 = -INFINITY, mx1 = -INFINITY;
#pragma unroll
        for (int ni = 0; ni < 8; ni++) {
            float v0 = sc[ni][0]*SC, v1 = sc[ni][1]*SC;
            float v2 = sc[ni][2]*SC, v3 = sc[ni][3]*SC;
            if (domask) {
                int cc = t0 + 8*ni + 2*qc;
                if (cc     > g0) v0 = -1e30f;
                if (cc + 1 > g0) v1 = -1e30f;
                if (cc     > g1) v2 = -1e30f;
                if (cc + 1 > g1) v3 = -1e30f;
            }
            sc[ni][0]=v0; sc[ni][1]=v1; sc[ni][2]=v2; sc[ni][3]=v3;
            mx0 = fmaxf(mx0, fmaxf(v0, v1));
            mx1 = fmaxf(mx1, fmaxf(v2, v3));
        }
        mx0 = fmaxf(mx0, __shfl_xor_sync(0xffffffffu, mx0, 1));
        mx0 = fmaxf(mx0, __shfl_xor_sync(0xffffffffu, mx0, 2));
        mx1 = fmaxf(mx1, __shfl_xor_sync(0xffffffffu, mx1, 1));
        mx1 = fmaxf(mx1, __shfl_xor_sync(0xffffffffu, mx1, 2));

        float mn0 = fmaxf(mr0, mx0), mn1 = fmaxf(mr1, mx1);
        float al0 = __expf(mr0 - mn0), al1 = __expf(mr1 - mn1);

        // ---- exp + row sum + store P (tf32) ----
        float s0s = 0.f, s1s = 0.f;
#pragma unroll
        for (int ni = 0; ni < 8; ni++) {
            float p0 = __expf(sc[ni][0] - mn0), p1 = __expf(sc[ni][1] - mn0);
            float p2 = __expf(sc[ni][2] - mn1), p3 = __expf(sc[ni][3] - mn1);
            s0s += p0 + p1; s1s += p2 + p3;
            float2 f0 = make_float2(__uint_as_float(f2tf(p0)), __uint_as_float(f2tf(p1)));
            float2 f1 = make_float2(__uint_as_float(f2tf(p2)), __uint_as_float(f2tf(p3)));
            *(float2*)(sP + (rb+qr)*VTP   + 8*ni + 2*qc) = f0;
            *(float2*)(sP + (rb+qr+8)*VTP + 8*ni + 2*qc) = f1;
        }
        s0s += __shfl_xor_sync(0xffffffffu, s0s, 1);
        s0s += __shfl_xor_sync(0xffffffffu, s0s, 2);
        s1s += __shfl_xor_sync(0xffffffffu, s1s, 1);
        s1s += __shfl_xor_sync(0xffffffffu, s1s, 2);
        l0 = l0 * al0 + s0s;
        l1 = l1 * al1 + s1s;
        mr0 = mn0; mr1 = mn1;

#pragma unroll
        for (int ni = 0; ni < 16; ni++) {
            o[ni][0] *= al0; o[ni][1] *= al0;
            o[ni][2] *= al1; o[ni][3] *= al1;
        }
        __syncwarp();

        // ---- PV: warp tile 16x128, k = 64 ----
#pragma unroll
        for (int k8 = 0; k8 < 8; k8++) {
            const int kk = k8 * 8;
            unsigned a0 = __float_as_uint(sP[(rb+qr)*VTP + kk + qc]);
            unsigned a1 = __float_as_uint(sP[(rb+qr+8)*VTP + kk + qc]);
            unsigned a2 = __float_as_uint(sP[(rb+qr)*VTP + kk + qc + 4]);
            unsigned a3 = __float_as_uint(sP[(rb+qr+8)*VTP + kk + qc + 4]);
#pragma unroll
            for (int ni = 0; ni < 16; ni++) {
                unsigned b0 = __float_as_uint(sVt[(8*ni+qr)*VTP + kk + qc]);
                unsigned b1 = __float_as_uint(sVt[(8*ni+qr)*VTP + kk + qc + 4]);
                mma8(o[ni], a0, a1, a2, a3, b0, b1);
            }
        }
        __syncthreads();
    }

    // ---- epilogue ----
    float i0 = 1.0f / l0, i1 = 1.0f / l1;
    float* out0 = out + (long long)(b*S_ + s0 + rb + qr) * (H_*V_) + h*V_;
    float* out1 = out0 + 8LL * (H_*V_);
#pragma unroll
    for (int ni = 0; ni < 16; ni++) {
        int cn = 8*ni + 2*qc;
        *(float2*)(out0 + cn) = make_float2(o[ni][0]*i0, o[ni][1]*i0);
        *(float2*)(out1 + cn) = make_float2(o[ni][2]*i1, o[ni][3]*i1);
    }
}

// =====================================================================
// Host launch
// =====================================================================
static float* sym_addr(const void* sym) {
    void* p = nullptr;
    cudaGetSymbolAddress(&p, sym);
    return (float*)p;
}

extern "C" void kernel_launch(void* const* d_in, const int* in_sizes, int n_in,
                              void* d_out, int out_size)
{
    const float* x     = (const float*)d_in[0];
    const float* wq    = (const float*)d_in[1];
    const float* wkv_a = (const float*)d_in[2];
    const float* wkv_b = (const float*)d_in[3];
    const float* wo    = (const float*)d_in[4];
    const float* kvw   = (const float*)d_in[5];
    const float* fcos  = (const float*)d_in[6];
    const float* fsin  = (const float*)d_in[7];
    float* out = (float*)d_out;

    float* qb    = sym_addr(g_q);
    float* kvpeb = sym_addr(g_kvpe);
    float* kvb   = sym_addr(g_kv);
    float* kpeb  = sym_addr(g_kpe);
    float* knb   = sym_addr(g_kn);
    float* vb    = sym_addr(g_v);
    float* o2b   = sym_addr(g_o2);

    static bool attr_done = false;
    if (!attr_done) {
        cudaFuncSetAttribute(gemm_tf32_nt, cudaFuncAttributeMaxDynamicSharedMemorySize, GEMM_SMEM);
        cudaFuncSetAttribute(flash_k,      cudaFuncAttributeMaxDynamicSharedMemorySize, FLASH_SMEM);
        attr_done = true;
    }

    dim3 blk(128);

    // 1. q = x @ wq^T   (4096 x 3072, K=2048)
    gemm_tf32_nt<<<dim3(24, 32, 1), blk, GEMM_SMEM>>>(
        x, wq, qb, BS_, H_*QK_, DIM_, DIM_, DIM_, H_*QK_, 0, 0, 0);

    // 2. kvpe = x @ wkv_a^T   (4096 x 576, K=2048)
    gemm_tf32_nt<<<dim3(5, 32, 1), blk, GEMM_SMEM>>>(
        x, wkv_a, kvpeb, BS_, C_+ROPE_, DIM_, DIM_, DIM_, C_+ROPE_, 0, 0, 0);

    // 3. rope(q_pe)
    rope_q_k<<<BS_, H_*32>>>(qb, fcos, fsin);

    // 4. rmsnorm(kv), rope(k_pe)
    kv_prep_k<<<BS_, 128>>>(kvpeb, kvw, fcos, fsin, kvb, kpeb);

    // 5. k_nope[h] = kv @ wkv_b[h,:128,:]^T
    gemm_tf32_nt<<<dim3(1, 32, H_), blk, GEMM_SMEM>>>(
        kvb, wkv_b, knb,
        BS_, NOPE_, C_, C_, C_, NOPE_,
        0, (long long)(NOPE_+V_)*C_, (long long)BS_*NOPE_);

    // 6. v[h] = kv @ wkv_b[h,128:,:]^T
    gemm_tf32_nt<<<dim3(1, 32, H_), blk, GEMM_SMEM>>>(
        kvb, wkv_b + (long long)NOPE_*C_, vb,
        BS_, V_, C_, C_, C_, V_,
        0, (long long)(NOPE_+V_)*C_, (long long)BS_*V_);

    // 7. flash attention -> g_o2
    flash_k<<<dim3(S_/FM, H_, B_), dim3(256), FLASH_SMEM>>>(qb, knb, kpeb, vb, o2b);

    // 8. out = o2 @ wo^T   (4096 x 2048, K=2048)
    gemm_tf32_nt<<<dim3(16, 32, 1), blk, GEMM_SMEM>>>(
        o2b, wo, out, BS_, DIM_, H_*V_, H_*V_, H_*V_, DIM_, 0, 0, 0);

    (void)in_sizes; (void)n_in; (void)out_size;
}

// round 5
// speedup vs baseline: 8.1511x; 1.6593x over previous
#include <cuda_runtime.h>
#include <cuda_bf16.h>
#include <math.h>
#include <stdint.h>

// ---------------- problem constants ----------------
#define B_    2
#define S_    2048
#define DIM_  2048
#define H_    16
#define C_    512
#define NOPE_ 128
#define ROPE_ 64
#define V_    128
#define QK_   192
#define BS_   (B_*S_)

// ---------------- scratch ----------------
__device__ float g_q[(long long)BS_*H_*QK_];
__device__ float g_kvpe[(long long)BS_*(C_+ROPE_)];
__device__ float g_kv[(long long)BS_*C_];
__device__ float g_kpe[(long long)BS_*ROPE_];
__device__ float g_knv[(long long)H_*BS_*256];   // per-head [k_nope(128) | v(128)]
__device__ float g_o2[(long long)BS_*H_*V_];
// tf32-rounded copies of GEMM inputs
__device__ float g_xr [(long long)BS_*DIM_];
__device__ float g_wqr[(long long)(H_*QK_)*DIM_];
__device__ float g_war[(long long)(C_+ROPE_)*DIM_];
__device__ float g_wbr[(long long)H_*256*C_];
__device__ float g_wor[(long long)DIM_*(H_*V_)];

// ---------------- helpers ----------------
__device__ __forceinline__ unsigned f2tf(float f) {
    unsigned u; asm("cvt.rna.tf32.f32 %0, %1;" : "=r"(u) : "f"(f)); return u;
}
__device__ __forceinline__ void mma8(float* c, unsigned a0, unsigned a1, unsigned a2,
                                     unsigned a3, unsigned b0, unsigned b1) {
    asm volatile(
        "mma.sync.aligned.m16n8k8.row.col.f32.tf32.tf32.f32 "
        "{%0,%1,%2,%3},{%4,%5,%6,%7},{%8,%9},{%0,%1,%2,%3};"
        : "+f"(c[0]), "+f"(c[1]), "+f"(c[2]), "+f"(c[3])
        : "r"(a0), "r"(a1), "r"(a2), "r"(a3), "r"(b0), "r"(b1));
}
__device__ __forceinline__ uint32_t su32(const void* p) {
    uint32_t a;
    asm("{ .reg .u64 t; cvta.to.shared.u64 t, %1; cvt.u32.u64 %0, t; }"
        : "=r"(a) : "l"(p));
    return a;
}

// =====================================================================
// tf32 pre-round: dst = rna(src), vectorized
// =====================================================================
__global__ void tfround_k(const float4* __restrict__ src, float4* __restrict__ dst,
                          int n4)
{
    int i = blockIdx.x * blockDim.x + threadIdx.x;
    if (i < n4) {
        float4 v = src[i];
        uint4 u = make_uint4(f2tf(v.x), f2tf(v.y), f2tf(v.z), f2tf(v.w));
        dst[i] = *(float4*)&u;
    }
}

// =====================================================================
// NT GEMM, legacy tf32 mma + 3-stage cp.async pipeline.
// C = A @ B^T. A: MxK (lda), B: NxK (ldb). Inputs PRE-ROUNDED to tf32.
// CTA 128x128xk32, 128 thr, 4 warps 64x64. XOR-swizzled 128B smem rows.
// =====================================================================
#define STG 3
#define TILEB 32768            // A 16KB + B 16KB per stage
#define GEMM_SMEM (STG*TILEB)

__global__ __launch_bounds__(128) void gemm_cp(
    const float* __restrict__ A, const float* __restrict__ Bm, float* __restrict__ Cm,
    int M, int N, int K, int lda, int ldb, int ldc,
    long long sAz, long long sBz, long long sCz)
{
    A  += (long long)blockIdx.z * sAz;
    Bm += (long long)blockIdx.z * sBz;
    Cm += (long long)blockIdx.z * sCz;

    extern __shared__ __align__(128) char smem[];
    const uint32_t sbase = su32(smem);

    const int tid  = threadIdx.x;
    const int lane = tid & 31;
    const int warp = tid >> 5;
    const int m0 = blockIdx.y * 128;
    const int n0 = blockIdx.x * 128;
    const int wm = (warp >> 1) * 64;
    const int wn = (warp & 1) * 64;
    const int qr = lane >> 2;
    const int qc = lane & 3;
    const int xr4 = 4 * qr;          // XOR term (constant per thread)

    float acc[4][8][4];
#pragma unroll
    for (int mi = 0; mi < 4; mi++)
#pragma unroll
        for (int ni = 0; ni < 8; ni++)
#pragma unroll
            for (int j = 0; j < 4; j++) acc[mi][ni][j] = 0.f;

    // per-thread chunk map: 8 A-chunks + 8 B-chunks per stage (16B each)
    const int crow = tid >> 3;         // base row step: id = tid + i*128 -> row = id>>3
    const int cc   = tid & 7;          // chunk col 0..7

    auto issue_stage = [&](int buf, int k0) {
        uint32_t abase = sbase + buf * TILEB;
        uint32_t bbase = abase + 16384;
        uint32_t dcol  = (uint32_t)((cc ^ (crow & 7)) << 4);
#pragma unroll
        for (int i = 0; i < 8; i++) {
            int row = crow + i * 16;
            uint32_t dst = abase + row * 128 + (uint32_t)(((cc ^ (row & 7)) << 4));
            const float* src = A + (long long)(m0 + row) * lda + k0 + cc * 4;
            asm volatile("cp.async.cg.shared.global [%0], [%1], 16;"
                         :: "r"(dst), "l"(src));
        }
        (void)dcol;
#pragma unroll
        for (int i = 0; i < 8; i++) {
            int row = crow + i * 16;
            uint32_t dst = bbase + row * 128 + (uint32_t)(((cc ^ (row & 7)) << 4));
            const float* src = Bm + (long long)(n0 + row) * ldb + k0 + cc * 4;
            int sz = (n0 + row < N) ? 16 : 0;
            asm volatile("cp.async.cg.shared.global [%0], [%1], 16, %2;"
                         :: "r"(dst), "l"(src), "r"(sz));
        }
        asm volatile("cp.async.commit_group;" ::: "memory");
    };

    const int S = K >> 5;
    issue_stage(0, 0);
    if (S > 1) issue_stage(1, 32);

    for (int s = 0; s < S; s++) {
        if (s + 1 < S) asm volatile("cp.async.wait_group 1;" ::: "memory");
        else           asm volatile("cp.async.wait_group 0;" ::: "memory");
        __syncthreads();
        if (s + 2 < S) issue_stage((s + 2) % STG, (s + 2) * 32);

        const float* as = (const float*)(smem + (s % STG) * TILEB);
        const float* bs = as + 4096;

#pragma unroll
        for (int k8 = 0; k8 < 4; k8++) {
            const int kk = k8 * 8;
            const int k0i = (kk + qc) ^ xr4;
            const int k1i = (kk + qc + 4) ^ xr4;
            unsigned a[4][4], b[8][2];
#pragma unroll
            for (int mi = 0; mi < 4; mi++) {
                int r = wm + mi * 16 + qr;
                a[mi][0] = __float_as_uint(as[r * 32 + k0i]);
                a[mi][1] = __float_as_uint(as[(r + 8) * 32 + k0i]);
                a[mi][2] = __float_as_uint(as[r * 32 + k1i]);
                a[mi][3] = __float_as_uint(as[(r + 8) * 32 + k1i]);
            }
#pragma unroll
            for (int ni = 0; ni < 8; ni++) {
                int rn = wn + ni * 8 + qr;
                b[ni][0] = __float_as_uint(bs[rn * 32 + k0i]);
                b[ni][1] = __float_as_uint(bs[rn * 32 + k1i]);
            }
#pragma unroll
            for (int mi = 0; mi < 4; mi++)
#pragma unroll
                for (int ni = 0; ni < 8; ni++)
                    mma8(acc[mi][ni], a[mi][0], a[mi][1], a[mi][2], a[mi][3],
                         b[ni][0], b[ni][1]);
        }
    }

#pragma unroll
    for (int mi = 0; mi < 4; mi++) {
        int r = m0 + wm + mi * 16 + qr;
#pragma unroll
        for (int ni = 0; ni < 8; ni++) {
            int cn = n0 + wn + ni * 8 + 2 * qc;
            if (cn < N) {
                *(float2*)(Cm + (long long)r * ldc + cn) =
                    make_float2(acc[mi][ni][0], acc[mi][ni][1]);
                *(float2*)(Cm + (long long)(r + 8) * ldc + cn) =
                    make_float2(acc[mi][ni][2], acc[mi][ni][3]);
            }
        }
    }
}

// =====================================================================
// RoPE on q_pe (in-place). grid = BS_, block = 512
// =====================================================================
__global__ void rope_q_k(float* __restrict__ q,
                         const float* __restrict__ fcos, const float* __restrict__ fsin)
{
    int bs = blockIdx.x;
    int s  = bs & (S_ - 1);
    int t  = threadIdx.x;
    int h  = t >> 5, i = t & 31;
    float c  = fcos[s*(ROPE_/2) + i];
    float sn = fsin[s*(ROPE_/2) + i];
    float* p = q + (long long)bs * (H_*QK_) + h*QK_ + NOPE_ + 2*i;
    float a = p[0], b = p[1];
    p[0] = a*c - b*sn;
    p[1] = a*sn + b*c;
}

// =====================================================================
// RMSNorm(kv)*w (tf32-rounded out) and RoPE(k_pe). grid = BS_, block = 128
// =====================================================================
__global__ void kv_prep_k(const float* __restrict__ kvpe, const float* __restrict__ w,
                          const float* __restrict__ fcos, const float* __restrict__ fsin,
                          float* __restrict__ kvout, float* __restrict__ kpeout)
{
    int bs = blockIdx.x;
    int s  = bs & (S_ - 1);
    const float* row = kvpe + (long long)bs * (C_ + ROPE_);
    __shared__ float red[4];
    int t = threadIdx.x;
    float v[4]; float ss = 0.f;
#pragma unroll
    for (int i = 0; i < 4; i++) { v[i] = row[t + i*128]; ss = fmaf(v[i], v[i], ss); }
#pragma unroll
    for (int o = 16; o > 0; o >>= 1) ss += __shfl_xor_sync(0xffffffffu, ss, o);
    if ((t & 31) == 0) red[t >> 5] = ss;
    __syncthreads();
    float tot = red[0] + red[1] + red[2] + red[3];
    float r = rsqrtf(tot * (1.0f/512.0f) + 1e-6f);
#pragma unroll
    for (int i = 0; i < 4; i++) {
        int c = t + i*128;
        kvout[(long long)bs*C_ + c] = __uint_as_float(f2tf(v[i] * r * w[c]));
    }
    if (t < 32) {
        float c  = fcos[s*(ROPE_/2) + t];
        float sn = fsin[s*(ROPE_/2) + t];
        float a = row[C_ + 2*t], b = row[C_ + 2*t + 1];
        kpeout[(long long)bs*ROPE_ + 2*t]     = a*c - b*sn;
        kpeout[(long long)bs*ROPE_ + 2*t + 1] = a*sn + b*c;
    }
}

// =====================================================================
// TF32 (legacy mma) causal flash attention — proven R3 design.
// CTA: 128 q-rows, 8 warps (16 rows each). K/V tiles of 64.
// Epilogue rounds o2 to tf32 (consumed by final GEMM via cp.async).
// =====================================================================
#define FM  128
#define FN  64
#define QP2 196
#define VTP 68
#define FLASH_SMEM ((FM*QP2 + FN*QP2 + V_*VTP + FM*VTP) * 4)

__global__ __launch_bounds__(256, 1) void flash_k(
    const float* __restrict__ q,    // (bs, H, 192) roped
    const float* __restrict__ knv,  // (H, bs, 256) = [k_nope | v]
    const float* __restrict__ kpe,  // (bs, 64)
    float* __restrict__ out)        // (bs, H*128)
{
    extern __shared__ float sm[];
    float* sQ  = sm;
    float* sK  = sQ  + FM*QP2;
    float* sVt = sK  + FN*QP2;
    float* sP  = sVt + V_*VTP;

    int bx = blockIdx.x;
    int nb = gridDim.x;
    int sblk = (bx & 1) ? (nb - 1 - (bx >> 1)) : (bx >> 1);
    const int s0 = sblk * FM;
    const int h  = blockIdx.y;
    const int b  = blockIdx.z;
    const int tid = threadIdx.x;
    const int lane = tid & 31;
    const int warp = tid >> 5;
    const int rb = warp * 16;
    const int qr = lane >> 2;
    const int qc = lane & 3;
    const int g0 = s0 + rb + qr;
    const int g1 = g0 + 8;

    const float* knh = knv + (long long)h * BS_ * 256;
    const float* vh  = knh + 128;
    const float SC = 0.07216878364870322f;

    for (int i = tid; i < FM * 48; i += 256) {
        int r = i / 48, c4 = i % 48;
        float4 x4 = *(const float4*)(q + (long long)(b*S_ + s0 + r) * (H_*QK_) + h*QK_ + c4*4);
        uint4 u = make_uint4(f2tf(x4.x), f2tf(x4.y), f2tf(x4.z), f2tf(x4.w));
        *(uint4*)(sQ + r*QP2 + c4*4) = u;
    }

    float mr0 = -INFINITY, mr1 = -INFINITY, l0 = 0.f, l1 = 0.f;
    float o[16][4];
#pragma unroll
    for (int ni = 0; ni < 16; ni++)
#pragma unroll
        for (int j = 0; j < 4; j++) o[ni][j] = 0.f;

    __syncthreads();

    for (int t0 = 0; t0 <= s0 + (FM - FN); t0 += FN) {
        const bool domask = (t0 + FN - 1 > s0);

        for (int i = tid; i < FN * 48; i += 256) {
            int r = i / 48, c4 = i % 48;
            long long trow = (long long)(b*S_ + t0 + r);
            float4 x4 = (c4 < 32)
                ? *(const float4*)(knh + trow*256 + c4*4)
                : *(const float4*)(kpe + trow*ROPE_ + (c4-32)*4);
            uint4 u = make_uint4(f2tf(x4.x), f2tf(x4.y), f2tf(x4.z), f2tf(x4.w));
            *(uint4*)(sK + r*QP2 + c4*4) = u;
        }
        for (int i = tid; i < FN * 32; i += 256) {
            int t  = i & 63, c4 = i >> 6;
            float4 x4 = *(const float4*)(vh + (long long)(b*S_ + t0 + t)*256 + c4*4);
            int d = c4 * 4;
            sVt[(d+0)*VTP + t] = __uint_as_float(f2tf(x4.x));
            sVt[(d+1)*VTP + t] = __uint_as_float(f2tf(x4.y));
            sVt[(d+2)*VTP + t] = __uint_as_float(f2tf(x4.z));
            sVt[(d+3)*VTP + t] = __uint_as_float(f2tf(x4.w));
        }
        __syncthreads();

        float sc[8][4];
#pragma unroll
        for (int ni = 0; ni < 8; ni++)
#pragma unroll
            for (int j = 0; j < 4; j++) sc[ni][j] = 0.f;

#pragma unroll
        for (int k8 = 0; k8 < 24; k8++) {
            const int kk = k8 * 8;
            unsigned a0 = __float_as_uint(sQ[(rb+qr)*QP2 + kk + qc]);
            unsigned a1 = __float_as_uint(sQ[(rb+qr+8)*QP2 + kk + qc]);
            unsigned a2 = __float_as_uint(sQ[(rb+qr)*QP2 + kk + qc + 4]);
            unsigned a3 = __float_as_uint(sQ[(rb+qr+8)*QP2 + kk + qc + 4]);
#pragma unroll
            for (int ni = 0; ni < 8; ni++) {
                unsigned b0 = __float_as_uint(sK[(8*ni+qr)*QP2 + kk + qc]);
                unsigned b1 = __float_as_uint(sK[(8*ni+qr)*QP2 + kk + qc + 4]);
                mma8(sc[ni], a0, a1, a2, a3, b0, b1);
            }
        }

        float mx0 = -INFINITY, mx1 = -INFINITY;
#pragma unroll
        for (int ni = 0; ni < 8; ni++) {
            float v0 = sc[ni][0]*SC, v1 = sc[ni][1]*SC;
            float v2 = sc[ni][2]*SC, v3 = sc[ni][3]*SC;
            if (domask) {
                int cc = t0 + 8*ni + 2*qc;
                if (cc     > g0) v0 = -1e30f;
                if (cc + 1 > g0) v1 = -1e30f;
                if (cc     > g1) v2 = -1e30f;
                if (cc + 1 > g1) v3 = -1e30f;
            }
            sc[ni][0]=v0; sc[ni][1]=v1; sc[ni][2]=v2; sc[ni][3]=v3;
            mx0 = fmaxf(mx0, fmaxf(v0, v1));
            mx1 = fmaxf(mx1, fmaxf(v2, v3));
        }
        mx0 = fmaxf(mx0, __shfl_xor_sync(0xffffffffu, mx0, 1));
        mx0 = fmaxf(mx0, __shfl_xor_sync(0xffffffffu, mx0, 2));
        mx1 = fmaxf(mx1, __shfl_xor_sync(0xffffffffu, mx1, 1));
        mx1 = fmaxf(mx1, __shfl_xor_sync(0xffffffffu, mx1, 2));

        float mn0 = fmaxf(mr0, mx0), mn1 = fmaxf(mr1, mx1);
        float al0 = __expf(mr0 - mn0), al1 = __expf(mr1 - mn1);

        float s0s = 0.f, s1s = 0.f;
#pragma unroll
        for (int ni = 0; ni < 8; ni++) {
            float p0 = __expf(sc[ni][0] - mn0), p1 = __expf(sc[ni][1] - mn0);
            float p2 = __expf(sc[ni][2] - mn1), p3 = __expf(sc[ni][3] - mn1);
            s0s += p0 + p1; s1s += p2 + p3;
            float2 f0 = make_float2(__uint_as_float(f2tf(p0)), __uint_as_float(f2tf(p1)));
            float2 f1 = make_float2(__uint_as_float(f2tf(p2)), __uint_as_float(f2tf(p3)));
            *(float2*)(sP + (rb+qr)*VTP   + 8*ni + 2*qc) = f0;
            *(float2*)(sP + (rb+qr+8)*VTP + 8*ni + 2*qc) = f1;
        }
        s0s += __shfl_xor_sync(0xffffffffu, s0s, 1);
        s0s += __shfl_xor_sync(0xffffffffu, s0s, 2);
        s1s += __shfl_xor_sync(0xffffffffu, s1s, 1);
        s1s += __shfl_xor_sync(0xffffffffu, s1s, 2);
        l0 = l0 * al0 + s0s;
        l1 = l1 * al1 + s1s;
        mr0 = mn0; mr1 = mn1;

#pragma unroll
        for (int ni = 0; ni < 16; ni++) {
            o[ni][0] *= al0; o[ni][1] *= al0;
            o[ni][2] *= al1; o[ni][3] *= al1;
        }
        __syncwarp();

#pragma unroll
        for (int k8 = 0; k8 < 8; k8++) {
            const int kk = k8 * 8;
            unsigned a0 = __float_as_uint(sP[(rb+qr)*VTP + kk + qc]);
            unsigned a1 = __float_as_uint(sP[(rb+qr+8)*VTP + kk + qc]);
            unsigned a2 = __float_as_uint(sP[(rb+qr)*VTP + kk + qc + 4]);
            unsigned a3 = __float_as_uint(sP[(rb+qr+8)*VTP + kk + qc + 4]);
#pragma unroll
            for (int ni = 0; ni < 16; ni++) {
                unsigned b0 = __float_as_uint(sVt[(8*ni+qr)*VTP + kk + qc]);
                unsigned b1 = __float_as_uint(sVt[(8*ni+qr)*VTP + kk + qc + 4]);
                mma8(o[ni], a0, a1, a2, a3, b0, b1);
            }
        }
        __syncthreads();
    }

    float i0 = 1.0f / l0, i1 = 1.0f / l1;
    float* out0 = out + (long long)(b*S_ + s0 + rb + qr) * (H_*V_) + h*V_;
    float* out1 = out0 + 8LL * (H_*V_);
#pragma unroll
    for (int ni = 0; ni < 16; ni++) {
        int cn = 8*ni + 2*qc;
        *(float2*)(out0 + cn) = make_float2(
            __uint_as_float(f2tf(o[ni][0]*i0)), __uint_as_float(f2tf(o[ni][1]*i0)));
        *(float2*)(out1 + cn) = make_float2(
            __uint_as_float(f2tf(o[ni][2]*i1)), __uint_as_float(f2tf(o[ni][3]*i1)));
    }
}

// =====================================================================
// Host launch
// =====================================================================
static float* sym_addr(const void* sym) {
    void* p = nullptr;
    cudaGetSymbolAddress(&p, sym);
    return (float*)p;
}

extern "C" void kernel_launch(void* const* d_in, const int* in_sizes, int n_in,
                              void* d_out, int out_size)
{
    const float* x     = (const float*)d_in[0];
    const float* wq    = (const float*)d_in[1];
    const float* wkv_a = (const float*)d_in[2];
    const float* wkv_b = (const float*)d_in[3];
    const float* wo    = (const float*)d_in[4];
    const float* kvw   = (const float*)d_in[5];
    const float* fcos  = (const float*)d_in[6];
    const float* fsin  = (const float*)d_in[7];
    float* out = (float*)d_out;

    float* qb    = sym_addr(g_q);
    float* kvpeb = sym_addr(g_kvpe);
    float* kvb   = sym_addr(g_kv);
    float* kpeb  = sym_addr(g_kpe);
    float* knvb  = sym_addr(g_knv);
    float* o2b   = sym_addr(g_o2);
    float* xr    = sym_addr(g_xr);
    float* wqr   = sym_addr(g_wqr);
    float* war   = sym_addr(g_war);
    float* wbr   = sym_addr(g_wbr);
    float* wor   = sym_addr(g_wor);

    static bool attr_done = false;
    if (!attr_done) {
        cudaFuncSetAttribute(gemm_cp, cudaFuncAttributeMaxDynamicSharedMemorySize, GEMM_SMEM);
        cudaFuncSetAttribute(flash_k, cudaFuncAttributeMaxDynamicSharedMemorySize, FLASH_SMEM);
        attr_done = true;
    }

    // 0. pre-round GEMM inputs to tf32
    {
        auto rr = [&](const float* s, float* d, long long n) {
            int n4 = (int)(n / 4);
            tfround_k<<<(n4 + 255) / 256, 256>>>((const float4*)s, (float4*)d, n4);
        };
        rr(x,     xr,  (long long)BS_*DIM_);
        rr(wq,    wqr, (long long)(H_*QK_)*DIM_);
        rr(wkv_a, war, (long long)(C_+ROPE_)*DIM_);
        rr(wkv_b, wbr, (long long)H_*256*C_);
        rr(wo,    wor, (long long)DIM_*(H_*V_));
    }

    dim3 blk(128);

    // 1. q = xr @ wqr^T   (4096 x 3072, K=2048)
    gemm_cp<<<dim3(24, 32, 1), blk, GEMM_SMEM>>>(
        xr, wqr, qb, BS_, H_*QK_, DIM_, DIM_, DIM_, H_*QK_, 0, 0, 0);

    // 2. kvpe = xr @ war^T   (4096 x 576, K=2048)
    gemm_cp<<<dim3(5, 32, 1), blk, GEMM_SMEM>>>(
        xr, war, kvpeb, BS_, C_+ROPE_, DIM_, DIM_, DIM_, C_+ROPE_, 0, 0, 0);

    // 3. rope(q_pe)
    rope_q_k<<<BS_, H_*32>>>(qb, fcos, fsin);

    // 4. rmsnorm(kv) [tf32-rounded], rope(k_pe)
    kv_prep_k<<<BS_, 128>>>(kvpeb, kvw, fcos, fsin, kvb, kpeb);

    // 5. knv[h] = kv @ wbr[h]^T   (N=256 per head: k_nope | v)
    gemm_cp<<<dim3(2, 32, H_), blk, GEMM_SMEM>>>(
        kvb, wbr, knvb,
        BS_, 256, C_, C_, C_, 256,
        0, (long long)256*C_, (long long)BS_*256);

    // 6. flash attention -> g_o2 (tf32-rounded)
    flash_k<<<dim3(S_/FM, H_, B_), dim3(256), FLASH_SMEM>>>(qb, knvb, kpeb, o2b);

    // 7. out = o2 @ wor^T   (4096 x 2048, K=2048)
    gemm_cp<<<dim3(16, 32, 1), blk, GEMM_SMEM>>>(
        o2b, wor, out, BS_, DIM_, H_*V_, H_*V_, H_*V_, DIM_, 0, 0, 0);

    (void)in_sizes; (void)n_in; (void)out_size;
}

// round 7
// speedup vs baseline: 9.1524x; 1.1228x over previous
#include <cuda_runtime.h>
#include <cuda_bf16.h>
#include <math.h>
#include <stdint.h>

// ---------------- problem constants ----------------
#define B_    2
#define S_    2048
#define DIM_  2048
#define H_    16
#define C_    512
#define NOPE_ 128
#define ROPE_ 64
#define V_    128
#define QK_   192
#define BS_   (B_*S_)

// ---------------- scratch ----------------
__device__ float g_q[(long long)BS_*H_*QK_];
__device__ float g_kvpe[(long long)BS_*(C_+ROPE_)];
__device__ float g_kv[(long long)BS_*C_];
__device__ float g_kpe[(long long)BS_*ROPE_];
__device__ float g_knv[(long long)H_*BS_*256];   // per-head [k_nope(128) | v(128)]
__device__ float g_o2[(long long)BS_*H_*V_];
// tf32-rounded copies of GEMM inputs
__device__ float g_xr [(long long)BS_*DIM_];
__device__ float g_wqr[(long long)(H_*QK_)*DIM_];
__device__ float g_war[(long long)(C_+ROPE_)*DIM_];
__device__ float g_wbr[(long long)H_*256*C_];
__device__ float g_wor[(long long)DIM_*(H_*V_)];

// ---------------- helpers ----------------
__device__ __forceinline__ unsigned f2tf(float f) {
    unsigned u; asm("cvt.rna.tf32.f32 %0, %1;" : "=r"(u) : "f"(f)); return u;
}
__device__ __forceinline__ void mma8(float* c, unsigned a0, unsigned a1, unsigned a2,
                                     unsigned a3, unsigned b0, unsigned b1) {
    asm volatile(
        "mma.sync.aligned.m16n8k8.row.col.f32.tf32.tf32.f32 "
        "{%0,%1,%2,%3},{%4,%5,%6,%7},{%8,%9},{%0,%1,%2,%3};"
        : "+f"(c[0]), "+f"(c[1]), "+f"(c[2]), "+f"(c[3])
        : "r"(a0), "r"(a1), "r"(a2), "r"(a3), "r"(b0), "r"(b1));
}
__device__ __forceinline__ uint32_t su32(const void* p) {
    uint32_t a;
    asm("{ .reg .u64 t; cvta.to.shared.u64 t, %1; cvt.u32.u64 %0, t; }"
        : "=r"(a) : "l"(p));
    return a;
}

// =====================================================================
// tf32 pre-round
// =====================================================================
__global__ void tfround_k(const float4* __restrict__ src, float4* __restrict__ dst,
                          int n4)
{
    int i = blockIdx.x * blockDim.x + threadIdx.x;
    if (i < n4) {
        float4 v = src[i];
        uint4 u = make_uint4(f2tf(v.x), f2tf(v.y), f2tf(v.z), f2tf(v.w));
        dst[i] = *(float4*)&u;
    }
}

// =====================================================================
// NT GEMM, legacy tf32 mma + 3-stage cp.async pipeline.
// roundOut=1 -> epilogue stores tf32-rounded values.
// =====================================================================
#define STG 3
#define TILEB 32768
#define GEMM_SMEM (STG*TILEB)

__global__ __launch_bounds__(128) void gemm_cp(
    const float* __restrict__ A, const float* __restrict__ Bm, float* __restrict__ Cm,
    int M, int N, int K, int lda, int ldb, int ldc,
    long long sAz, long long sBz, long long sCz, int roundOut)
{
    A  += (long long)blockIdx.z * sAz;
    Bm += (long long)blockIdx.z * sBz;
    Cm += (long long)blockIdx.z * sCz;

    extern __shared__ __align__(128) char smem[];
    const uint32_t sbase = su32(smem);

    const int tid  = threadIdx.x;
    const int lane = tid & 31;
    const int warp = tid >> 5;
    const int m0 = blockIdx.y * 128;
    const int n0 = blockIdx.x * 128;
    const int wm = (warp >> 1) * 64;
    const int wn = (warp & 1) * 64;
    const int qr = lane >> 2;
    const int qc = lane & 3;
    const int xr4 = 4 * qr;

    float acc[4][8][4];
#pragma unroll
    for (int mi = 0; mi < 4; mi++)
#pragma unroll
        for (int ni = 0; ni < 8; ni++)
#pragma unroll
            for (int j = 0; j < 4; j++) acc[mi][ni][j] = 0.f;

    const int crow = tid >> 3;
    const int cc   = tid & 7;

    auto issue_stage = [&](int buf, int k0) {
        uint32_t abase = sbase + buf * TILEB;
        uint32_t bbase = abase + 16384;
#pragma unroll
        for (int i = 0; i < 8; i++) {
            int row = crow + i * 16;
            uint32_t dst = abase + row * 128 + (uint32_t)(((cc ^ (row & 7)) << 4));
            const float* src = A + (long long)(m0 + row) * lda + k0 + cc * 4;
            asm volatile("cp.async.cg.shared.global [%0], [%1], 16;"
                         :: "r"(dst), "l"(src));
        }
#pragma unroll
        for (int i = 0; i < 8; i++) {
            int row = crow + i * 16;
            uint32_t dst = bbase + row * 128 + (uint32_t)(((cc ^ (row & 7)) << 4));
            const float* src = Bm + (long long)(n0 + row) * ldb + k0 + cc * 4;
            int sz = (n0 + row < N) ? 16 : 0;
            asm volatile("cp.async.cg.shared.global [%0], [%1], 16, %2;"
                         :: "r"(dst), "l"(src), "r"(sz));
        }
        asm volatile("cp.async.commit_group;" ::: "memory");
    };

    const int S = K >> 5;
    issue_stage(0, 0);
    if (S > 1) issue_stage(1, 32);

    for (int s = 0; s < S; s++) {
        if (s + 1 < S) asm volatile("cp.async.wait_group 1;" ::: "memory");
        else           asm volatile("cp.async.wait_group 0;" ::: "memory");
        __syncthreads();
        if (s + 2 < S) issue_stage((s + 2) % STG, (s + 2) * 32);

        const float* as = (const float*)(smem + (s % STG) * TILEB);
        const float* bs = as + 4096;

#pragma unroll
        for (int k8 = 0; k8 < 4; k8++) {
            const int kk = k8 * 8;
            const int k0i = (kk + qc) ^ xr4;
            const int k1i = (kk + qc + 4) ^ xr4;
            unsigned a[4][4], b[8][2];
#pragma unroll
            for (int mi = 0; mi < 4; mi++) {
                int r = wm + mi * 16 + qr;
                a[mi][0] = __float_as_uint(as[r * 32 + k0i]);
                a[mi][1] = __float_as_uint(as[(r + 8) * 32 + k0i]);
                a[mi][2] = __float_as_uint(as[r * 32 + k1i]);
                a[mi][3] = __float_as_uint(as[(r + 8) * 32 + k1i]);
            }
#pragma unroll
            for (int ni = 0; ni < 8; ni++) {
                int rn = wn + ni * 8 + qr;
                b[ni][0] = __float_as_uint(bs[rn * 32 + k0i]);
                b[ni][1] = __float_as_uint(bs[rn * 32 + k1i]);
            }
#pragma unroll
            for (int mi = 0; mi < 4; mi++)
#pragma unroll
                for (int ni = 0; ni < 8; ni++)
                    mma8(acc[mi][ni], a[mi][0], a[mi][1], a[mi][2], a[mi][3],
                         b[ni][0], b[ni][1]);
        }
    }

#pragma unroll
    for (int mi = 0; mi < 4; mi++) {
        int r = m0 + wm + mi * 16 + qr;
#pragma unroll
        for (int ni = 0; ni < 8; ni++) {
            int cn = n0 + wn + ni * 8 + 2 * qc;
            if (cn < N) {
                float v0 = acc[mi][ni][0], v1 = acc[mi][ni][1];
                float v2 = acc[mi][ni][2], v3 = acc[mi][ni][3];
                if (roundOut) {
                    v0 = __uint_as_float(f2tf(v0)); v1 = __uint_as_float(f2tf(v1));
                    v2 = __uint_as_float(f2tf(v2)); v3 = __uint_as_float(f2tf(v3));
                }
                *(float2*)(Cm + (long long)r * ldc + cn)       = make_float2(v0, v1);
                *(float2*)(Cm + (long long)(r + 8) * ldc + cn) = make_float2(v2, v3);
            }
        }
    }
}

// =====================================================================
// RoPE on q_pe (rounded out). grid = BS_, block = 512
// =====================================================================
__global__ void rope_q_k(float* __restrict__ q,
                         const float* __restrict__ fcos, const float* __restrict__ fsin)
{
    int bs = blockIdx.x;
    int s  = bs & (S_ - 1);
    int t  = threadIdx.x;
    int h  = t >> 5, i = t & 31;
    float c  = fcos[s*(ROPE_/2) + i];
    float sn = fsin[s*(ROPE_/2) + i];
    float* p = q + (long long)bs * (H_*QK_) + h*QK_ + NOPE_ + 2*i;
    float a = p[0], b = p[1];
    p[0] = __uint_as_float(f2tf(a*c - b*sn));
    p[1] = __uint_as_float(f2tf(a*sn + b*c));
}

// =====================================================================
// RMSNorm(kv)*w and RoPE(k_pe), both tf32-rounded. grid = BS_, block = 128
// =====================================================================
__global__ void kv_prep_k(const float* __restrict__ kvpe, const float* __restrict__ w,
                          const float* __restrict__ fcos, const float* __restrict__ fsin,
                          float* __restrict__ kvout, float* __restrict__ kpeout)
{
    int bs = blockIdx.x;
    int s  = bs & (S_ - 1);
    const float* row = kvpe + (long long)bs * (C_ + ROPE_);
    __shared__ float red[4];
    int t = threadIdx.x;
    float v[4]; float ss = 0.f;
#pragma unroll
    for (int i = 0; i < 4; i++) { v[i] = row[t + i*128]; ss = fmaf(v[i], v[i], ss); }
#pragma unroll
    for (int o = 16; o > 0; o >>= 1) ss += __shfl_xor_sync(0xffffffffu, ss, o);
    if ((t & 31) == 0) red[t >> 5] = ss;
    __syncthreads();
    float tot = red[0] + red[1] + red[2] + red[3];
    float r = rsqrtf(tot * (1.0f/512.0f) + 1e-6f);
#pragma unroll
    for (int i = 0; i < 4; i++) {
        int c = t + i*128;
        kvout[(long long)bs*C_ + c] = __uint_as_float(f2tf(v[i] * r * w[c]));
    }
    if (t < 32) {
        float c  = fcos[s*(ROPE_/2) + t];
        float sn = fsin[s*(ROPE_/2) + t];
        float a = row[C_ + 2*t], b = row[C_ + 2*t + 1];
        kpeout[(long long)bs*ROPE_ + 2*t]     = __uint_as_float(f2tf(a*c - b*sn));
        kpeout[(long long)bs*ROPE_ + 2*t + 1] = __uint_as_float(f2tf(a*sn + b*c));
    }
}

// =====================================================================
// TF32 flash attention w/ in-loop cp.async K prefetch + reg V prefetch.
// All inputs pre-rounded to tf32 (no cvt in loads).
// =====================================================================
#define FM  128
#define FN  64
#define QP2 196
#define VTP 68
#define FLASH_SMEM ((FM*QP2 + FN*QP2 + V_*VTP + FM*VTP) * 4)

__global__ __launch_bounds__(256, 1) void flash_k(
    const float* __restrict__ q,    // (bs, H, 192) roped, tf32
    const float* __restrict__ knv,  // (H, bs, 256) = [k_nope | v], tf32
    const float* __restrict__ kpe,  // (bs, 64), tf32
    float* __restrict__ out)        // (bs, H*128)
{
    extern __shared__ float sm[];
    float* sQ  = sm;
    float* sK  = sQ  + FM*QP2;
    float* sVt = sK  + FN*QP2;
    float* sP  = sVt + V_*VTP;
    const uint32_t skb = su32(sK);

    int bx = blockIdx.x;
    int nb = gridDim.x;
    int sblk = (bx & 1) ? (nb - 1 - (bx >> 1)) : (bx >> 1);
    const int s0 = sblk * FM;
    const int h  = blockIdx.y;
    const int b  = blockIdx.z;
    const int tid = threadIdx.x;
    const int lane = tid & 31;
    const int warp = tid >> 5;
    const int rb = warp * 16;
    const int qr = lane >> 2;
    const int qc = lane & 3;
    const int g0 = s0 + rb + qr;
    const int g1 = g0 + 8;

    const float* knh = knv + (long long)h * BS_ * 256;
    const float* vh  = knh + 128;
    const float SC = 0.07216878364870322f;

    const int vt = tid & 63;          // V prefetch: this thread's t
    const int vcb = tid >> 6;         // base col group

    auto loadK = [&](int t0) {
#pragma unroll
        for (int i = 0; i < 12; i++) {
            int id = tid + i * 256;
            int r = id / 48, c = id % 48;
            long long trow = (long long)(b*S_ + t0 + r);
            const float* src = (c < 32) ? (knh + trow*256 + c*4)
                                        : (kpe + trow*(long long)ROPE_ + (c-32)*4);
            uint32_t dst = skb + (uint32_t)((r*QP2 + c*4) * 4);
            asm volatile("cp.async.cg.shared.global [%0], [%1], 16;"
                         :: "r"(dst), "l"(src));
        }
        asm volatile("cp.async.commit_group;" ::: "memory");
    };
    float4 vreg[8];
    auto ldV = [&](int t0) {
        const float* vrow = vh + (long long)(b*S_ + t0 + vt) * 256;
#pragma unroll
        for (int j = 0; j < 8; j++)
            vreg[j] = *(const float4*)(vrow + (vcb + j*4) * 4);
    };
    auto stV = [&]() {
#pragma unroll
        for (int j = 0; j < 8; j++) {
            int d = (vcb + j*4) * 4;
            sVt[(d+0)*VTP + vt] = vreg[j].x;
            sVt[(d+1)*VTP + vt] = vreg[j].y;
            sVt[(d+2)*VTP + vt] = vreg[j].z;
            sVt[(d+3)*VTP + vt] = vreg[j].w;
        }
    };

    // Q tile (raw copy)
    for (int i = tid; i < FM * 48; i += 256) {
        int r = i / 48, c4 = i % 48;
        *(float4*)(sQ + r*QP2 + c4*4) =
            *(const float4*)(q + (long long)(b*S_ + s0 + r) * (H_*QK_) + h*QK_ + c4*4);
    }

    float mr0 = -INFINITY, mr1 = -INFINITY, l0 = 0.f, l1 = 0.f;
    float o[16][4];
#pragma unroll
    for (int ni = 0; ni < 16; ni++)
#pragma unroll
        for (int j = 0; j < 4; j++) o[ni][j] = 0.f;

    // prologue: K(0) via cp.async, V(0) via regs
    loadK(0);
    ldV(0);
    asm volatile("cp.async.wait_group 0;" ::: "memory");
    stV();
    __syncthreads();

    const int tlast = s0 + (FM - FN);
    for (int t0 = 0; t0 <= tlast; t0 += FN) {
        const bool domask = (t0 + FN - 1 > s0);
        const bool nxt = (t0 + FN <= tlast);

        // ---- QK mma ----
        float sc[8][4];
#pragma unroll
        for (int ni = 0; ni < 8; ni++)
#pragma unroll
            for (int j = 0; j < 4; j++) sc[ni][j] = 0.f;

#pragma unroll
        for (int k8 = 0; k8 < 24; k8++) {
            const int kk = k8 * 8;
            unsigned a0 = __float_as_uint(sQ[(rb+qr)*QP2 + kk + qc]);
            unsigned a1 = __float_as_uint(sQ[(rb+qr+8)*QP2 + kk + qc]);
            unsigned a2 = __float_as_uint(sQ[(rb+qr)*QP2 + kk + qc + 4]);
            unsigned a3 = __float_as_uint(sQ[(rb+qr+8)*QP2 + kk + qc + 4]);
#pragma unroll
            for (int ni = 0; ni < 8; ni++) {
                unsigned b0 = __float_as_uint(sK[(8*ni+qr)*QP2 + kk + qc]);
                unsigned b1 = __float_as_uint(sK[(8*ni+qr)*QP2 + kk + qc + 4]);
                mma8(sc[ni], a0, a1, a2, a3, b0, b1);
            }
        }
        __syncthreads();              // everyone done reading sK
        if (nxt) loadK(t0 + FN);      // overlaps softmax + PV

        // ---- softmax ----
        float mx0 = -INFINITY, mx1 = -INFINITY;
#pragma unroll
        for (int ni = 0; ni < 8; ni++) {
            float v0 = sc[ni][0]*SC, v1 = sc[ni][1]*SC;
            float v2 = sc[ni][2]*SC, v3 = sc[ni][3]*SC;
            if (domask) {
                int cc = t0 + 8*ni + 2*qc;
                if (cc     > g0) v0 = -1e30f;
                if (cc + 1 > g0) v1 = -1e30f;
                if (cc     > g1) v2 = -1e30f;
                if (cc + 1 > g1) v3 = -1e30f;
            }
            sc[ni][0]=v0; sc[ni][1]=v1; sc[ni][2]=v2; sc[ni][3]=v3;
            mx0 = fmaxf(mx0, fmaxf(v0, v1));
            mx1 = fmaxf(mx1, fmaxf(v2, v3));
        }
        mx0 = fmaxf(mx0, __shfl_xor_sync(0xffffffffu, mx0, 1));
        mx0 = fmaxf(mx0, __shfl_xor_sync(0xffffffffu, mx0, 2));
        mx1 = fmaxf(mx1, __shfl_xor_sync(0xffffffffu, mx1, 1));
        mx1 = fmaxf(mx1, __shfl_xor_sync(0xffffffffu, mx1, 2));

        float mn0 = fmaxf(mr0, mx0), mn1 = fmaxf(mr1, mx1);
        float al0 = __expf(mr0 - mn0), al1 = __expf(mr1 - mn1);

        float s0s = 0.f, s1s = 0.f;
#pragma unroll
        for (int ni = 0; ni < 8; ni++) {
            float p0 = __expf(sc[ni][0] - mn0), p1 = __expf(sc[ni][1] - mn0);
            float p2 = __expf(sc[ni][2] - mn1), p3 = __expf(sc[ni][3] - mn1);
            s0s += p0 + p1; s1s += p2 + p3;
            float2 f0 = make_float2(__uint_as_float(f2tf(p0)), __uint_as_float(f2tf(p1)));
            float2 f1 = make_float2(__uint_as_float(f2tf(p2)), __uint_as_float(f2tf(p3)));
            *(float2*)(sP + (rb+qr)*VTP   + 8*ni + 2*qc) = f0;
            *(float2*)(sP + (rb+qr+8)*VTP + 8*ni + 2*qc) = f1;
        }
        s0s += __shfl_xor_sync(0xffffffffu, s0s, 1);
        s0s += __shfl_xor_sync(0xffffffffu, s0s, 2);
        s1s += __shfl_xor_sync(0xffffffffu, s1s, 1);
        s1s += __shfl_xor_sync(0xffffffffu, s1s, 2);
        l0 = l0 * al0 + s0s;
        l1 = l1 * al1 + s1s;
        mr0 = mn0; mr1 = mn1;

#pragma unroll
        for (int ni = 0; ni < 16; ni++) {
            o[ni][0] *= al0; o[ni][1] *= al0;
            o[ni][2] *= al1; o[ni][3] *= al1;
        }
        __syncwarp();

        if (nxt) ldV(t0 + FN);        // LDG flight overlaps PV

        // ---- PV mma ----
#pragma unroll
        for (int k8 = 0; k8 < 8; k8++) {
            const int kk = k8 * 8;
            unsigned a0 = __float_as_uint(sP[(rb+qr)*VTP + kk + qc]);
            unsigned a1 = __float_as_uint(sP[(rb+qr+8)*VTP + kk + qc]);
            unsigned a2 = __float_as_uint(sP[(rb+qr)*VTP + kk + qc + 4]);
            unsigned a3 = __float_as_uint(sP[(rb+qr+8)*VTP + kk + qc + 4]);
#pragma unroll
            for (int ni = 0; ni < 16; ni++) {
                unsigned b0 = __float_as_uint(sVt[(8*ni+qr)*VTP + kk + qc]);
                unsigned b1 = __float_as_uint(sVt[(8*ni+qr)*VTP + kk + qc + 4]);
                mma8(o[ni], a0, a1, a2, a3, b0, b1);
            }
        }
        __syncthreads();              // done reading sVt/sP
        if (nxt) {
            stV();
            asm volatile("cp.async.wait_group 0;" ::: "memory");
            __syncthreads();          // K arrival + V stores visible
        }
    }

    float i0 = 1.0f / l0, i1 = 1.0f / l1;
    float* out0 = out + (long long)(b*S_ + s0 + rb + qr) * (H_*V_) + h*V_;
    float* out1 = out0 + 8LL * (H_*V_);
#pragma unroll
    for (int ni = 0; ni < 16; ni++) {
        int cn = 8*ni + 2*qc;
        *(float2*)(out0 + cn) = make_float2(
            __uint_as_float(f2tf(o[ni][0]*i0)), __uint_as_float(f2tf(o[ni][1]*i0)));
        *(float2*)(out1 + cn) = make_float2(
            __uint_as_float(f2tf(o[ni][2]*i1)), __uint_as_float(f2tf(o[ni][3]*i1)));
    }
}

// =====================================================================
// Host launch
// =====================================================================
static float* sym_addr(const void* sym) {
    void* p = nullptr;
    cudaGetSymbolAddress(&p, sym);
    return (float*)p;
}

extern "C" void kernel_launch(void* const* d_in, const int* in_sizes, int n_in,
                              void* d_out, int out_size)
{
    const float* x     = (const float*)d_in[0];
    const float* wq    = (const float*)d_in[1];
    const float* wkv_a = (const float*)d_in[2];
    const float* wkv_b = (const float*)d_in[3];
    const float* wo    = (const float*)d_in[4];
    const float* kvw   = (const float*)d_in[5];
    const float* fcos  = (const float*)d_in[6];
    const float* fsin  = (const float*)d_in[7];
    float* out = (float*)d_out;

    float* qb    = sym_addr(g_q);
    float* kvpeb = sym_addr(g_kvpe);
    float* kvb   = sym_addr(g_kv);
    float* kpeb  = sym_addr(g_kpe);
    float* knvb  = sym_addr(g_knv);
    float* o2b   = sym_addr(g_o2);
    float* xr    = sym_addr(g_xr);
    float* wqr   = sym_addr(g_wqr);
    float* war   = sym_addr(g_war);
    float* wbr   = sym_addr(g_wbr);
    float* wor   = sym_addr(g_wor);

    static bool attr_done = false;
    if (!attr_done) {
        cudaFuncSetAttribute(gemm_cp, cudaFuncAttributeMaxDynamicSharedMemorySize, GEMM_SMEM);
        cudaFuncSetAttribute(flash_k, cudaFuncAttributeMaxDynamicSharedMemorySize, FLASH_SMEM);
        attr_done = true;
    }

    // 0. pre-round GEMM inputs to tf32
    {
        auto rr = [&](const float* s, float* d, long long n) {
            int n4 = (int)(n / 4);
            tfround_k<<<(n4 + 255) / 256, 256>>>((const float4*)s, (float4*)d, n4);
        };
        rr(x,     xr,  (long long)BS_*DIM_);
        rr(wq,    wqr, (long long)(H_*QK_)*DIM_);
        rr(wkv_a, war, (long long)(C_+ROPE_)*DIM_);
        rr(wkv_b, wbr, (long long)H_*256*C_);
        rr(wo,    wor, (long long)DIM_*(H_*V_));
    }

    dim3 blk(128);

    // 1. q = xr @ wqr^T  (rounded out)
    gemm_cp<<<dim3(24, 32, 1), blk, GEMM_SMEM>>>(
        xr, wqr, qb, BS_, H_*QK_, DIM_, DIM_, DIM_, H_*QK_, 0, 0, 0, 1);

    // 2. kvpe = xr @ war^T
    gemm_cp<<<dim3(5, 32, 1), blk, GEMM_SMEM>>>(
        xr, war, kvpeb, BS_, C_+ROPE_, DIM_, DIM_, DIM_, C_+ROPE_, 0, 0, 0, 0);

    // 3. rope(q_pe) (rounded out)
    rope_q_k<<<BS_, H_*32>>>(qb, fcos, fsin);

    // 4. rmsnorm(kv), rope(k_pe) (both rounded)
    kv_prep_k<<<BS_, 128>>>(kvpeb, kvw, fcos, fsin, kvb, kpeb);

    // 5. knv[h] = kv @ wbr[h]^T (rounded out)
    gemm_cp<<<dim3(2, 32, H_), blk, GEMM_SMEM>>>(
        kvb, wbr, knvb,
        BS_, 256, C_, C_, C_, 256,
        0, (long long)256*C_, (long long)BS_*256, 1);

    // 6. flash attention -> g_o2 (rounded out)
    flash_k<<<dim3(S_/FM, H_, B_), dim3(256), FLASH_SMEM>>>(qb, knvb, kpeb, o2b);

    // 7. out = o2 @ wor^T (fp32 out)
    gemm_cp<<<dim3(16, 32, 1), blk, GEMM_SMEM>>>(
        o2b, wor, out, BS_, DIM_, H_*V_, H_*V_, H_*V_, DIM_, 0, 0, 0, 0);

    (void)in_sizes; (void)n_in; (void)out_size;
}

// round 10
// speedup vs baseline: 15.2073x; 1.6616x over previous
#include <cuda_runtime.h>
#include <cuda_fp16.h>
#include <math.h>
#include <stdint.h>

// ---------------- problem constants ----------------
#define B_    2
#define S_    2048
#define DIM_  2048
#define H_    16
#define C_    512
#define NOPE_ 128
#define ROPE_ 64
#define V_    128
#define QK_   192
#define BS_   (B_*S_)
#define QLD   3648          // merged [q(3072) | kvpe(576)] row stride

// ---------------- scratch (fp16 pipeline) ----------------
__device__ __half g_qkv[(long long)BS_*QLD];
__device__ __half g_kv [(long long)BS_*C_];
__device__ __half g_kpe[(long long)BS_*ROPE_];
__device__ __half g_knv[(long long)H_*BS_*256];   // per-head [k_nope(128) | v(128)]
__device__ __half g_o2 [(long long)BS_*H_*V_];
__device__ __half g_xh [(long long)BS_*DIM_];
__device__ __half g_wqa[(long long)QLD*DIM_];     // [wq(3072) ; wkv_a(576)] rows
__device__ __half g_wbh[(long long)H_*256*C_];
__device__ __half g_woh[(long long)DIM_*(H_*V_)];

// ---------------- helpers ----------------
__device__ __forceinline__ void mma16(float* c, unsigned a0, unsigned a1, unsigned a2,
                                      unsigned a3, unsigned b0, unsigned b1) {
    asm volatile(
        "mma.sync.aligned.m16n8k16.row.col.f32.f16.f16.f32 "
        "{%0,%1,%2,%3},{%4,%5,%6,%7},{%8,%9},{%0,%1,%2,%3};"
        : "+f"(c[0]), "+f"(c[1]), "+f"(c[2]), "+f"(c[3])
        : "r"(a0), "r"(a1), "r"(a2), "r"(a3), "r"(b0), "r"(b1));
}
__device__ __forceinline__ uint32_t su32(const void* p) {
    uint32_t a;
    asm("{ .reg .u64 t; cvta.to.shared.u64 t, %1; cvt.u32.u64 %0, t; }"
        : "=r"(a) : "l"(p));
    return a;
}
__device__ __forceinline__ unsigned packh2(float a, float b) {
    __half2 h = __floats2half2_rn(a, b);
    return *(unsigned*)&h;
}
__device__ __forceinline__ unsigned packhh(__half a, __half b) {
    __half2 h = __halves2half2(a, b);
    return *(unsigned*)&h;
}

// =====================================================================
// fp32 -> fp16 convert
// =====================================================================
__global__ void hround_k(const float4* __restrict__ src, uint2* __restrict__ dst,
                         int n4)
{
    int i = blockIdx.x * blockDim.x + threadIdx.x;
    if (i < n4) {
        float4 v = src[i];
        uint2 u;
        u.x = packh2(v.x, v.y);
        u.y = packh2(v.z, v.w);
        dst[i] = u;
    }
}

// =====================================================================
// fp16 NT GEMM, m16n8k16 + 3-stage cp.async pipeline.
// C = A @ B^T. A: MxK (lda), B: NxK (ldb). CTA 128x128, k-stage 64.
// smem rows padded to 144B (word stride 36 == 4 mod 32) -> conflict-free.
// OUTH=1: fp16 output; OUTH=0: fp32 output.
// =====================================================================
#define HSTG 3
#define HTILE 36864               // per stage: A 18432 + B 18432
#define GEMM_SMEM (HSTG*HTILE)    // 110592

template<int OUTH>
__global__ __launch_bounds__(128) void gemm_h(
    const __half* __restrict__ A, const __half* __restrict__ Bm, void* Cv,
    int M, int N, int K, int lda, int ldb, int ldc,
    long long sAz, long long sBz, long long sCz)
{
    A  += (long long)blockIdx.z * sAz;
    Bm += (long long)blockIdx.z * sBz;
    if (OUTH) Cv = (void*)((__half*)Cv + (long long)blockIdx.z * sCz);
    else      Cv = (void*)((float*)Cv  + (long long)blockIdx.z * sCz);

    extern __shared__ __align__(128) char smem[];
    const uint32_t sbase = su32(smem);

    const int tid  = threadIdx.x;
    const int lane = tid & 31;
    const int warp = tid >> 5;
    const int m0 = blockIdx.y * 128;
    const int n0 = blockIdx.x * 128;
    const int wm = (warp >> 1) * 64;
    const int wn = (warp & 1) * 64;
    const int qr = lane >> 2;
    const int qc = lane & 3;

    float acc[4][8][4];
#pragma unroll
    for (int mi = 0; mi < 4; mi++)
#pragma unroll
        for (int ni = 0; ni < 8; ni++)
#pragma unroll
            for (int j = 0; j < 4; j++) acc[mi][ni][j] = 0.f;

    const int crow = tid >> 3;      // 0..15
    const int cc   = tid & 7;       // chunk 0..7 (16B = 8 fp16)

    auto issue_stage = [&](int buf, int k0) {
        uint32_t abase = sbase + buf * HTILE;
        uint32_t bbase = abase + 18432;
#pragma unroll
        for (int i = 0; i < 8; i++) {
            int row = crow + i * 16;
            uint32_t dst = abase + row * 144 + cc * 16;
            const __half* src = A + (long long)(m0 + row) * lda + k0 + cc * 8;
            asm volatile("cp.async.cg.shared.global [%0], [%1], 16;"
                         :: "r"(dst), "l"(src));
        }
#pragma unroll
        for (int i = 0; i < 8; i++) {
            int row = crow + i * 16;
            uint32_t dst = bbase + row * 144 + cc * 16;
            const __half* src = Bm + (long long)(n0 + row) * ldb + k0 + cc * 8;
            int sz = (n0 + row < N) ? 16 : 0;
            asm volatile("cp.async.cg.shared.global [%0], [%1], 16, %2;"
                         :: "r"(dst), "l"(src), "r"(sz));
        }
        asm volatile("cp.async.commit_group;" ::: "memory");
    };

    const int S = K >> 6;
    issue_stage(0, 0);
    if (S > 1) issue_stage(1, 64);

    for (int s = 0; s < S; s++) {
        if (s + 1 < S) asm volatile("cp.async.wait_group 1;" ::: "memory");
        else           asm volatile("cp.async.wait_group 0;" ::: "memory");
        __syncthreads();
        if (s + 2 < S) issue_stage((s + 2) % HSTG, (s + 2) * 64);

        const unsigned* as = (const unsigned*)(smem + (s % HSTG) * HTILE);
        const unsigned* bs = as + 4608;   // 18432B / 4

#pragma unroll
        for (int kb = 0; kb < 4; kb++) {
            const int kw = kb * 8 + qc;
            unsigned a[4][4], b[8][2];
#pragma unroll
            for (int mi = 0; mi < 4; mi++) {
                int r = wm + mi * 16 + qr;
                a[mi][0] = as[r * 36 + kw];
                a[mi][1] = as[(r + 8) * 36 + kw];
                a[mi][2] = as[r * 36 + kw + 4];
                a[mi][3] = as[(r + 8) * 36 + kw + 4];
            }
#pragma unroll
            for (int ni = 0; ni < 8; ni++) {
                int rn = wn + ni * 8 + qr;
                b[ni][0] = bs[rn * 36 + kw];
                b[ni][1] = bs[rn * 36 + kw + 4];
            }
#pragma unroll
            for (int mi = 0; mi < 4; mi++)
#pragma unroll
                for (int ni = 0; ni < 8; ni++)
                    mma16(acc[mi][ni], a[mi][0], a[mi][1], a[mi][2], a[mi][3],
                          b[ni][0], b[ni][1]);
        }
    }

#pragma unroll
    for (int mi = 0; mi < 4; mi++) {
        int r = m0 + wm + mi * 16 + qr;
#pragma unroll
        for (int ni = 0; ni < 8; ni++) {
            int cn = n0 + wn + ni * 8 + 2 * qc;
            if (cn < N) {
                if (OUTH) {
                    __half* C = (__half*)Cv;
                    *(__half2*)(C + (long long)r * ldc + cn) =
                        __floats2half2_rn(acc[mi][ni][0], acc[mi][ni][1]);
                    *(__half2*)(C + (long long)(r + 8) * ldc + cn) =
                        __floats2half2_rn(acc[mi][ni][2], acc[mi][ni][3]);
                } else {
                    float* C = (float*)Cv;
                    *(float2*)(C + (long long)r * ldc + cn) =
                        make_float2(acc[mi][ni][0], acc[mi][ni][1]);
                    *(float2*)(C + (long long)(r + 8) * ldc + cn) =
                        make_float2(acc[mi][ni][2], acc[mi][ni][3]);
                }
            }
        }
    }
}

// =====================================================================
// RoPE on q_pe inside merged g_qkv. grid = BS_, block = 512
// =====================================================================
__global__ void rope_q_k(__half* __restrict__ q,
                         const float* __restrict__ fcos, const float* __restrict__ fsin)
{
    int bs = blockIdx.x;
    int s  = bs & (S_ - 1);
    int t  = threadIdx.x;
    int h  = t >> 5, i = t & 31;
    float c  = fcos[s*(ROPE_/2) + i];
    float sn = fsin[s*(ROPE_/2) + i];
    __half2* p = (__half2*)(q + (long long)bs * QLD + h*QK_ + NOPE_ + 2*i);
    float2 v = __half22float2(*p);
    *p = __floats2half2_rn(v.x*c - v.y*sn, v.x*sn + v.y*c);
}

// =====================================================================
// RMSNorm(kv)*w and RoPE(k_pe) from merged g_qkv tail. grid = BS_, block = 128
// =====================================================================
__global__ void kv_prep_k(const __half* __restrict__ qkv, const float* __restrict__ w,
                          const float* __restrict__ fcos, const float* __restrict__ fsin,
                          __half* __restrict__ kvout, __half* __restrict__ kpeout)
{
    int bs = blockIdx.x;
    int s  = bs & (S_ - 1);
    const __half* row = qkv + (long long)bs * QLD + 3072;
    __shared__ float red[4];
    int t = threadIdx.x;
    float v[4]; float ss = 0.f;
#pragma unroll
    for (int i = 0; i < 4; i++) {
        v[i] = __half2float(row[t + i*128]);
        ss = fmaf(v[i], v[i], ss);
    }
#pragma unroll
    for (int o = 16; o > 0; o >>= 1) ss += __shfl_xor_sync(0xffffffffu, ss, o);
    if ((t & 31) == 0) red[t >> 5] = ss;
    __syncthreads();
    float tot = red[0] + red[1] + red[2] + red[3];
    float r = rsqrtf(tot * (1.0f/512.0f) + 1e-6f);
#pragma unroll
    for (int i = 0; i < 4; i++) {
        int c = t + i*128;
        kvout[(long long)bs*C_ + c] = __float2half_rn(v[i] * r * w[c]);
    }
    if (t < 32) {
        float c  = fcos[s*(ROPE_/2) + t];
        float sn = fsin[s*(ROPE_/2) + t];
        float2 pe = __half22float2(*(const __half2*)(row + C_ + 2*t));
        *(__half2*)(kpeout + (long long)bs*ROPE_ + 2*t) =
            __floats2half2_rn(pe.x*c - pe.y*sn, pe.x*sn + pe.y*c);
    }
}

// =====================================================================
// fp16 flash attention (m16n8k16), cp.async K prefetch + reg V prefetch.
// CTA: 128 q-rows, 8 warps x 16 rows, K/V tiles of 64. ~111KB smem.
// =====================================================================
#define FM 128
#define FN 64
#define SK_OFF  (128*400)            // sQ: 128 x 400B
#define SV_OFF  (SK_OFF + 64*400)    // sK: 64 x 400B
#define SP_OFF  (SV_OFF + 128*144)   // sVt: 128 x 144B
#define FLASH_SMEM (SP_OFF + 128*144)

__global__ __launch_bounds__(256, 1) void flash_h(
    const __half* __restrict__ q,    // merged g_qkv, row stride QLD
    const __half* __restrict__ knv,  // (H, bs, 256) fp16
    const __half* __restrict__ kpe,  // (bs, 64) fp16
    __half* __restrict__ out)        // (bs, H*128) fp16
{
    extern __shared__ __align__(128) char sm[];
    const unsigned* sQ = (const unsigned*)(sm);
    const unsigned* sK = (const unsigned*)(sm + SK_OFF);
    unsigned* sV = (unsigned*)(sm + SV_OFF);
    unsigned* sP = (unsigned*)(sm + SP_OFF);
    const uint32_t skb = su32(sm) + SK_OFF;

    int bx = blockIdx.x;
    int nb = gridDim.x;
    int sblk = (bx & 1) ? (nb - 1 - (bx >> 1)) : (bx >> 1);
    const int s0 = sblk * FM;
    const int h  = blockIdx.y;
    const int b  = blockIdx.z;
    const int tid = threadIdx.x;
    const int lane = tid & 31;
    const int warp = tid >> 5;
    const int rb = warp * 16;
    const int qr = lane >> 2;
    const int qc = lane & 3;
    const int g0 = s0 + rb + qr;
    const int g1 = g0 + 8;

    const __half* knh = knv + (long long)h * BS_ * 256;
    const float SC = 0.07216878364870322f;  // 1/sqrt(192)

    auto loadK = [&](int t0) {
#pragma unroll
        for (int i = 0; i < 6; i++) {
            int id = tid + i * 256;
            int r = id / 24, c = id % 24;
            long long trow = (long long)(b*S_ + t0 + r);
            const __half* src = (c < 16) ? (knh + trow*256 + c*8)
                                         : (kpe + trow*(long long)ROPE_ + (c-16)*8);
            uint32_t dst = skb + (uint32_t)(r*400 + c*16);
            asm volatile("cp.async.cg.shared.global [%0], [%1], 16;"
                         :: "r"(dst), "l"(src));
        }
        asm volatile("cp.async.commit_group;" ::: "memory");
    };

    const int tp = tid & 31;     // t-pair index
    const int dg = tid >> 5;     // d-group (16 d's)
    union HU { uint4 u[2]; __half x[16]; };
    HU vlo, vhi;
    auto ldV = [&](int t0) {
        const __half* base = knh + (long long)(b*S_ + t0 + 2*tp) * 256 + 128 + dg*16;
        vlo.u[0] = *(const uint4*)(base);
        vlo.u[1] = *(const uint4*)(base + 8);
        vhi.u[0] = *(const uint4*)(base + 256);
        vhi.u[1] = *(const uint4*)(base + 264);
    };
    auto stV = [&]() {
#pragma unroll
        for (int d = 0; d < 16; d++)
            sV[(dg*16 + d)*36 + tp] = packhh(vlo.x[d], vhi.x[d]);
    };

    // Q tile (raw uint4 copy)
#pragma unroll
    for (int i = 0; i < 12; i++) {
        int id = tid + i * 256;
        int r = id / 24, c = id % 24;
        *(uint4*)(sm + r*400 + c*16) =
            *(const uint4*)(q + (long long)(b*S_ + s0 + r) * QLD + h*QK_ + c*8);
    }

    float mr0 = -INFINITY, mr1 = -INFINITY, l0 = 0.f, l1 = 0.f;
    float o[16][4];
#pragma unroll
    for (int ni = 0; ni < 16; ni++)
#pragma unroll
        for (int j = 0; j < 4; j++) o[ni][j] = 0.f;

    loadK(0);
    ldV(0);
    asm volatile("cp.async.wait_group 0;" ::: "memory");
    stV();
    __syncthreads();

    const int tlast = s0 + (FM - FN);
    for (int t0 = 0; t0 <= tlast; t0 += FN) {
        const bool domask = (t0 + FN - 1 > s0);
        const bool nxt = (t0 + FN <= tlast);

        // ---- QK (192 = 12 x k16) ----
        float sc[8][4];
#pragma unroll
        for (int ni = 0; ni < 8; ni++)
#pragma unroll
            for (int j = 0; j < 4; j++) sc[ni][j] = 0.f;

#pragma unroll
        for (int kb = 0; kb < 12; kb++) {
            const int kw = kb * 8 + qc;
            unsigned a0 = sQ[(rb+qr)*100 + kw];
            unsigned a1 = sQ[(rb+qr+8)*100 + kw];
            unsigned a2 = sQ[(rb+qr)*100 + kw + 4];
            unsigned a3 = sQ[(rb+qr+8)*100 + kw + 4];
#pragma unroll
            for (int ni = 0; ni < 8; ni++) {
                unsigned b0 = sK[(8*ni+qr)*100 + kw];
                unsigned b1 = sK[(8*ni+qr)*100 + kw + 4];
                mma16(sc[ni], a0, a1, a2, a3, b0, b1);
            }
        }
        __syncthreads();              // done reading sK
        if (nxt) loadK(t0 + FN);      // overlaps softmax + PV

        // ---- softmax (fp32) ----
        float mx0 = -INFINITY, mx1 = -INFINITY;
#pragma unroll
        for (int ni = 0; ni < 8; ni++) {
            float v0 = sc[ni][0]*SC, v1 = sc[ni][1]*SC;
            float v2 = sc[ni][2]*SC, v3 = sc[ni][3]*SC;
            if (domask) {
                int cc = t0 + 8*ni + 2*qc;
                if (cc     > g0) v0 = -1e30f;
                if (cc + 1 > g0) v1 = -1e30f;
                if (cc     > g1) v2 = -1e30f;
                if (cc + 1 > g1) v3 = -1e30f;
            }
            sc[ni][0]=v0; sc[ni][1]=v1; sc[ni][2]=v2; sc[ni][3]=v3;
            mx0 = fmaxf(mx0, fmaxf(v0, v1));
            mx1 = fmaxf(mx1, fmaxf(v2, v3));
        }
        mx0 = fmaxf(mx0, __shfl_xor_sync(0xffffffffu, mx0, 1));
        mx0 = fmaxf(mx0, __shfl_xor_sync(0xffffffffu, mx0, 2));
        mx1 = fmaxf(mx1, __shfl_xor_sync(0xffffffffu, mx1, 1));
        mx1 = fmaxf(mx1, __shfl_xor_sync(0xffffffffu, mx1, 2));

        float mn0 = fmaxf(mr0, mx0), mn1 = fmaxf(mr1, mx1);
        float al0 = __expf(mr0 - mn0), al1 = __expf(mr1 - mn1);

        float s0s = 0.f, s1s = 0.f;
#pragma unroll
        for (int ni = 0; ni < 8; ni++) {
            float p0 = __expf(sc[ni][0] - mn0), p1 = __expf(sc[ni][1] - mn0);
            float p2 = __expf(sc[ni][2] - mn1), p3 = __expf(sc[ni][3] - mn1);
            s0s += p0 + p1; s1s += p2 + p3;
            sP[(rb+qr)*36   + 4*ni + qc] = packh2(p0, p1);
            sP[(rb+qr+8)*36 + 4*ni + qc] = packh2(p2, p3);
        }
        s0s += __shfl_xor_sync(0xffffffffu, s0s, 1);
        s0s += __shfl_xor_sync(0xffffffffu, s0s, 2);
        s1s += __shfl_xor_sync(0xffffffffu, s1s, 1);
        s1s += __shfl_xor_sync(0xffffffffu, s1s, 2);
        l0 = l0 * al0 + s0s;
        l1 = l1 * al1 + s1s;
        mr0 = mn0; mr1 = mn1;

#pragma unroll
        for (int ni = 0; ni < 16; ni++) {
            o[ni][0] *= al0; o[ni][1] *= al0;
            o[ni][2] *= al1; o[ni][3] *= al1;
        }
        __syncwarp();

        if (nxt) ldV(t0 + FN);        // LDG flight overlaps PV

        // ---- PV (64 = 4 x k16) ----
#pragma unroll
        for (int kb = 0; kb < 4; kb++) {
            const int kw = kb * 8 + qc;
            unsigned a0 = sP[(rb+qr)*36 + kw];
            unsigned a1 = sP[(rb+qr+8)*36 + kw];
            unsigned a2 = sP[(rb+qr)*36 + kw + 4];
            unsigned a3 = sP[(rb+qr+8)*36 + kw + 4];
#pragma unroll
            for (int ni = 0; ni < 16; ni++) {
                unsigned b0 = sV[(8*ni+qr)*36 + kw];
                unsigned b1 = sV[(8*ni+qr)*36 + kw + 4];
                mma16(o[ni], a0, a1, a2, a3, b0, b1);
            }
        }
        __syncthreads();              // done reading sV/sP
        if (nxt) {
            stV();
            asm volatile("cp.async.wait_group 0;" ::: "memory");
            __syncthreads();
        }
    }

    float i0 = 1.0f / l0, i1 = 1.0f / l1;
    __half* out0 = out + (long long)(b*S_ + s0 + rb + qr) * (H_*V_) + h*V_;
    __half* out1 = out0 + 8LL * (H_*V_);
#pragma unroll
    for (int ni = 0; ni < 16; ni++) {
        int cn = 8*ni + 2*qc;
        *(__half2*)(out0 + cn) = __floats2half2_rn(o[ni][0]*i0, o[ni][1]*i0);
        *(__half2*)(out1 + cn) = __floats2half2_rn(o[ni][2]*i1, o[ni][3]*i1);
    }
}

// =====================================================================
// Host launch
// =====================================================================
static void* sym_addr(const void* sym) {
    void* p = nullptr;
    cudaGetSymbolAddress(&p, sym);
    return p;
}

extern "C" void kernel_launch(void* const* d_in, const int* in_sizes, int n_in,
                              void* d_out, int out_size)
{
    const float* x     = (const float*)d_in[0];
    const float* wq    = (const float*)d_in[1];
    const float* wkv_a = (const float*)d_in[2];
    const float* wkv_b = (const float*)d_in[3];
    const float* wo    = (const float*)d_in[4];
    const float* kvw   = (const float*)d_in[5];
    const float* fcos  = (const float*)d_in[6];
    const float* fsin  = (const float*)d_in[7];
    float* out = (float*)d_out;

    __half* qkvb = (__half*)sym_addr(g_qkv);
    __half* kvb  = (__half*)sym_addr(g_kv);
    __half* kpeb = (__half*)sym_addr(g_kpe);
    __half* knvb = (__half*)sym_addr(g_knv);
    __half* o2b  = (__half*)sym_addr(g_o2);
    __half* xh   = (__half*)sym_addr(g_xh);
    __half* wqa  = (__half*)sym_addr(g_wqa);
    __half* wbh  = (__half*)sym_addr(g_wbh);
    __half* woh  = (__half*)sym_addr(g_woh);

    static bool attr_done = false;
    if (!attr_done) {
        cudaFuncSetAttribute(gemm_h<1>, cudaFuncAttributeMaxDynamicSharedMemorySize, GEMM_SMEM);
        cudaFuncSetAttribute(gemm_h<0>, cudaFuncAttributeMaxDynamicSharedMemorySize, GEMM_SMEM);
        cudaFuncSetAttribute(flash_h,   cudaFuncAttributeMaxDynamicSharedMemorySize, FLASH_SMEM);
        attr_done = true;
    }

    // 0. convert inputs to fp16
    {
        auto rr = [&](const float* s, __half* d, long long n) {
            int n4 = (int)(n / 4);
            hround_k<<<(n4 + 255) / 256, 256>>>((const float4*)s, (uint2*)d, n4);
        };
        rr(x,     xh,  (long long)BS_*DIM_);
        rr(wq,    wqa, (long long)(H_*QK_)*DIM_);
        rr(wkv_a, wqa + (long long)(H_*QK_)*DIM_, (long long)(C_+ROPE_)*DIM_);
        rr(wkv_b, wbh, (long long)H_*256*C_);
        rr(wo,    woh, (long long)DIM_*(H_*V_));
    }

    dim3 blk(128);

    // 1. merged projections: qkv = xh @ wqa^T   (4096 x 3648, K=2048)
    gemm_h<1><<<dim3(29, 32, 1), blk, GEMM_SMEM>>>(
        xh, wqa, qkvb, BS_, QLD, DIM_, DIM_, DIM_, QLD, 0, 0, 0);

    // 2. rope(q_pe)
    rope_q_k<<<BS_, H_*32>>>(qkvb, fcos, fsin);

    // 3. rmsnorm(kv), rope(k_pe)
    kv_prep_k<<<BS_, 128>>>(qkvb, kvw, fcos, fsin, kvb, kpeb);

    // 4. knv[h] = kv @ wbh[h]^T   (N=256 per head)
    gemm_h<1><<<dim3(2, 32, H_), blk, GEMM_SMEM>>>(
        kvb, wbh, knvb,
        BS_, 256, C_, C_, C_, 256,
        0, (long long)256*C_, (long long)BS_*256);

    // 5. flash attention -> g_o2
    flash_h<<<dim3(S_/FM, H_, B_), dim3(256), FLASH_SMEM>>>(qkvb, knvb, kpeb, o2b);

    // 6. out = o2 @ woh^T   (fp32 out)
    gemm_h<0><<<dim3(16, 32, 1), blk, GEMM_SMEM>>>(
        o2b, woh, out, BS_, DIM_, H_*V_, H_*V_, H_*V_, DIM_, 0, 0, 0);

    (void)in_sizes; (void)n_in; (void)out_size;
}

// round 11
// speedup vs baseline: 16.5272x; 1.0868x over previous
#include <cuda_runtime.h>
#include <cuda_fp16.h>
#include <math.h>
#include <stdint.h>

// ---------------- problem constants ----------------
#define B_    2
#define S_    2048
#define DIM_  2048
#define H_    16
#define C_    512
#define NOPE_ 128
#define ROPE_ 64
#define V_    128
#define QK_   192
#define BS_   (B_*S_)
#define QLD   3648          // merged [q(3072) | kvpe(576)] row stride

// ---------------- scratch (fp16 pipeline) ----------------
__device__ __half g_qkv[(long long)BS_*QLD];
__device__ __half g_kv [(long long)BS_*C_];
__device__ __half g_kpe[(long long)BS_*ROPE_];
__device__ __half g_knv[(long long)H_*BS_*256];   // per-head [k_nope(128) | v(128)]
__device__ __half g_o2 [(long long)BS_*H_*V_];
__device__ __half g_xh [(long long)BS_*DIM_];
__device__ __half g_wqa[(long long)QLD*DIM_];     // [wq(3072) ; wkv_a(576)] rows
__device__ __half g_wbh[(long long)H_*256*C_];
__device__ __half g_woh[(long long)DIM_*(H_*V_)];

// ---------------- helpers ----------------
__device__ __forceinline__ void mma16(float* c, unsigned a0, unsigned a1, unsigned a2,
                                      unsigned a3, unsigned b0, unsigned b1) {
    asm volatile(
        "mma.sync.aligned.m16n8k16.row.col.f32.f16.f16.f32 "
        "{%0,%1,%2,%3},{%4,%5,%6,%7},{%8,%9},{%0,%1,%2,%3};"
        : "+f"(c[0]), "+f"(c[1]), "+f"(c[2]), "+f"(c[3])
        : "r"(a0), "r"(a1), "r"(a2), "r"(a3), "r"(b0), "r"(b1));
}
__device__ __forceinline__ void ldsm4(unsigned &r0, unsigned &r1, unsigned &r2,
                                      unsigned &r3, uint32_t addr) {
    asm volatile("ldmatrix.sync.aligned.m8n8.x4.shared.b16 {%0,%1,%2,%3}, [%4];"
                 : "=r"(r0), "=r"(r1), "=r"(r2), "=r"(r3) : "r"(addr));
}
__device__ __forceinline__ uint32_t su32(const void* p) {
    uint32_t a;
    asm("{ .reg .u64 t; cvta.to.shared.u64 t, %1; cvt.u32.u64 %0, t; }"
        : "=r"(a) : "l"(p));
    return a;
}
__device__ __forceinline__ unsigned packh2(float a, float b) {
    __half2 h = __floats2half2_rn(a, b);
    return *(unsigned*)&h;
}
__device__ __forceinline__ unsigned packhh(__half a, __half b) {
    __half2 h = __halves2half2(a, b);
    return *(unsigned*)&h;
}

// =====================================================================
// fp32 -> fp16 convert
// =====================================================================
__global__ void hround_k(const float4* __restrict__ src, uint2* __restrict__ dst,
                         int n4)
{
    int i = blockIdx.x * blockDim.x + threadIdx.x;
    if (i < n4) {
        float4 v = src[i];
        uint2 u;
        u.x = packh2(v.x, v.y);
        u.y = packh2(v.z, v.w);
        dst[i] = u;
    }
}

// =====================================================================
// fp16 NT GEMM, m16n8k16 + 3-stage cp.async pipeline + ldmatrix frags.
// C = A @ B^T. A: MxK (lda), B: NxK (ldb). CTA 128x128, k-stage 64.
// smem rows 144B (word stride 36 == 4 mod 32) -> conflict-free LDSM.
// =====================================================================
#define HSTG 3
#define HTILE 36864               // per stage: A 18432 + B 18432
#define GEMM_SMEM (HSTG*HTILE)    // 110592

template<int OUTH>
__global__ __launch_bounds__(128) void gemm_h(
    const __half* __restrict__ A, const __half* __restrict__ Bm, void* Cv,
    int M, int N, int K, int lda, int ldb, int ldc,
    long long sAz, long long sBz, long long sCz)
{
    A  += (long long)blockIdx.z * sAz;
    Bm += (long long)blockIdx.z * sBz;
    if (OUTH) Cv = (void*)((__half*)Cv + (long long)blockIdx.z * sCz);
    else      Cv = (void*)((float*)Cv  + (long long)blockIdx.z * sCz);

    extern __shared__ __align__(128) char smem[];
    const uint32_t sbase = su32(smem);

    const int tid  = threadIdx.x;
    const int lane = tid & 31;
    const int warp = tid >> 5;
    const int m0 = blockIdx.y * 128;
    const int n0 = blockIdx.x * 128;
    const int wm = (warp >> 1) * 64;
    const int wn = (warp & 1) * 64;
    const int qr = lane >> 2;
    const int qc = lane & 3;

    // LDSM lane geometry
    const int l15 = lane & 15;           // A: row within 16
    const int ahl = (lane >> 4) << 3;    // A: k half (0/8)
    const int bg  = lane >> 3;           // B: group 0..3
    const int brw = ((bg >> 1) << 3) + (lane & 7);  // B: row within pair-tile (0..15)
    const int bkl = (bg & 1) << 3;       // B: k half

    float acc[4][8][4];
#pragma unroll
    for (int mi = 0; mi < 4; mi++)
#pragma unroll
        for (int ni = 0; ni < 8; ni++)
#pragma unroll
            for (int j = 0; j < 4; j++) acc[mi][ni][j] = 0.f;

    const int crow = tid >> 3;      // 0..15
    const int cc   = tid & 7;       // chunk 0..7 (16B = 8 fp16)

    auto issue_stage = [&](int buf, int k0) {
        uint32_t abase = sbase + buf * HTILE;
        uint32_t bbase = abase + 18432;
#pragma unroll
        for (int i = 0; i < 8; i++) {
            int row = crow + i * 16;
            uint32_t dst = abase + row * 144 + cc * 16;
            const __half* src = A + (long long)(m0 + row) * lda + k0 + cc * 8;
            asm volatile("cp.async.cg.shared.global [%0], [%1], 16;"
                         :: "r"(dst), "l"(src));
        }
#pragma unroll
        for (int i = 0; i < 8; i++) {
            int row = crow + i * 16;
            uint32_t dst = bbase + row * 144 + cc * 16;
            const __half* src = Bm + (long long)(n0 + row) * ldb + k0 + cc * 8;
            int sz = (n0 + row < N) ? 16 : 0;
            asm volatile("cp.async.cg.shared.global [%0], [%1], 16, %2;"
                         :: "r"(dst), "l"(src), "r"(sz));
        }
        asm volatile("cp.async.commit_group;" ::: "memory");
    };

    const int S = K >> 6;
    issue_stage(0, 0);
    if (S > 1) issue_stage(1, 64);

    for (int s = 0; s < S; s++) {
        if (s + 1 < S) asm volatile("cp.async.wait_group 1;" ::: "memory");
        else           asm volatile("cp.async.wait_group 0;" ::: "memory");
        __syncthreads();
        if (s + 2 < S) issue_stage((s + 2) % HSTG, (s + 2) * 64);

        const uint32_t abase = sbase + (s % HSTG) * HTILE;
        const uint32_t bbase = abase + 18432;

#pragma unroll
        for (int kb = 0; kb < 4; kb++) {
            unsigned a[4][4], b[8][2];
#pragma unroll
            for (int mi = 0; mi < 4; mi++) {
                uint32_t ad = abase + (wm + mi*16 + l15) * 144 + (kb*16 + ahl) * 2;
                ldsm4(a[mi][0], a[mi][1], a[mi][2], a[mi][3], ad);
            }
#pragma unroll
            for (int p = 0; p < 4; p++) {
                uint32_t bd = bbase + (wn + p*16 + brw) * 144 + (kb*16 + bkl) * 2;
                ldsm4(b[2*p][0], b[2*p][1], b[2*p+1][0], b[2*p+1][1], bd);
            }
#pragma unroll
            for (int mi = 0; mi < 4; mi++)
#pragma unroll
                for (int ni = 0; ni < 8; ni++)
                    mma16(acc[mi][ni], a[mi][0], a[mi][1], a[mi][2], a[mi][3],
                          b[ni][0], b[ni][1]);
        }
    }

#pragma unroll
    for (int mi = 0; mi < 4; mi++) {
        int r = m0 + wm + mi * 16 + qr;
#pragma unroll
        for (int ni = 0; ni < 8; ni++) {
            int cn = n0 + wn + ni * 8 + 2 * qc;
            if (cn < N) {
                if (OUTH) {
                    __half* C = (__half*)Cv;
                    *(__half2*)(C + (long long)r * ldc + cn) =
                        __floats2half2_rn(acc[mi][ni][0], acc[mi][ni][1]);
                    *(__half2*)(C + (long long)(r + 8) * ldc + cn) =
                        __floats2half2_rn(acc[mi][ni][2], acc[mi][ni][3]);
                } else {
                    float* C = (float*)Cv;
                    *(float2*)(C + (long long)r * ldc + cn) =
                        make_float2(acc[mi][ni][0], acc[mi][ni][1]);
                    *(float2*)(C + (long long)(r + 8) * ldc + cn) =
                        make_float2(acc[mi][ni][2], acc[mi][ni][3]);
                }
            }
        }
    }
}

// =====================================================================
// RoPE on q_pe inside merged g_qkv. grid = BS_, block = 512
// =====================================================================
__global__ void rope_q_k(__half* __restrict__ q,
                         const float* __restrict__ fcos, const float* __restrict__ fsin)
{
    int bs = blockIdx.x;
    int s  = bs & (S_ - 1);
    int t  = threadIdx.x;
    int h  = t >> 5, i = t & 31;
    float c  = fcos[s*(ROPE_/2) + i];
    float sn = fsin[s*(ROPE_/2) + i];
    __half2* p = (__half2*)(q + (long long)bs * QLD + h*QK_ + NOPE_ + 2*i);
    float2 v = __half22float2(*p);
    *p = __floats2half2_rn(v.x*c - v.y*sn, v.x*sn + v.y*c);
}

// =====================================================================
// RMSNorm(kv)*w and RoPE(k_pe) from merged g_qkv tail. grid = BS_, block = 128
// =====================================================================
__global__ void kv_prep_k(const __half* __restrict__ qkv, const float* __restrict__ w,
                          const float* __restrict__ fcos, const float* __restrict__ fsin,
                          __half* __restrict__ kvout, __half* __restrict__ kpeout)
{
    int bs = blockIdx.x;
    int s  = bs & (S_ - 1);
    const __half* row = qkv + (long long)bs * QLD + 3072;
    __shared__ float red[4];
    int t = threadIdx.x;
    float v[4]; float ss = 0.f;
#pragma unroll
    for (int i = 0; i < 4; i++) {
        v[i] = __half2float(row[t + i*128]);
        ss = fmaf(v[i], v[i], ss);
    }
#pragma unroll
    for (int o = 16; o > 0; o >>= 1) ss += __shfl_xor_sync(0xffffffffu, ss, o);
    if ((t & 31) == 0) red[t >> 5] = ss;
    __syncthreads();
    float tot = red[0] + red[1] + red[2] + red[3];
    float r = rsqrtf(tot * (1.0f/512.0f) + 1e-6f);
#pragma unroll
    for (int i = 0; i < 4; i++) {
        int c = t + i*128;
        kvout[(long long)bs*C_ + c] = __float2half_rn(v[i] * r * w[c]);
    }
    if (t < 32) {
        float c  = fcos[s*(ROPE_/2) + t];
        float sn = fsin[s*(ROPE_/2) + t];
        float2 pe = __half22float2(*(const __half2*)(row + C_ + 2*t));
        *(__half2*)(kpeout + (long long)bs*ROPE_ + 2*t) =
            __floats2half2_rn(pe.x*c - pe.y*sn, pe.x*sn + pe.y*c);
    }
}

// =====================================================================
// fp16 flash attention (m16n8k16 + ldmatrix), cp.async K prefetch +
// reg V prefetch. CTA: 128 q-rows, 8 warps x 16 rows, K/V tiles of 64.
// =====================================================================
#define FM 128
#define FN 64
#define SK_OFF  (128*400)            // sQ: 128 x 400B
#define SV_OFF  (SK_OFF + 64*400)    // sK: 64 x 400B
#define SP_OFF  (SV_OFF + 128*144)   // sVt: 128 x 144B
#define FLASH_SMEM (SP_OFF + 128*144)

__global__ __launch_bounds__(256, 1) void flash_h(
    const __half* __restrict__ q,    // merged g_qkv, row stride QLD
    const __half* __restrict__ knv,  // (H, bs, 256) fp16
    const __half* __restrict__ kpe,  // (bs, 64) fp16
    __half* __restrict__ out)        // (bs, H*128) fp16
{
    extern __shared__ __align__(128) char sm[];
    unsigned* sV = (unsigned*)(sm + SV_OFF);
    unsigned* sP = (unsigned*)(sm + SP_OFF);
    const uint32_t sqb = su32(sm);
    const uint32_t skb = sqb + SK_OFF;
    const uint32_t svb = sqb + SV_OFF;
    const uint32_t spb = sqb + SP_OFF;

    int bx = blockIdx.x;
    int nb = gridDim.x;
    int sblk = (bx & 1) ? (nb - 1 - (bx >> 1)) : (bx >> 1);
    const int s0 = sblk * FM;
    const int h  = blockIdx.y;
    const int b  = blockIdx.z;
    const int tid = threadIdx.x;
    const int lane = tid & 31;
    const int warp = tid >> 5;
    const int rb = warp * 16;
    const int qr = lane >> 2;
    const int qc = lane & 3;
    const int g0 = s0 + rb + qr;
    const int g1 = g0 + 8;

    // LDSM lane geometry
    const int l15 = lane & 15;
    const int ahl = (lane >> 4) << 3;
    const int bg  = lane >> 3;
    const int brw = ((bg >> 1) << 3) + (lane & 7);
    const int bkl = (bg & 1) << 3;

    const __half* knh = knv + (long long)h * BS_ * 256;
    const float SC = 0.07216878364870322f;  // 1/sqrt(192)

    auto loadK = [&](int t0) {
#pragma unroll
        for (int i = 0; i < 6; i++) {
            int id = tid + i * 256;
            int r = id / 24, c = id % 24;
            long long trow = (long long)(b*S_ + t0 + r);
            const __half* src = (c < 16) ? (knh + trow*256 + c*8)
                                         : (kpe + trow*(long long)ROPE_ + (c-16)*8);
            uint32_t dst = skb + (uint32_t)(r*400 + c*16);
            asm volatile("cp.async.cg.shared.global [%0], [%1], 16;"
                         :: "r"(dst), "l"(src));
        }
        asm volatile("cp.async.commit_group;" ::: "memory");
    };

    const int tp = tid & 31;     // t-pair index
    const int dg = tid >> 5;     // d-group (16 d's)
    union HU { uint4 u[2]; __half x[16]; };
    HU vlo, vhi;
    auto ldV = [&](int t0) {
        const __half* base = knh + (long long)(b*S_ + t0 + 2*tp) * 256 + 128 + dg*16;
        vlo.u[0] = *(const uint4*)(base);
        vlo.u[1] = *(const uint4*)(base + 8);
        vhi.u[0] = *(const uint4*)(base + 256);
        vhi.u[1] = *(const uint4*)(base + 264);
    };
    auto stV = [&]() {
#pragma unroll
        for (int d = 0; d < 16; d++)
            sV[(dg*16 + d)*36 + tp] = packhh(vlo.x[d], vhi.x[d]);
    };

    // Q tile (raw uint4 copy)
#pragma unroll
    for (int i = 0; i < 12; i++) {
        int id = tid + i * 256;
        int r = id / 24, c = id % 24;
        *(uint4*)(sm + r*400 + c*16) =
            *(const uint4*)(q + (long long)(b*S_ + s0 + r) * QLD + h*QK_ + c*8);
    }

    float mr0 = -INFINITY, mr1 = -INFINITY, l0 = 0.f, l1 = 0.f;
    float o[16][4];
#pragma unroll
    for (int ni = 0; ni < 16; ni++)
#pragma unroll
        for (int j = 0; j < 4; j++) o[ni][j] = 0.f;

    loadK(0);
    ldV(0);
    asm volatile("cp.async.wait_group 0;" ::: "memory");
    stV();
    __syncthreads();

    const int tlast = s0 + (FM - FN);
    for (int t0 = 0; t0 <= tlast; t0 += FN) {
        const bool domask = (t0 + FN - 1 > s0);
        const bool nxt = (t0 + FN <= tlast);

        // ---- QK (192 = 12 x k16) ----
        float sc[8][4];
#pragma unroll
        for (int ni = 0; ni < 8; ni++)
#pragma unroll
            for (int j = 0; j < 4; j++) sc[ni][j] = 0.f;

#pragma unroll
        for (int kb = 0; kb < 12; kb++) {
            unsigned a0, a1, a2, a3;
            ldsm4(a0, a1, a2, a3,
                  sqb + (rb + l15) * 400 + (kb*16 + ahl) * 2);
            unsigned kb_[8][2];
#pragma unroll
            for (int p = 0; p < 4; p++) {
                ldsm4(kb_[2*p][0], kb_[2*p][1], kb_[2*p+1][0], kb_[2*p+1][1],
                      skb + (p*16 + brw) * 400 + (kb*16 + bkl) * 2);
            }
#pragma unroll
            for (int ni = 0; ni < 8; ni++)
                mma16(sc[ni], a0, a1, a2, a3, kb_[ni][0], kb_[ni][1]);
        }
        __syncthreads();              // done reading sK
        if (nxt) loadK(t0 + FN);      // overlaps softmax + PV

        // ---- softmax (fp32) ----
        float mx0 = -INFINITY, mx1 = -INFINITY;
#pragma unroll
        for (int ni = 0; ni < 8; ni++) {
            float v0 = sc[ni][0]*SC, v1 = sc[ni][1]*SC;
            float v2 = sc[ni][2]*SC, v3 = sc[ni][3]*SC;
            if (domask) {
                int cc = t0 + 8*ni + 2*qc;
                if (cc     > g0) v0 = -1e30f;
                if (cc + 1 > g0) v1 = -1e30f;
                if (cc     > g1) v2 = -1e30f;
                if (cc + 1 > g1) v3 = -1e30f;
            }
            sc[ni][0]=v0; sc[ni][1]=v1; sc[ni][2]=v2; sc[ni][3]=v3;
            mx0 = fmaxf(mx0, fmaxf(v0, v1));
            mx1 = fmaxf(mx1, fmaxf(v2, v3));
        }
        mx0 = fmaxf(mx0, __shfl_xor_sync(0xffffffffu, mx0, 1));
        mx0 = fmaxf(mx0, __shfl_xor_sync(0xffffffffu, mx0, 2));
        mx1 = fmaxf(mx1, __shfl_xor_sync(0xffffffffu, mx1, 1));
        mx1 = fmaxf(mx1, __shfl_xor_sync(0xffffffffu, mx1, 2));

        float mn0 = fmaxf(mr0, mx0), mn1 = fmaxf(mr1, mx1);
        float al0 = __expf(mr0 - mn0), al1 = __expf(mr1 - mn1);

        float s0s = 0.f, s1s = 0.f;
#pragma unroll
        for (int ni = 0; ni < 8; ni++) {
            float p0 = __expf(sc[ni][0] - mn0), p1 = __expf(sc[ni][1] - mn0);
            float p2 = __expf(sc[ni][2] - mn1), p3 = __expf(sc[ni][3] - mn1);
            s0s += p0 + p1; s1s += p2 + p3;
            sP[(rb+qr)*36   + 4*ni + qc] = packh2(p0, p1);
            sP[(rb+qr+8)*36 + 4*ni + qc] = packh2(p2, p3);
        }
        s0s += __shfl_xor_sync(0xffffffffu, s0s, 1);
        s0s += __shfl_xor_sync(0xffffffffu, s0s, 2);
        s1s += __shfl_xor_sync(0xffffffffu, s1s, 1);
        s1s += __shfl_xor_sync(0xffffffffu, s1s, 2);
        l0 = l0 * al0 + s0s;
        l1 = l1 * al1 + s1s;
        mr0 = mn0; mr1 = mn1;

#pragma unroll
        for (int ni = 0; ni < 16; ni++) {
            o[ni][0] *= al0; o[ni][1] *= al0;
            o[ni][2] *= al1; o[ni][3] *= al1;
        }
        __syncwarp();

        if (nxt) ldV(t0 + FN);        // LDG flight overlaps PV

        // ---- PV (64 = 4 x k16) ----
#pragma unroll
        for (int kb = 0; kb < 4; kb++) {
            unsigned a0, a1, a2, a3;
            ldsm4(a0, a1, a2, a3,
                  spb + (rb + l15) * 144 + (kb*16 + ahl) * 2);
            unsigned vb_[16][2];
#pragma unroll
            for (int p = 0; p < 8; p++) {
                ldsm4(vb_[2*p][0], vb_[2*p][1], vb_[2*p+1][0], vb_[2*p+1][1],
                      svb + (p*16 + brw) * 144 + (kb*16 + bkl) * 2);
            }
#pragma unroll
            for (int ni = 0; ni < 16; ni++)
                mma16(o[ni], a0, a1, a2, a3, vb_[ni][0], vb_[ni][1]);
        }
        __syncthreads();              // done reading sV/sP
        if (nxt) {
            stV();
            asm volatile("cp.async.wait_group 0;" ::: "memory");
            __syncthreads();
        }
    }

    float i0 = 1.0f / l0, i1 = 1.0f / l1;
    __half* out0 = out + (long long)(b*S_ + s0 + rb + qr) * (H_*V_) + h*V_;
    __half* out1 = out0 + 8LL * (H_*V_);
#pragma unroll
    for (int ni = 0; ni < 16; ni++) {
        int cn = 8*ni + 2*qc;
        *(__half2*)(out0 + cn) = __floats2half2_rn(o[ni][0]*i0, o[ni][1]*i0);
        *(__half2*)(out1 + cn) = __floats2half2_rn(o[ni][2]*i1, o[ni][3]*i1);
    }
}

// =====================================================================
// Host launch
// =====================================================================
static void* sym_addr(const void* sym) {
    void* p = nullptr;
    cudaGetSymbolAddress(&p, sym);
    return p;
}

extern "C" void kernel_launch(void* const* d_in, const int* in_sizes, int n_in,
                              void* d_out, int out_size)
{
    const float* x     = (const float*)d_in[0];
    const float* wq    = (const float*)d_in[1];
    const float* wkv_a = (const float*)d_in[2];
    const float* wkv_b = (const float*)d_in[3];
    const float* wo    = (const float*)d_in[4];
    const float* kvw   = (const float*)d_in[5];
    const float* fcos  = (const float*)d_in[6];
    const float* fsin  = (const float*)d_in[7];
    float* out = (float*)d_out;

    __half* qkvb = (__half*)sym_addr(g_qkv);
    __half* kvb  = (__half*)sym_addr(g_kv);
    __half* kpeb = (__half*)sym_addr(g_kpe);
    __half* knvb = (__half*)sym_addr(g_knv);
    __half* o2b  = (__half*)sym_addr(g_o2);
    __half* xh   = (__half*)sym_addr(g_xh);
    __half* wqa  = (__half*)sym_addr(g_wqa);
    __half* wbh  = (__half*)sym_addr(g_wbh);
    __half* woh  = (__half*)sym_addr(g_woh);

    static bool attr_done = false;
    if (!attr_done) {
        cudaFuncSetAttribute(gemm_h<1>, cudaFuncAttributeMaxDynamicSharedMemorySize, GEMM_SMEM);
        cudaFuncSetAttribute(gemm_h<0>, cudaFuncAttributeMaxDynamicSharedMemorySize, GEMM_SMEM);
        cudaFuncSetAttribute(flash_h,   cudaFuncAttributeMaxDynamicSharedMemorySize, FLASH_SMEM);
        attr_done = true;
    }

    // 0. convert inputs to fp16
    {
        auto rr = [&](const float* s, __half* d, long long n) {
            int n4 = (int)(n / 4);
            hround_k<<<(n4 + 255) / 256, 256>>>((const float4*)s, (uint2*)d, n4);
        };
        rr(x,     xh,  (long long)BS_*DIM_);
        rr(wq,    wqa, (long long)(H_*QK_)*DIM_);
        rr(wkv_a, wqa + (long long)(H_*QK_)*DIM_, (long long)(C_+ROPE_)*DIM_);
        rr(wkv_b, wbh, (long long)H_*256*C_);
        rr(wo,    woh, (long long)DIM_*(H_*V_));
    }

    dim3 blk(128);

    // 1. merged projections: qkv = xh @ wqa^T   (4096 x 3648, K=2048)
    gemm_h<1><<<dim3(29, 32, 1), blk, GEMM_SMEM>>>(
        xh, wqa, qkvb, BS_, QLD, DIM_, DIM_, DIM_, QLD, 0, 0, 0);

    // 2. rope(q_pe)
    rope_q_k<<<BS_, H_*32>>>(qkvb, fcos, fsin);

    // 3. rmsnorm(kv), rope(k_pe)
    kv_prep_k<<<BS_, 128>>>(qkvb, kvw, fcos, fsin, kvb, kpeb);

    // 4. knv[h] = kv @ wbh[h]^T   (N=256 per head)
    gemm_h<1><<<dim3(2, 32, H_), blk, GEMM_SMEM>>>(
        kvb, wbh, knvb,
        BS_, 256, C_, C_, C_, 256,
        0, (long long)256*C_, (long long)BS_*256);

    // 5. flash attention -> g_o2
    flash_h<<<dim3(S_/FM, H_, B_), dim3(256), FLASH_SMEM>>>(qkvb, knvb, kpeb, o2b);

    // 6. out = o2 @ woh^T   (fp32 out)
    gemm_h<0><<<dim3(16, 32, 1), blk, GEMM_SMEM>>>(
        o2b, woh, out, BS_, DIM_, H_*V_, H_*V_, H_*V_, DIM_, 0, 0, 0);

    (void)in_sizes; (void)n_in; (void)out_size;
}

// round 12
// speedup vs baseline: 17.1082x; 1.0352x over previous
#include <cuda_runtime.h>
#include <cuda_fp16.h>
#include <math.h>
#include <stdint.h>

// ---------------- problem constants ----------------
#define B_    2
#define S_    2048
#define DIM_  2048
#define H_    16
#define C_    512
#define NOPE_ 128
#define ROPE_ 64
#define V_    128
#define QK_   192
#define BS_   (B_*S_)
#define QLD   3648          // merged [q(3072) | kvpe(576)] row stride

// ---------------- scratch (fp16 pipeline) ----------------
__device__ __half g_qkv[(long long)BS_*QLD];
__device__ __half g_kv [(long long)BS_*C_];
__device__ __half g_kpe[(long long)BS_*ROPE_];
__device__ __half g_knv[(long long)H_*BS_*256];   // per-head [k_nope(128) | v(128)]
__device__ __half g_o2 [(long long)BS_*H_*V_];
__device__ __half g_xh [(long long)BS_*DIM_];
__device__ __half g_wqa[(long long)QLD*DIM_];     // [wq(3072) ; wkv_a(576)] rows
__device__ __half g_wbh[(long long)H_*256*C_];
__device__ __half g_woh[(long long)DIM_*(H_*V_)];

// ---------------- helpers ----------------
__device__ __forceinline__ void mma16(float* c, unsigned a0, unsigned a1, unsigned a2,
                                      unsigned a3, unsigned b0, unsigned b1) {
    asm volatile(
        "mma.sync.aligned.m16n8k16.row.col.f32.f16.f16.f32 "
        "{%0,%1,%2,%3},{%4,%5,%6,%7},{%8,%9},{%0,%1,%2,%3};"
        : "+f"(c[0]), "+f"(c[1]), "+f"(c[2]), "+f"(c[3])
        : "r"(a0), "r"(a1), "r"(a2), "r"(a3), "r"(b0), "r"(b1));
}
__device__ __forceinline__ void ldsm4(unsigned &r0, unsigned &r1, unsigned &r2,
                                      unsigned &r3, uint32_t addr) {
    asm volatile("ldmatrix.sync.aligned.m8n8.x4.shared.b16 {%0,%1,%2,%3}, [%4];"
                 : "=r"(r0), "=r"(r1), "=r"(r2), "=r"(r3) : "r"(addr));
}
__device__ __forceinline__ uint32_t su32(const void* p) {
    uint32_t a;
    asm("{ .reg .u64 t; cvta.to.shared.u64 t, %1; cvt.u32.u64 %0, t; }"
        : "=r"(a) : "l"(p));
    return a;
}
__device__ __forceinline__ unsigned packh2(float a, float b) {
    __half2 h = __floats2half2_rn(a, b);
    return *(unsigned*)&h;
}
__device__ __forceinline__ unsigned packhh(__half a, __half b) {
    __half2 h = __halves2half2(a, b);
    return *(unsigned*)&h;
}

// =====================================================================
// fp32 -> fp16 convert
// =====================================================================
__global__ void hround_k(const float4* __restrict__ src, uint2* __restrict__ dst,
                         int n4)
{
    int i = blockIdx.x * blockDim.x + threadIdx.x;
    if (i < n4) {
        float4 v = src[i];
        uint2 u;
        u.x = packh2(v.x, v.y);
        u.y = packh2(v.z, v.w);
        dst[i] = u;
    }
}

// =====================================================================
// fp16 NT GEMM, m16n8k16 + ldmatrix + 3-stage cp.async.
// 256 threads, 8 warps, warp tile 64x32 (acc 64 regs) -> 2 CTAs/SM.
// C = A @ B^T. A: MxK (lda), B: NxK (ldb). CTA 128x128, k-stage 64.
// smem rows 144B (word stride 36 == 4 mod 32) -> conflict-free LDSM.
// =====================================================================
#define HSTG 3
#define HTILE 36864               // per stage: A 18432 + B 18432
#define GEMM_SMEM (HSTG*HTILE)    // 110592

template<int OUTH>
__global__ __launch_bounds__(256, 2) void gemm_h(
    const __half* __restrict__ A, const __half* __restrict__ Bm, void* Cv,
    int M, int N, int K, int lda, int ldb, int ldc,
    long long sAz, long long sBz, long long sCz)
{
    A  += (long long)blockIdx.z * sAz;
    Bm += (long long)blockIdx.z * sBz;
    if (OUTH) Cv = (void*)((__half*)Cv + (long long)blockIdx.z * sCz);
    else      Cv = (void*)((float*)Cv  + (long long)blockIdx.z * sCz);

    extern __shared__ __align__(128) char smem[];
    const uint32_t sbase = su32(smem);

    const int tid  = threadIdx.x;
    const int lane = tid & 31;
    const int warp = tid >> 5;
    const int m0 = blockIdx.y * 128;
    const int n0 = blockIdx.x * 128;
    const int wm = (warp >> 2) * 64;     // 2 warp rows (M)
    const int wn = (warp & 3) * 32;      // 4 warp cols (N)
    const int qr = lane >> 2;
    const int qc = lane & 3;

    // LDSM lane geometry (proven mapping from R11)
    const int l15 = lane & 15;           // A: row within 16
    const int ahl = (lane >> 4) << 3;    // A: k half (0/8)
    const int bg  = lane >> 3;           // B: group 0..3
    const int brw = ((bg >> 1) << 3) + (lane & 7);  // B: row within pair-tile
    const int bkl = (bg & 1) << 3;       // B: k half

    float acc[4][4][4];
#pragma unroll
    for (int mi = 0; mi < 4; mi++)
#pragma unroll
        for (int ni = 0; ni < 4; ni++)
#pragma unroll
            for (int j = 0; j < 4; j++) acc[mi][ni][j] = 0.f;

    const int crow = tid >> 3;      // 0..31
    const int cc   = tid & 7;       // chunk 0..7 (16B = 8 fp16)

    auto issue_stage = [&](int buf, int k0) {
        uint32_t abase = sbase + buf * HTILE;
        uint32_t bbase = abase + 18432;
#pragma unroll
        for (int i = 0; i < 4; i++) {
            int row = crow + i * 32;
            uint32_t dst = abase + row * 144 + cc * 16;
            const __half* src = A + (long long)(m0 + row) * lda + k0 + cc * 8;
            asm volatile("cp.async.cg.shared.global [%0], [%1], 16;"
                         :: "r"(dst), "l"(src));
        }
#pragma unroll
        for (int i = 0; i < 4; i++) {
            int row = crow + i * 32;
            uint32_t dst = bbase + row * 144 + cc * 16;
            const __half* src = Bm + (long long)(n0 + row) * ldb + k0 + cc * 8;
            int sz = (n0 + row < N) ? 16 : 0;
            asm volatile("cp.async.cg.shared.global [%0], [%1], 16, %2;"
                         :: "r"(dst), "l"(src), "r"(sz));
        }
        asm volatile("cp.async.commit_group;" ::: "memory");
    };

    const int S = K >> 6;
    issue_stage(0, 0);
    if (S > 1) issue_stage(1, 64);

    for (int s = 0; s < S; s++) {
        if (s + 1 < S) asm volatile("cp.async.wait_group 1;" ::: "memory");
        else           asm volatile("cp.async.wait_group 0;" ::: "memory");
        __syncthreads();
        if (s + 2 < S) issue_stage((s + 2) % HSTG, (s + 2) * 64);

        const uint32_t abase = sbase + (s % HSTG) * HTILE;
        const uint32_t bbase = abase + 18432;

#pragma unroll
        for (int kb = 0; kb < 4; kb++) {
            unsigned a[4][4], b[4][2];
#pragma unroll
            for (int mi = 0; mi < 4; mi++) {
                uint32_t ad = abase + (wm + mi*16 + l15) * 144 + (kb*16 + ahl) * 2;
                ldsm4(a[mi][0], a[mi][1], a[mi][2], a[mi][3], ad);
            }
#pragma unroll
            for (int p = 0; p < 2; p++) {
                uint32_t bd = bbase + (wn + p*16 + brw) * 144 + (kb*16 + bkl) * 2;
                ldsm4(b[2*p][0], b[2*p][1], b[2*p+1][0], b[2*p+1][1], bd);
            }
#pragma unroll
            for (int mi = 0; mi < 4; mi++)
#pragma unroll
                for (int ni = 0; ni < 4; ni++)
                    mma16(acc[mi][ni], a[mi][0], a[mi][1], a[mi][2], a[mi][3],
                          b[ni][0], b[ni][1]);
        }
    }

#pragma unroll
    for (int mi = 0; mi < 4; mi++) {
        int r = m0 + wm + mi * 16 + qr;
#pragma unroll
        for (int ni = 0; ni < 4; ni++) {
            int cn = n0 + wn + ni * 8 + 2 * qc;
            if (cn < N) {
                if (OUTH) {
                    __half* C = (__half*)Cv;
                    *(__half2*)(C + (long long)r * ldc + cn) =
                        __floats2half2_rn(acc[mi][ni][0], acc[mi][ni][1]);
                    *(__half2*)(C + (long long)(r + 8) * ldc + cn) =
                        __floats2half2_rn(acc[mi][ni][2], acc[mi][ni][3]);
                } else {
                    float* C = (float*)Cv;
                    *(float2*)(C + (long long)r * ldc + cn) =
                        make_float2(acc[mi][ni][0], acc[mi][ni][1]);
                    *(float2*)(C + (long long)(r + 8) * ldc + cn) =
                        make_float2(acc[mi][ni][2], acc[mi][ni][3]);
                }
            }
        }
    }
}

// =====================================================================
// RoPE on q_pe inside merged g_qkv. grid = BS_, block = 512
// =====================================================================
__global__ void rope_q_k(__half* __restrict__ q,
                         const float* __restrict__ fcos, const float* __restrict__ fsin)
{
    int bs = blockIdx.x;
    int s  = bs & (S_ - 1);
    int t  = threadIdx.x;
    int h  = t >> 5, i = t & 31;
    float c  = fcos[s*(ROPE_/2) + i];
    float sn = fsin[s*(ROPE_/2) + i];
    __half2* p = (__half2*)(q + (long long)bs * QLD + h*QK_ + NOPE_ + 2*i);
    float2 v = __half22float2(*p);
    *p = __floats2half2_rn(v.x*c - v.y*sn, v.x*sn + v.y*c);
}

// =====================================================================
// RMSNorm(kv)*w and RoPE(k_pe) from merged g_qkv tail. grid = BS_, block = 128
// =====================================================================
__global__ void kv_prep_k(const __half* __restrict__ qkv, const float* __restrict__ w,
                          const float* __restrict__ fcos, const float* __restrict__ fsin,
                          __half* __restrict__ kvout, __half* __restrict__ kpeout)
{
    int bs = blockIdx.x;
    int s  = bs & (S_ - 1);
    const __half* row = qkv + (long long)bs * QLD + 3072;
    __shared__ float red[4];
    int t = threadIdx.x;
    float v[4]; float ss = 0.f;
#pragma unroll
    for (int i = 0; i < 4; i++) {
        v[i] = __half2float(row[t + i*128]);
        ss = fmaf(v[i], v[i], ss);
    }
#pragma unroll
    for (int o = 16; o > 0; o >>= 1) ss += __shfl_xor_sync(0xffffffffu, ss, o);
    if ((t & 31) == 0) red[t >> 5] = ss;
    __syncthreads();
    float tot = red[0] + red[1] + red[2] + red[3];
    float r = rsqrtf(tot * (1.0f/512.0f) + 1e-6f);
#pragma unroll
    for (int i = 0; i < 4; i++) {
        int c = t + i*128;
        kvout[(long long)bs*C_ + c] = __float2half_rn(v[i] * r * w[c]);
    }
    if (t < 32) {
        float c  = fcos[s*(ROPE_/2) + t];
        float sn = fsin[s*(ROPE_/2) + t];
        float2 pe = __half22float2(*(const __half2*)(row + C_ + 2*t));
        *(__half2*)(kpeout + (long long)bs*ROPE_ + 2*t) =
            __floats2half2_rn(pe.x*c - pe.y*sn, pe.x*sn + pe.y*c);
    }
}

// =====================================================================
// fp16 flash attention (m16n8k16 + ldmatrix), cp.async K prefetch +
// reg V prefetch. CTA: 128 q-rows, 8 warps x 16 rows, K/V tiles of 64.
// =====================================================================
#define FM 128
#define FN 64
#define SK_OFF  (128*400)            // sQ: 128 x 400B
#define SV_OFF  (SK_OFF + 64*400)    // sK: 64 x 400B
#define SP_OFF  (SV_OFF + 128*144)   // sVt: 128 x 144B
#define FLASH_SMEM (SP_OFF + 128*144)

__global__ __launch_bounds__(256, 1) void flash_h(
    const __half* __restrict__ q,    // merged g_qkv, row stride QLD
    const __half* __restrict__ knv,  // (H, bs, 256) fp16
    const __half* __restrict__ kpe,  // (bs, 64) fp16
    __half* __restrict__ out)        // (bs, H*128) fp16
{
    extern __shared__ __align__(128) char sm[];
    unsigned* sV = (unsigned*)(sm + SV_OFF);
    unsigned* sP = (unsigned*)(sm + SP_OFF);
    const uint32_t sqb = su32(sm);
    const uint32_t skb = sqb + SK_OFF;
    const uint32_t svb = sqb + SV_OFF;
    const uint32_t spb = sqb + SP_OFF;

    int bx = blockIdx.x;
    int nb = gridDim.x;
    int sblk = (bx & 1) ? (nb - 1 - (bx >> 1)) : (bx >> 1);
    const int s0 = sblk * FM;
    const int h  = blockIdx.y;
    const int b  = blockIdx.z;
    const int tid = threadIdx.x;
    const int lane = tid & 31;
    const int warp = tid >> 5;
    const int rb = warp * 16;
    const int qr = lane >> 2;
    const int qc = lane & 3;
    const int g0 = s0 + rb + qr;
    const int g1 = g0 + 8;

    // LDSM lane geometry
    const int l15 = lane & 15;
    const int ahl = (lane >> 4) << 3;
    const int bg  = lane >> 3;
    const int brw = ((bg >> 1) << 3) + (lane & 7);
    const int bkl = (bg & 1) << 3;

    const __half* knh = knv + (long long)h * BS_ * 256;
    const float SC = 0.07216878364870322f;  // 1/sqrt(192)

    auto loadK = [&](int t0) {
#pragma unroll
        for (int i = 0; i < 6; i++) {
            int id = tid + i * 256;
            int r = id / 24, c = id % 24;
            long long trow = (long long)(b*S_ + t0 + r);
            const __half* src = (c < 16) ? (knh + trow*256 + c*8)
                                         : (kpe + trow*(long long)ROPE_ + (c-16)*8);
            uint32_t dst = skb + (uint32_t)(r*400 + c*16);
            asm volatile("cp.async.cg.shared.global [%0], [%1], 16;"
                         :: "r"(dst), "l"(src));
        }
        asm volatile("cp.async.commit_group;" ::: "memory");
    };

    const int tp = tid & 31;     // t-pair index
    const int dg = tid >> 5;     // d-group (16 d's)
    union HU { uint4 u[2]; __half x[16]; };
    HU vlo, vhi;
    auto ldV = [&](int t0) {
        const __half* base = knh + (long long)(b*S_ + t0 + 2*tp) * 256 + 128 + dg*16;
        vlo.u[0] = *(const uint4*)(base);
        vlo.u[1] = *(const uint4*)(base + 8);
        vhi.u[0] = *(const uint4*)(base + 256);
        vhi.u[1] = *(const uint4*)(base + 264);
    };
    auto stV = [&]() {
#pragma unroll
        for (int d = 0; d < 16; d++)
            sV[(dg*16 + d)*36 + tp] = packhh(vlo.x[d], vhi.x[d]);
    };

    // Q tile (raw uint4 copy)
#pragma unroll
    for (int i = 0; i < 12; i++) {
        int id = tid + i * 256;
        int r = id / 24, c = id % 24;
        *(uint4*)(sm + r*400 + c*16) =
            *(const uint4*)(q + (long long)(b*S_ + s0 + r) * QLD + h*QK_ + c*8);
    }

    float mr0 = -INFINITY, mr1 = -INFINITY, l0 = 0.f, l1 = 0.f;
    float o[16][4];
#pragma unroll
    for (int ni = 0; ni < 16; ni++)
#pragma unroll
        for (int j = 0; j < 4; j++) o[ni][j] = 0.f;

    loadK(0);
    ldV(0);
    asm volatile("cp.async.wait_group 0;" ::: "memory");
    stV();
    __syncthreads();

    const int tlast = s0 + (FM - FN);
    for (int t0 = 0; t0 <= tlast; t0 += FN) {
        const bool domask = (t0 + FN - 1 > s0);
        const bool nxt = (t0 + FN <= tlast);

        // ---- QK (192 = 12 x k16) ----
        float sc[8][4];
#pragma unroll
        for (int ni = 0; ni < 8; ni++)
#pragma unroll
            for (int j = 0; j < 4; j++) sc[ni][j] = 0.f;

#pragma unroll
        for (int kb = 0; kb < 12; kb++) {
            unsigned a0, a1, a2, a3;
            ldsm4(a0, a1, a2, a3,
                  sqb + (rb + l15) * 400 + (kb*16 + ahl) * 2);
            unsigned kb_[8][2];
#pragma unroll
            for (int p = 0; p < 4; p++) {
                ldsm4(kb_[2*p][0], kb_[2*p][1], kb_[2*p+1][0], kb_[2*p+1][1],
                      skb + (p*16 + brw) * 400 + (kb*16 + bkl) * 2);
            }
#pragma unroll
            for (int ni = 0; ni < 8; ni++)
                mma16(sc[ni], a0, a1, a2, a3, kb_[ni][0], kb_[ni][1]);
        }
        __syncthreads();              // done reading sK
        if (nxt) loadK(t0 + FN);      // overlaps softmax + PV

        // ---- softmax (fp32) ----
        float mx0 = -INFINITY, mx1 = -INFINITY;
#pragma unroll
        for (int ni = 0; ni < 8; ni++) {
            float v0 = sc[ni][0]*SC, v1 = sc[ni][1]*SC;
            float v2 = sc[ni][2]*SC, v3 = sc[ni][3]*SC;
            if (domask) {
                int cc = t0 + 8*ni + 2*qc;
                if (cc     > g0) v0 = -1e30f;
                if (cc + 1 > g0) v1 = -1e30f;
                if (cc     > g1) v2 = -1e30f;
                if (cc + 1 > g1) v3 = -1e30f;
            }
            sc[ni][0]=v0; sc[ni][1]=v1; sc[ni][2]=v2; sc[ni][3]=v3;
            mx0 = fmaxf(mx0, fmaxf(v0, v1));
            mx1 = fmaxf(mx1, fmaxf(v2, v3));
        }
        mx0 = fmaxf(mx0, __shfl_xor_sync(0xffffffffu, mx0, 1));
        mx0 = fmaxf(mx0, __shfl_xor_sync(0xffffffffu, mx0, 2));
        mx1 = fmaxf(mx1, __shfl_xor_sync(0xffffffffu, mx1, 1));
        mx1 = fmaxf(mx1, __shfl_xor_sync(0xffffffffu, mx1, 2));

        float mn0 = fmaxf(mr0, mx0), mn1 = fmaxf(mr1, mx1);
        float al0 = __expf(mr0 - mn0), al1 = __expf(mr1 - mn1);

        float s0s = 0.f, s1s = 0.f;
#pragma unroll
        for (int ni = 0; ni < 8; ni++) {
            float p0 = __expf(sc[ni][0] - mn0), p1 = __expf(sc[ni][1] - mn0);
            float p2 = __expf(sc[ni][2] - mn1), p3 = __expf(sc[ni][3] - mn1);
            s0s += p0 + p1; s1s += p2 + p3;
            sP[(rb+qr)*36   + 4*ni + qc] = packh2(p0, p1);
            sP[(rb+qr+8)*36 + 4*ni + qc] = packh2(p2, p3);
        }
        s0s += __shfl_xor_sync(0xffffffffu, s0s, 1);
        s0s += __shfl_xor_sync(0xffffffffu, s0s, 2);
        s1s += __shfl_xor_sync(0xffffffffu, s1s, 1);
        s1s += __shfl_xor_sync(0xffffffffu, s1s, 2);
        l0 = l0 * al0 + s0s;
        l1 = l1 * al1 + s1s;
        mr0 = mn0; mr1 = mn1;

#pragma unroll
        for (int ni = 0; ni < 16; ni++) {
            o[ni][0] *= al0; o[ni][1] *= al0;
            o[ni][2] *= al1; o[ni][3] *= al1;
        }
        __syncwarp();

        if (nxt) ldV(t0 + FN);        // LDG flight overlaps PV

        // ---- PV (64 = 4 x k16) ----
#pragma unroll
        for (int kb = 0; kb < 4; kb++) {
            unsigned a0, a1, a2, a3;
            ldsm4(a0, a1, a2, a3,
                  spb + (rb + l15) * 144 + (kb*16 + ahl) * 2);
            unsigned vb_[16][2];
#pragma unroll
            for (int p = 0; p < 8; p++) {
                ldsm4(vb_[2*p][0], vb_[2*p][1], vb_[2*p+1][0], vb_[2*p+1][1],
                      svb + (p*16 + brw) * 144 + (kb*16 + bkl) * 2);
            }
#pragma unroll
            for (int ni = 0; ni < 16; ni++)
                mma16(o[ni], a0, a1, a2, a3, vb_[ni][0], vb_[ni][1]);
        }
        __syncthreads();              // done reading sV/sP
        if (nxt) {
            stV();
            asm volatile("cp.async.wait_group 0;" ::: "memory");
            __syncthreads();
        }
    }

    float i0 = 1.0f / l0, i1 = 1.0f / l1;
    __half* out0 = out + (long long)(b*S_ + s0 + rb + qr) * (H_*V_) + h*V_;
    __half* out1 = out0 + 8LL * (H_*V_);
#pragma unroll
    for (int ni = 0; ni < 16; ni++) {
        int cn = 8*ni + 2*qc;
        *(__half2*)(out0 + cn) = __floats2half2_rn(o[ni][0]*i0, o[ni][1]*i0);
        *(__half2*)(out1 + cn) = __floats2half2_rn(o[ni][2]*i1, o[ni][3]*i1);
    }
}

// =====================================================================
// Host launch
// =====================================================================
static void* sym_addr(const void* sym) {
    void* p = nullptr;
    cudaGetSymbolAddress(&p, sym);
    return p;
}

extern "C" void kernel_launch(void* const* d_in, const int* in_sizes, int n_in,
                              void* d_out, int out_size)
{
    const float* x     = (const float*)d_in[0];
    const float* wq    = (const float*)d_in[1];
    const float* wkv_a = (const float*)d_in[2];
    const float* wkv_b = (const float*)d_in[3];
    const float* wo    = (const float*)d_in[4];
    const float* kvw   = (const float*)d_in[5];
    const float* fcos  = (const float*)d_in[6];
    const float* fsin  = (const float*)d_in[7];
    float* out = (float*)d_out;

    __half* qkvb = (__half*)sym_addr(g_qkv);
    __half* kvb  = (__half*)sym_addr(g_kv);
    __half* kpeb = (__half*)sym_addr(g_kpe);
    __half* knvb = (__half*)sym_addr(g_knv);
    __half* o2b  = (__half*)sym_addr(g_o2);
    __half* xh   = (__half*)sym_addr(g_xh);
    __half* wqa  = (__half*)sym_addr(g_wqa);
    __half* wbh  = (__half*)sym_addr(g_wbh);
    __half* woh  = (__half*)sym_addr(g_woh);

    static bool attr_done = false;
    if (!attr_done) {
        cudaFuncSetAttribute(gemm_h<1>, cudaFuncAttributeMaxDynamicSharedMemorySize, GEMM_SMEM);
        cudaFuncSetAttribute(gemm_h<0>, cudaFuncAttributeMaxDynamicSharedMemorySize, GEMM_SMEM);
        cudaFuncSetAttribute(flash_h,   cudaFuncAttributeMaxDynamicSharedMemorySize, FLASH_SMEM);
        attr_done = true;
    }

    // 0. convert inputs to fp16
    {
        auto rr = [&](const float* s, __half* d, long long n) {
            int n4 = (int)(n / 4);
            hround_k<<<(n4 + 255) / 256, 256>>>((const float4*)s, (uint2*)d, n4);
        };
        rr(x,     xh,  (long long)BS_*DIM_);
        rr(wq,    wqa, (long long)(H_*QK_)*DIM_);
        rr(wkv_a, wqa + (long long)(H_*QK_)*DIM_, (long long)(C_+ROPE_)*DIM_);
        rr(wkv_b, wbh, (long long)H_*256*C_);
        rr(wo,    woh, (long long)DIM_*(H_*V_));
    }

    dim3 blk(256);

    // 1. merged projections: qkv = xh @ wqa^T   (4096 x 3648, K=2048)
    gemm_h<1><<<dim3(29, 32, 1), blk, GEMM_SMEM>>>(
        xh, wqa, qkvb, BS_, QLD, DIM_, DIM_, DIM_, QLD, 0, 0, 0);

    // 2. rope(q_pe)
    rope_q_k<<<BS_, H_*32>>>(qkvb, fcos, fsin);

    // 3. rmsnorm(kv), rope(k_pe)
    kv_prep_k<<<BS_, 128>>>(qkvb, kvw, fcos, fsin, kvb, kpeb);

    // 4. knv[h] = kv @ wbh[h]^T   (N=256 per head)
    gemm_h<1><<<dim3(2, 32, H_), blk, GEMM_SMEM>>>(
        kvb, wbh, knvb,
        BS_, 256, C_, C_, C_, 256,
        0, (long long)256*C_, (long long)BS_*256);

    // 5. flash attention -> g_o2
    flash_h<<<dim3(S_/FM, H_, B_), dim3(256), FLASH_SMEM>>>(qkvb, knvb, kpeb, o2b);

    // 6. out = o2 @ woh^T   (fp32 out)
    gemm_h<0><<<dim3(16, 32, 1), blk, GEMM_SMEM>>>(
        o2b, woh, out, BS_, DIM_, H_*V_, H_*V_, H_*V_, DIM_, 0, 0, 0);

    (void)in_sizes; (void)n_in; (void)out_size;
}

// round 13
// speedup vs baseline: 17.4628x; 1.0207x over previous
#include <cuda_runtime.h>
#include <cuda_fp16.h>
#include <math.h>
#include <stdint.h>

// ---------------- problem constants ----------------
#define B_    2
#define S_    2048
#define DIM_  2048
#define H_    16
#define C_    512
#define NOPE_ 128
#define ROPE_ 64
#define V_    128
#define QK_   192
#define BS_   (B_*S_)
#define QLD   3648          // merged [q(3072) | kvpe(576)] row stride

// ---------------- scratch (fp16 pipeline) ----------------
__device__ __half g_qkv[(long long)BS_*QLD];
__device__ __half g_kv [(long long)BS_*C_];
__device__ __half g_kpe[(long long)BS_*ROPE_];
__device__ __half g_knv[(long long)H_*BS_*256];   // per-head [k_nope(128) | v(128)]
__device__ __half g_o2 [(long long)BS_*H_*V_];
__device__ __half g_xh [(long long)BS_*DIM_];
__device__ __half g_wqa[(long long)QLD*DIM_];     // [wq(3072) ; wkv_a(576)] rows
__device__ __half g_wbh[(long long)H_*256*C_];
__device__ __half g_woh[(long long)DIM_*(H_*V_)];

// ---------------- helpers ----------------
__device__ __forceinline__ void mma16(float* c, unsigned a0, unsigned a1, unsigned a2,
                                      unsigned a3, unsigned b0, unsigned b1) {
    asm volatile(
        "mma.sync.aligned.m16n8k16.row.col.f32.f16.f16.f32 "
        "{%0,%1,%2,%3},{%4,%5,%6,%7},{%8,%9},{%0,%1,%2,%3};"
        : "+f"(c[0]), "+f"(c[1]), "+f"(c[2]), "+f"(c[3])
        : "r"(a0), "r"(a1), "r"(a2), "r"(a3), "r"(b0), "r"(b1));
}
__device__ __forceinline__ void ldsm4(unsigned &r0, unsigned &r1, unsigned &r2,
                                      unsigned &r3, uint32_t addr) {
    asm volatile("ldmatrix.sync.aligned.m8n8.x4.shared.b16 {%0,%1,%2,%3}, [%4];"
                 : "=r"(r0), "=r"(r1), "=r"(r2), "=r"(r3) : "r"(addr));
}
__device__ __forceinline__ uint32_t su32(const void* p) {
    uint32_t a;
    asm("{ .reg .u64 t; cvta.to.shared.u64 t, %1; cvt.u32.u64 %0, t; }"
        : "=r"(a) : "l"(p));
    return a;
}
__device__ __forceinline__ unsigned packh2(float a, float b) {
    __half2 h = __floats2half2_rn(a, b);
    return *(unsigned*)&h;
}
__device__ __forceinline__ unsigned packhh(__half a, __half b) {
    __half2 h = __halves2half2(a, b);
    return *(unsigned*)&h;
}

// =====================================================================
// fp32 -> fp16 convert
// =====================================================================
__global__ void hround_k(const float4* __restrict__ src, uint2* __restrict__ dst,
                         int n4)
{
    int i = blockIdx.x * blockDim.x + threadIdx.x;
    if (i < n4) {
        float4 v = src[i];
        uint2 u;
        u.x = packh2(v.x, v.y);
        u.y = packh2(v.z, v.w);
        dst[i] = u;
    }
}

// =====================================================================
// fp16 NT GEMM, m16n8k16 + ldmatrix + 3-stage cp.async.
// 256 threads, 8 warps, warp tile 64x32 -> 2 CTAs/SM.
// =====================================================================
#define HSTG 3
#define HTILE 36864
#define GEMM_SMEM (HSTG*HTILE)

template<int OUTH>
__global__ __launch_bounds__(256, 2) void gemm_h(
    const __half* __restrict__ A, const __half* __restrict__ Bm, void* Cv,
    int M, int N, int K, int lda, int ldb, int ldc,
    long long sAz, long long sBz, long long sCz)
{
    A  += (long long)blockIdx.z * sAz;
    Bm += (long long)blockIdx.z * sBz;
    if (OUTH) Cv = (void*)((__half*)Cv + (long long)blockIdx.z * sCz);
    else      Cv = (void*)((float*)Cv  + (long long)blockIdx.z * sCz);

    extern __shared__ __align__(128) char smem[];
    const uint32_t sbase = su32(smem);

    const int tid  = threadIdx.x;
    const int lane = tid & 31;
    const int warp = tid >> 5;
    const int m0 = blockIdx.y * 128;
    const int n0 = blockIdx.x * 128;
    const int wm = (warp >> 2) * 64;
    const int wn = (warp & 3) * 32;
    const int qr = lane >> 2;
    const int qc = lane & 3;

    const int l15 = lane & 15;
    const int ahl = (lane >> 4) << 3;
    const int bg  = lane >> 3;
    const int brw = ((bg >> 1) << 3) + (lane & 7);
    const int bkl = (bg & 1) << 3;

    float acc[4][4][4];
#pragma unroll
    for (int mi = 0; mi < 4; mi++)
#pragma unroll
        for (int ni = 0; ni < 4; ni++)
#pragma unroll
            for (int j = 0; j < 4; j++) acc[mi][ni][j] = 0.f;

    const int crow = tid >> 3;
    const int cc   = tid & 7;

    auto issue_stage = [&](int buf, int k0) {
        uint32_t abase = sbase + buf * HTILE;
        uint32_t bbase = abase + 18432;
#pragma unroll
        for (int i = 0; i < 4; i++) {
            int row = crow + i * 32;
            uint32_t dst = abase + row * 144 + cc * 16;
            const __half* src = A + (long long)(m0 + row) * lda + k0 + cc * 8;
            asm volatile("cp.async.cg.shared.global [%0], [%1], 16;"
                         :: "r"(dst), "l"(src));
        }
#pragma unroll
        for (int i = 0; i < 4; i++) {
            int row = crow + i * 32;
            uint32_t dst = bbase + row * 144 + cc * 16;
            const __half* src = Bm + (long long)(n0 + row) * ldb + k0 + cc * 8;
            int sz = (n0 + row < N) ? 16 : 0;
            asm volatile("cp.async.cg.shared.global [%0], [%1], 16, %2;"
                         :: "r"(dst), "l"(src), "r"(sz));
        }
        asm volatile("cp.async.commit_group;" ::: "memory");
    };

    const int S = K >> 6;
    issue_stage(0, 0);
    if (S > 1) issue_stage(1, 64);

    for (int s = 0; s < S; s++) {
        if (s + 1 < S) asm volatile("cp.async.wait_group 1;" ::: "memory");
        else           asm volatile("cp.async.wait_group 0;" ::: "memory");
        __syncthreads();
        if (s + 2 < S) issue_stage((s + 2) % HSTG, (s + 2) * 64);

        const uint32_t abase = sbase + (s % HSTG) * HTILE;
        const uint32_t bbase = abase + 18432;

#pragma unroll
        for (int kb = 0; kb < 4; kb++) {
            unsigned a[4][4], b[4][2];
#pragma unroll
            for (int mi = 0; mi < 4; mi++) {
                uint32_t ad = abase + (wm + mi*16 + l15) * 144 + (kb*16 + ahl) * 2;
                ldsm4(a[mi][0], a[mi][1], a[mi][2], a[mi][3], ad);
            }
#pragma unroll
            for (int p = 0; p < 2; p++) {
                uint32_t bd = bbase + (wn + p*16 + brw) * 144 + (kb*16 + bkl) * 2;
                ldsm4(b[2*p][0], b[2*p][1], b[2*p+1][0], b[2*p+1][1], bd);
            }
#pragma unroll
            for (int mi = 0; mi < 4; mi++)
#pragma unroll
                for (int ni = 0; ni < 4; ni++)
                    mma16(acc[mi][ni], a[mi][0], a[mi][1], a[mi][2], a[mi][3],
                          b[ni][0], b[ni][1]);
        }
    }

#pragma unroll
    for (int mi = 0; mi < 4; mi++) {
        int r = m0 + wm + mi * 16 + qr;
#pragma unroll
        for (int ni = 0; ni < 4; ni++) {
            int cn = n0 + wn + ni * 8 + 2 * qc;
            if (cn < N) {
                if (OUTH) {
                    __half* C = (__half*)Cv;
                    *(__half2*)(C + (long long)r * ldc + cn) =
                        __floats2half2_rn(acc[mi][ni][0], acc[mi][ni][1]);
                    *(__half2*)(C + (long long)(r + 8) * ldc + cn) =
                        __floats2half2_rn(acc[mi][ni][2], acc[mi][ni][3]);
                } else {
                    float* C = (float*)Cv;
                    *(float2*)(C + (long long)r * ldc + cn) =
                        make_float2(acc[mi][ni][0], acc[mi][ni][1]);
                    *(float2*)(C + (long long)(r + 8) * ldc + cn) =
                        make_float2(acc[mi][ni][2], acc[mi][ni][3]);
                }
            }
        }
    }
}

// =====================================================================
// RoPE on q_pe inside merged g_qkv. grid = BS_, block = 512
// =====================================================================
__global__ void rope_q_k(__half* __restrict__ q,
                         const float* __restrict__ fcos, const float* __restrict__ fsin)
{
    int bs = blockIdx.x;
    int s  = bs & (S_ - 1);
    int t  = threadIdx.x;
    int h  = t >> 5, i = t & 31;
    float c  = fcos[s*(ROPE_/2) + i];
    float sn = fsin[s*(ROPE_/2) + i];
    __half2* p = (__half2*)(q + (long long)bs * QLD + h*QK_ + NOPE_ + 2*i);
    float2 v = __half22float2(*p);
    *p = __floats2half2_rn(v.x*c - v.y*sn, v.x*sn + v.y*c);
}

// =====================================================================
// RMSNorm(kv)*w and RoPE(k_pe) from merged g_qkv tail. grid = BS_, block = 128
// =====================================================================
__global__ void kv_prep_k(const __half* __restrict__ qkv, const float* __restrict__ w,
                          const float* __restrict__ fcos, const float* __restrict__ fsin,
                          __half* __restrict__ kvout, __half* __restrict__ kpeout)
{
    int bs = blockIdx.x;
    int s  = bs & (S_ - 1);
    const __half* row = qkv + (long long)bs * QLD + 3072;
    __shared__ float red[4];
    int t = threadIdx.x;
    float v[4]; float ss = 0.f;
#pragma unroll
    for (int i = 0; i < 4; i++) {
        v[i] = __half2float(row[t + i*128]);
        ss = fmaf(v[i], v[i], ss);
    }
#pragma unroll
    for (int o = 16; o > 0; o >>= 1) ss += __shfl_xor_sync(0xffffffffu, ss, o);
    if ((t & 31) == 0) red[t >> 5] = ss;
    __syncthreads();
    float tot = red[0] + red[1] + red[2] + red[3];
    float r = rsqrtf(tot * (1.0f/512.0f) + 1e-6f);
#pragma unroll
    for (int i = 0; i < 4; i++) {
        int c = t + i*128;
        kvout[(long long)bs*C_ + c] = __float2half_rn(v[i] * r * w[c]);
    }
    if (t < 32) {
        float c  = fcos[s*(ROPE_/2) + t];
        float sn = fsin[s*(ROPE_/2) + t];
        float2 pe = __half22float2(*(const __half2*)(row + C_ + 2*t));
        *(__half2*)(kpeout + (long long)bs*ROPE_ + 2*t) =
            __floats2half2_rn(pe.x*c - pe.y*sn, pe.x*sn + pe.y*c);
    }
}

// =====================================================================
// fp16 flash attention, DOUBLE-BUFFERED K and V: 1 barrier / iteration.
// CTA: 128 q-rows, 8 warps x 16 rows, K/V tiles of 64. ~154KB smem.
// =====================================================================
#define FM 128
#define FN 64
#define SQ_SZ  (128*400)
#define SK_SZ  (64*400)
#define SV_SZ  (128*144)
#define SK0_OFF SQ_SZ
#define SV0_OFF (SK0_OFF + 2*SK_SZ)
#define SP_OFF2 (SV0_OFF + 2*SV_SZ)
#define FLASH_SMEM (SP_OFF2 + SV_SZ)   // 157696

__global__ __launch_bounds__(256, 1) void flash_h(
    const __half* __restrict__ q,    // merged g_qkv, row stride QLD
    const __half* __restrict__ knv,  // (H, bs, 256) fp16
    const __half* __restrict__ kpe,  // (bs, 64) fp16
    __half* __restrict__ out)        // (bs, H*128) fp16
{
    extern __shared__ __align__(128) char sm[];
    const uint32_t sqb = su32(sm);
    const uint32_t spb = sqb + SP_OFF2;
    unsigned* sP = (unsigned*)(sm + SP_OFF2);

    int bx = blockIdx.x;
    int nb = gridDim.x;
    int sblk = (bx & 1) ? (nb - 1 - (bx >> 1)) : (bx >> 1);
    const int s0 = sblk * FM;
    const int h  = blockIdx.y;
    const int b  = blockIdx.z;
    const int tid = threadIdx.x;
    const int lane = tid & 31;
    const int warp = tid >> 5;
    const int rb = warp * 16;
    const int qr = lane >> 2;
    const int qc = lane & 3;
    const int g0 = s0 + rb + qr;
    const int g1 = g0 + 8;

    const int l15 = lane & 15;
    const int ahl = (lane >> 4) << 3;
    const int bg  = lane >> 3;
    const int brw = ((bg >> 1) << 3) + (lane & 7);
    const int bkl = (bg & 1) << 3;

    const __half* knh = knv + (long long)h * BS_ * 256;
    const float SC = 0.07216878364870322f;  // 1/sqrt(192)

    auto loadK = [&](int t0, int buf) {
        const uint32_t kb0 = sqb + SK0_OFF + buf * SK_SZ;
#pragma unroll
        for (int i = 0; i < 6; i++) {
            int id = tid + i * 256;
            int r = id / 24, c = id % 24;
            long long trow = (long long)(b*S_ + t0 + r);
            const __half* src = (c < 16) ? (knh + trow*256 + c*8)
                                         : (kpe + trow*(long long)ROPE_ + (c-16)*8);
            uint32_t dst = kb0 + (uint32_t)(r*400 + c*16);
            asm volatile("cp.async.cg.shared.global [%0], [%1], 16;"
                         :: "r"(dst), "l"(src));
        }
        asm volatile("cp.async.commit_group;" ::: "memory");
    };

    const int tp = tid & 31;     // t-pair index
    const int dg = tid >> 5;     // d-group (16 d's)
    union HU { uint4 u[2]; __half x[16]; };
    HU vlo, vhi;
    auto ldV = [&](int t0) {
        const __half* base = knh + (long long)(b*S_ + t0 + 2*tp) * 256 + 128 + dg*16;
        vlo.u[0] = *(const uint4*)(base);
        vlo.u[1] = *(const uint4*)(base + 8);
        vhi.u[0] = *(const uint4*)(base + 256);
        vhi.u[1] = *(const uint4*)(base + 264);
    };
    auto stV = [&](int buf) {
        unsigned* sV = (unsigned*)(sm + SV0_OFF + buf * SV_SZ);
#pragma unroll
        for (int d = 0; d < 16; d++)
            sV[(dg*16 + d)*36 + tp] = packhh(vlo.x[d], vhi.x[d]);
    };

    // Q tile (raw uint4 copy)
#pragma unroll
    for (int i = 0; i < 12; i++) {
        int id = tid + i * 256;
        int r = id / 24, c = id % 24;
        *(uint4*)(sm + r*400 + c*16) =
            *(const uint4*)(q + (long long)(b*S_ + s0 + r) * QLD + h*QK_ + c*8);
    }

    float mr0 = -INFINITY, mr1 = -INFINITY, l0 = 0.f, l1 = 0.f;
    float o[16][4];
#pragma unroll
    for (int ni = 0; ni < 16; ni++)
#pragma unroll
        for (int j = 0; j < 4; j++) o[ni][j] = 0.f;

    loadK(0, 0);
    ldV(0);
    asm volatile("cp.async.wait_group 0;" ::: "memory");
    stV(0);
    __syncthreads();

    const int tlast = s0 + (FM - FN);
    int cur = 0;
    for (int t0 = 0; t0 <= tlast; t0 += FN, cur ^= 1) {
        const bool domask = (t0 + FN - 1 > s0);
        const bool nxt = (t0 + FN <= tlast);
        const uint32_t skb = sqb + SK0_OFF + cur * SK_SZ;
        const uint32_t svb = sqb + SV0_OFF + cur * SV_SZ;

        // ---- QK (192 = 12 x k16) ----
        float sc[8][4];
#pragma unroll
        for (int ni = 0; ni < 8; ni++)
#pragma unroll
            for (int j = 0; j < 4; j++) sc[ni][j] = 0.f;

#pragma unroll
        for (int kb = 0; kb < 12; kb++) {
            unsigned a0, a1, a2, a3;
            ldsm4(a0, a1, a2, a3,
                  sqb + (rb + l15) * 400 + (kb*16 + ahl) * 2);
            unsigned kb_[8][2];
#pragma unroll
            for (int p = 0; p < 4; p++) {
                ldsm4(kb_[2*p][0], kb_[2*p][1], kb_[2*p+1][0], kb_[2*p+1][1],
                      skb + (p*16 + brw) * 400 + (kb*16 + bkl) * 2);
            }
#pragma unroll
            for (int ni = 0; ni < 8; ni++)
                mma16(sc[ni], a0, a1, a2, a3, kb_[ni][0], kb_[ni][1]);
        }
        // issue next K into the OTHER buffer (safe: last read ended before
        // the barrier that closed iteration t0-1)
        if (nxt) loadK(t0 + FN, cur ^ 1);

        // ---- softmax (fp32) ----
        float mx0 = -INFINITY, mx1 = -INFINITY;
#pragma unroll
        for (int ni = 0; ni < 8; ni++) {
            float v0 = sc[ni][0]*SC, v1 = sc[ni][1]*SC;
            float v2 = sc[ni][2]*SC, v3 = sc[ni][3]*SC;
            if (domask) {
                int cc = t0 + 8*ni + 2*qc;
                if (cc     > g0) v0 = -1e30f;
                if (cc + 1 > g0) v1 = -1e30f;
                if (cc     > g1) v2 = -1e30f;
                if (cc + 1 > g1) v3 = -1e30f;
            }
            sc[ni][0]=v0; sc[ni][1]=v1; sc[ni][2]=v2; sc[ni][3]=v3;
            mx0 = fmaxf(mx0, fmaxf(v0, v1));
            mx1 = fmaxf(mx1, fmaxf(v2, v3));
        }
        mx0 = fmaxf(mx0, __shfl_xor_sync(0xffffffffu, mx0, 1));
        mx0 = fmaxf(mx0, __shfl_xor_sync(0xffffffffu, mx0, 2));
        mx1 = fmaxf(mx1, __shfl_xor_sync(0xffffffffu, mx1, 1));
        mx1 = fmaxf(mx1, __shfl_xor_sync(0xffffffffu, mx1, 2));

        float mn0 = fmaxf(mr0, mx0), mn1 = fmaxf(mr1, mx1);
        float al0 = __expf(mr0 - mn0), al1 = __expf(mr1 - mn1);

        float s0s = 0.f, s1s = 0.f;
#pragma unroll
        for (int ni = 0; ni < 8; ni++) {
            float p0 = __expf(sc[ni][0] - mn0), p1 = __expf(sc[ni][1] - mn0);
            float p2 = __expf(sc[ni][2] - mn1), p3 = __expf(sc[ni][3] - mn1);
            s0s += p0 + p1; s1s += p2 + p3;
            sP[(rb+qr)*36   + 4*ni + qc] = packh2(p0, p1);
            sP[(rb+qr+8)*36 + 4*ni + qc] = packh2(p2, p3);
        }
        s0s += __shfl_xor_sync(0xffffffffu, s0s, 1);
        s0s += __shfl_xor_sync(0xffffffffu, s0s, 2);
        s1s += __shfl_xor_sync(0xffffffffu, s1s, 1);
        s1s += __shfl_xor_sync(0xffffffffu, s1s, 2);
        l0 = l0 * al0 + s0s;
        l1 = l1 * al1 + s1s;
        mr0 = mn0; mr1 = mn1;

#pragma unroll
        for (int ni = 0; ni < 16; ni++) {
            o[ni][0] *= al0; o[ni][1] *= al0;
            o[ni][2] *= al1; o[ni][3] *= al1;
        }
        __syncwarp();                 // P rows are warp-private

        if (nxt) ldV(t0 + FN);        // LDG flight overlaps PV

        // ---- PV (64 = 4 x k16) ----
#pragma unroll
        for (int kb = 0; kb < 4; kb++) {
            unsigned a0, a1, a2, a3;
            ldsm4(a0, a1, a2, a3,
                  spb + (rb + l15) * 144 + (kb*16 + ahl) * 2);
            unsigned vb_[16][2];
#pragma unroll
            for (int p = 0; p < 8; p++) {
                ldsm4(vb_[2*p][0], vb_[2*p][1], vb_[2*p+1][0], vb_[2*p+1][1],
                      svb + (p*16 + brw) * 144 + (kb*16 + bkl) * 2);
            }
#pragma unroll
            for (int ni = 0; ni < 16; ni++)
                mma16(o[ni], a0, a1, a2, a3, vb_[ni][0], vb_[ni][1]);
        }

        if (nxt) {
            stV(cur ^ 1);             // other V buffer (WAR cleared last iter)
            asm volatile("cp.async.wait_group 0;" ::: "memory");
            __syncthreads();          // single barrier: publish K + V
        }
    }

    float i0 = 1.0f / l0, i1 = 1.0f / l1;
    __half* out0 = out + (long long)(b*S_ + s0 + rb + qr) * (H_*V_) + h*V_;
    __half* out1 = out0 + 8LL * (H_*V_);
#pragma unroll
    for (int ni = 0; ni < 16; ni++) {
        int cn = 8*ni + 2*qc;
        *(__half2*)(out0 + cn) = __floats2half2_rn(o[ni][0]*i0, o[ni][1]*i0);
        *(__half2*)(out1 + cn) = __floats2half2_rn(o[ni][2]*i1, o[ni][3]*i1);
    }
}

// =====================================================================
// Host launch
// =====================================================================
static void* sym_addr(const void* sym) {
    void* p = nullptr;
    cudaGetSymbolAddress(&p, sym);
    return p;
}

extern "C" void kernel_launch(void* const* d_in, const int* in_sizes, int n_in,
                              void* d_out, int out_size)
{
    const float* x     = (const float*)d_in[0];
    const float* wq    = (const float*)d_in[1];
    const float* wkv_a = (const float*)d_in[2];
    const float* wkv_b = (const float*)d_in[3];
    const float* wo    = (const float*)d_in[4];
    const float* kvw   = (const float*)d_in[5];
    const float* fcos  = (const float*)d_in[6];
    const float* fsin  = (const float*)d_in[7];
    float* out = (float*)d_out;

    __half* qkvb = (__half*)sym_addr(g_qkv);
    __half* kvb  = (__half*)sym_addr(g_kv);
    __half* kpeb = (__half*)sym_addr(g_kpe);
    __half* knvb = (__half*)sym_addr(g_knv);
    __half* o2b  = (__half*)sym_addr(g_o2);
    __half* xh   = (__half*)sym_addr(g_xh);
    __half* wqa  = (__half*)sym_addr(g_wqa);
    __half* wbh  = (__half*)sym_addr(g_wbh);
    __half* woh  = (__half*)sym_addr(g_woh);

    static bool attr_done = false;
    if (!attr_done) {
        cudaFuncSetAttribute(gemm_h<1>, cudaFuncAttributeMaxDynamicSharedMemorySize, GEMM_SMEM);
        cudaFuncSetAttribute(gemm_h<0>, cudaFuncAttributeMaxDynamicSharedMemorySize, GEMM_SMEM);
        cudaFuncSetAttribute(flash_h,   cudaFuncAttributeMaxDynamicSharedMemorySize, FLASH_SMEM);
        attr_done = true;
    }

    // 0. convert inputs to fp16
    {
        auto rr = [&](const float* s, __half* d, long long n) {
            int n4 = (int)(n / 4);
            hround_k<<<(n4 + 255) / 256, 256>>>((const float4*)s, (uint2*)d, n4);
        };
        rr(x,     xh,  (long long)BS_*DIM_);
        rr(wq,    wqa, (long long)(H_*QK_)*DIM_);
        rr(wkv_a, wqa + (long long)(H_*QK_)*DIM_, (long long)(C_+ROPE_)*DIM_);
        rr(wkv_b, wbh, (long long)H_*256*C_);
        rr(wo,    woh, (long long)DIM_*(H_*V_));
    }

    dim3 blk(256);

    // 1. merged projections: qkv = xh @ wqa^T   (4096 x 3648, K=2048)
    gemm_h<1><<<dim3(29, 32, 1), blk, GEMM_SMEM>>>(
        xh, wqa, qkvb, BS_, QLD, DIM_, DIM_, DIM_, QLD, 0, 0, 0);

    // 2. rope(q_pe)
    rope_q_k<<<BS_, H_*32>>>(qkvb, fcos, fsin);

    // 3. rmsnorm(kv), rope(k_pe)
    kv_prep_k<<<BS_, 128>>>(qkvb, kvw, fcos, fsin, kvb, kpeb);

    // 4. knv[h] = kv @ wbh[h]^T   (N=256 per head)
    gemm_h<1><<<dim3(2, 32, H_), blk, GEMM_SMEM>>>(
        kvb, wbh, knvb,
        BS_, 256, C_, C_, C_, 256,
        0, (long long)256*C_, (long long)BS_*256);

    // 5. flash attention -> g_o2
    flash_h<<<dim3(S_/FM, H_, B_), dim3(256), FLASH_SMEM>>>(qkvb, knvb, kpeb, o2b);

    // 6. out = o2 @ woh^T   (fp32 out)
    gemm_h<0><<<dim3(16, 32, 1), blk, GEMM_SMEM>>>(
        o2b, woh, out, BS_, DIM_, H_*V_, H_*V_, H_*V_, DIM_, 0, 0, 0);

    (void)in_sizes; (void)n_in; (void)out_size;
}